// round 5
// baseline (speedup 1.0000x reference)
#include <cuda_runtime.h>
#include <math.h>

#define Bdim 16
#define Ldim 4096
#define Cdim 256
#define Ddim 512
#define EPSF 1e-8f

typedef unsigned long long ull;

// ------------------- scratch (device globals; no allocs allowed) -------------------
__device__ float g_feats[(size_t)Bdim * Ddim * Ldim];   // [b][d=512][l]
__device__ float g_attn[(size_t)Bdim * 4 * Ldim];       // [b][i][l]
__device__ float g_xT[(size_t)Bdim * Cdim * Ldim];      // [b][c][l]
__device__ float g_wT[589824];                          // transposed weights

#define OFF_PWT 0        // [4][256][128]
#define OFF_W1T 131072   // [512][128]
#define OFF_FWT 196608   // [512][512]
#define OFF_RWT 458752   // [256][512]
#define WT_TOTAL 589824

// ------------------- packed f32x2 + cp.async helpers -------------------
__device__ __forceinline__ ull pk2(float x) {
    ull r; asm("mov.b64 %0, {%1, %1};" : "=l"(r) : "f"(x)); return r;
}
__device__ __forceinline__ void fma2(ull& c, ull a, ull b) {
    asm("fma.rn.f32x2 %0, %1, %2, %0;" : "+l"(c) : "l"(a), "l"(b));
}
__device__ __forceinline__ float2 up2(ull v) {
    float2 f; asm("mov.b64 {%0, %1}, %2;" : "=f"(f.x), "=f"(f.y) : "l"(v)); return f;
}
__device__ __forceinline__ void cpa16(float* dst, const float* src) {
    unsigned s = (unsigned)__cvta_generic_to_shared(dst);
    asm volatile("cp.async.cg.shared.global [%0], [%1], 16;" :: "r"(s), "l"(src));
}
#define CP_COMMIT() asm volatile("cp.async.commit_group;")
#define CP_WAIT0()  asm volatile("cp.async.wait_group 0;" ::: "memory")

// 8x8 micro-tile GEMM step (for k_conv / k_attn), f32x2-packed along j.
template <int BS>
__device__ __forceinline__ void gemm_step2(const float* __restrict__ A,
                                           const float* __restrict__ Bm,
                                           int ty, int tx, ull acc[8][4]) {
    #pragma unroll 4
    for (int kk = 0; kk < 32; kk++) {
        const float* ar = A + kk * 128 + ty * 8;
        const float* br = Bm + kk * BS + tx * 8;
        float4 a0 = *(const float4*)ar;
        float4 a1 = *(const float4*)(ar + 4);
        ulonglong2 bb0 = *(const ulonglong2*)br;
        ulonglong2 bb1 = *(const ulonglong2*)(br + 4);
        ull bp[4] = {bb0.x, bb0.y, bb1.x, bb1.y};
        float av[8] = {a0.x, a0.y, a0.z, a0.w, a1.x, a1.y, a1.z, a1.w};
        #pragma unroll
        for (int i = 0; i < 8; i++) {
            ull ai = pk2(av[i]);
            #pragma unroll
            for (int j2 = 0; j2 < 4; j2++) fma2(acc[i][j2], ai, bp[j2]);
        }
    }
}

__device__ __forceinline__ void unpack_acc(const ull a[8][4], float f[8][8]) {
    #pragma unroll
    for (int i = 0; i < 8; i++)
        #pragma unroll
        for (int j2 = 0; j2 < 4; j2++) {
            float2 p = up2(a[i][j2]);
            f[i][2 * j2] = p.x;
            f[i][2 * j2 + 1] = p.y;
        }
}

// warp footprint = 4 ty x 8 tx
#define TILE_COORDS(tid, tx, ty)                         \
    int lane_ = (tid) & 31, warp_ = (tid) >> 5;          \
    int tx = ((warp_ & 1) << 3) | (lane_ & 7);           \
    int ty = ((warp_ >> 1) << 2) | (lane_ >> 3);

// ------------------- K0: weight transposes -------------------
__global__ void k_prep(const float* __restrict__ pw1, const float* __restrict__ pw3,
                       const float* __restrict__ pw5, const float* __restrict__ pw7,
                       const float* __restrict__ w1, const float* __restrict__ fw,
                       const float* __restrict__ rw) {
    int idx = blockIdx.x * blockDim.x + threadIdx.x;
    if (idx >= WT_TOTAL) return;
    float v;
    if (idx < OFF_W1T) {
        int s = idx >> 15;
        int r = idx & 32767;
        int c = r >> 7, o = r & 127;
        const float* pw = (s == 0) ? pw1 : (s == 1) ? pw3 : (s == 2) ? pw5 : pw7;
        v = pw[o * Cdim + c];
    } else if (idx < OFF_FWT) {
        int r = idx - OFF_W1T;
        int c = r >> 7, o = r & 127;
        v = w1[o * Ddim + c];
    } else if (idx < OFF_RWT) {
        int r = idx - OFF_FWT;
        int c = r >> 9, o = r & 511;
        v = fw[o * Ddim + c];
    } else {
        int r = idx - OFF_RWT;
        int c = r >> 9, o = r & 511;
        v = rw[o * Cdim + c];
    }
    g_wT[idx] = v;
}

// ------------------- K0b: x transpose [b][l][c] -> [b][c][l] -------------------
__global__ __launch_bounds__(256) void k_xT(const float* __restrict__ x) {
    __shared__ float t[32][33];
    int b = blockIdx.z;
    int c0 = blockIdx.y * 32, l0 = blockIdx.x * 32;
    int tid = threadIdx.x;
    int tc = tid & 31, tr = tid >> 5;
    #pragma unroll
    for (int q = 0; q < 4; q++) {
        int l = tr + q * 8;
        t[l][tc] = x[((size_t)b * Ldim + l0 + l) * Cdim + c0 + tc];
    }
    __syncthreads();
    #pragma unroll
    for (int q = 0; q < 4; q++) {
        int c = tr + q * 8;
        g_xT[((size_t)b * Cdim + c0 + c) * Ldim + l0 + tc] = t[tc][c];
    }
}

// ------------------- K1: depthwise conv + pointwise + channel RMSNorm + GELU -------------------
__global__ __launch_bounds__(256, 2) void k_conv(
    const float* __restrict__ x,
    const float* __restrict__ dw1, const float* __restrict__ dw3,
    const float* __restrict__ dw5, const float* __restrict__ dw7,
    const float* __restrict__ cn1, const float* __restrict__ cn3,
    const float* __restrict__ cn5, const float* __restrict__ cn7) {
    extern __shared__ float sm[];
    float* xs  = sm;                 // [134][32]
    float* hs  = sm + 4288;          // [32][132]
    float* ws0 = sm + 8512;
    float* ws1 = sm + 12608;
    float* red = sm + 16704;         // [128][17]

    int tid = threadIdx.x;
    int lt = blockIdx.x, b = blockIdx.y, sc = blockIdx.z;
    int l0 = lt * 128;
    int k = 2 * sc + 1;
    int r = sc;
    const float* dw = (sc == 0) ? dw1 : (sc == 1) ? dw3 : (sc == 2) ? dw5 : dw7;
    const float* cn = (sc == 0) ? cn1 : (sc == 1) ? cn3 : (sc == 2) ? cn5 : cn7;
    const float* pwT = g_wT + OFF_PWT + sc * 32768;

    ull acc[8][4];
    #pragma unroll
    for (int i = 0; i < 8; i++)
        #pragma unroll
        for (int j = 0; j < 4; j++) acc[i][j] = 0ull;

    int cld = tid & 31, lg = tid >> 5;
    TILE_COORDS(tid, tx, ty);

    float xr[17];
    #pragma unroll
    for (int q = 0; q < 17; q++) {
        int i = lg + 8 * q;
        if (i < 134) {
            int gl = l0 - 3 + i;
            xr[q] = (gl >= 0 && gl < Ldim) ? x[((size_t)b * Ldim + gl) * Cdim + cld] : 0.f;
        }
    }
    #pragma unroll
    for (int q = 0; q < 4; q++) {
        int idx = q * 256 + tid, kk = idx >> 5, seg = (idx & 31) << 2;
        cpa16(ws0 + kk * 128 + seg, pwT + (size_t)kk * 128 + seg);
    }
    CP_COMMIT();

    for (int c0 = 0, ci = 0; c0 < Cdim; c0 += 32, ci++) {
        float* wsc = (ci & 1) ? ws1 : ws0;
        float* wsn = (ci & 1) ? ws0 : ws1;
        CP_WAIT0();
        #pragma unroll
        for (int q = 0; q < 17; q++) {
            int i = lg + 8 * q;
            if (i < 134) xs[i * 32 + cld] = xr[q];
        }
        __syncthreads();
        float rd[7];
        #pragma unroll
        for (int t = 0; t < 7; t++) rd[t] = (t < k) ? dw[(c0 + cld) * k + t] : 0.f;
        #pragma unroll
        for (int ii = 0; ii < 16; ii++) {
            int l = lg * 16 + ii;
            float s = 0.f;
            for (int t = 0; t < k; t++) s += rd[t] * xs[(l + 3 - r + t) * 32 + cld];
            hs[cld * 132 + l] = s;
        }
        if (c0 + 32 < Cdim) {
            #pragma unroll
            for (int q = 0; q < 17; q++) {
                int i = lg + 8 * q;
                if (i < 134) {
                    int gl = l0 - 3 + i;
                    xr[q] = (gl >= 0 && gl < Ldim)
                          ? x[((size_t)b * Ldim + gl) * Cdim + c0 + 32 + cld] : 0.f;
                }
            }
            #pragma unroll
            for (int q = 0; q < 4; q++) {
                int idx = q * 256 + tid, kk = idx >> 5, seg = (idx & 31) << 2;
                cpa16(wsn + kk * 128 + seg, pwT + (size_t)(c0 + 32 + kk) * 128 + seg);
            }
            CP_COMMIT();
        }
        __syncthreads();
        gemm_step2<132>(wsc, hs, ty, tx, acc);
        __syncthreads();
    }

    float accf[8][8];
    unpack_acc(acc, accf);

    #pragma unroll
    for (int j = 0; j < 8; j++) {
        float p = 0.f;
        #pragma unroll
        for (int i = 0; i < 8; i++) p += accf[i][j] * accf[i][j];
        red[(tx * 8 + j) * 17 + ty] = p;
    }
    __syncthreads();
    float inv[8];
    #pragma unroll
    for (int j = 0; j < 8; j++) {
        float s = 0.f;
        #pragma unroll
        for (int t = 0; t < 16; t++) s += red[(tx * 8 + j) * 17 + t];
        float rms = sqrtf(s * (1.f / 128.f));
        inv[j] = 1.f / (rms + EPSF);
    }
    float cnv[8];
    #pragma unroll
    for (int i = 0; i < 8; i++) cnv[i] = cn[ty * 8 + i];
    #pragma unroll
    for (int i = 0; i < 8; i++) {
        float v[8];
        #pragma unroll
        for (int j = 0; j < 8; j++) {
            float h = accf[i][j] * cnv[i] * inv[j];
            v[j] = h * normcdff(h);
        }
        size_t base = ((size_t)b * Ddim + sc * 128 + ty * 8 + i) * Ldim + l0 + tx * 8;
        *(float4*)(g_feats + base) = make_float4(v[0], v[1], v[2], v[3]);
        *(float4*)(g_feats + base + 4) = make_float4(v[4], v[5], v[6], v[7]);
    }
}

// ------------------- K2: attention MLP + softmax -------------------
__global__ __launch_bounds__(256, 2) void k_attn(const float* __restrict__ b1p,
                                                 const float* __restrict__ w2p,
                                                 const float* __restrict__ b2p) {
    extern __shared__ float sm[];
    float* ws0 = sm;
    float* ws1 = sm + 4096;
    float* fs0 = sm + 8192;
    float* fs1 = sm + 12288;
    float* red = sm + 16384;
    float* w2s = sm + 18560;

    int tid = threadIdx.x;
    int b = blockIdx.y;
    int l0 = blockIdx.x * 128;
    const float* w1T = g_wT + OFF_W1T;

    w2s[tid] = w2p[tid];
    w2s[tid + 256] = w2p[tid + 256];

    ull acc[8][4];
    #pragma unroll
    for (int i = 0; i < 8; i++)
        #pragma unroll
        for (int j = 0; j < 4; j++) acc[i][j] = 0ull;

    TILE_COORDS(tid, tx, ty);

    #pragma unroll
    for (int q = 0; q < 4; q++) {
        int idx = q * 256 + tid, kk = idx >> 5, seg = (idx & 31) << 2;
        cpa16(ws0 + kk * 128 + seg, w1T + (size_t)kk * 128 + seg);
        cpa16(fs0 + kk * 128 + seg, g_feats + ((size_t)b * Ddim + kk) * Ldim + l0 + seg);
    }
    CP_COMMIT();

    for (int ci = 0; ci < 16; ci++) {
        float* wsc = (ci & 1) ? ws1 : ws0;
        float* fsc = (ci & 1) ? fs1 : fs0;
        CP_WAIT0();
        __syncthreads();
        if (ci < 15) {
            float* wsn = (ci & 1) ? ws0 : ws1;
            float* fsn = (ci & 1) ? fs0 : fs1;
            int c0 = (ci + 1) * 32;
            #pragma unroll
            for (int q = 0; q < 4; q++) {
                int idx = q * 256 + tid, kk = idx >> 5, seg = (idx & 31) << 2;
                cpa16(wsn + kk * 128 + seg, w1T + (size_t)(c0 + kk) * 128 + seg);
                cpa16(fsn + kk * 128 + seg, g_feats + ((size_t)b * Ddim + c0 + kk) * Ldim + l0 + seg);
            }
            CP_COMMIT();
        }
        gemm_step2<128>(wsc, fsc, ty, tx, acc);
    }
    __syncthreads();

    float accf[8][8];
    unpack_acc(acc, accf);

    float b1v[8];
    #pragma unroll
    for (int i = 0; i < 8; i++) b1v[i] = b1p[ty * 8 + i];
    #pragma unroll
    for (int i = 0; i < 8; i++)
        #pragma unroll
        for (int j = 0; j < 8; j++) {
            float h = accf[i][j] + b1v[i];
            accf[i][j] = h * normcdff(h);
        }

    float a2[4][8];
    for (int i4 = 0; i4 < 4; i4++) {
        float wv[8];
        #pragma unroll
        for (int i = 0; i < 8; i++) wv[i] = w2s[i4 * 128 + ty * 8 + i];
        #pragma unroll
        for (int j = 0; j < 8; j++) {
            float p = 0.f;
            #pragma unroll
            for (int i = 0; i < 8; i++) p += wv[i] * accf[i][j];
            red[(tx * 8 + j) * 17 + ty] = p;
        }
        __syncthreads();
        float b2v = b2p[i4];
        #pragma unroll
        for (int j = 0; j < 8; j++) {
            float s = 0.f;
            #pragma unroll
            for (int t = 0; t < 16; t++) s += red[(tx * 8 + j) * 17 + t];
            a2[i4][j] = s + b2v;
        }
        __syncthreads();
    }

    #pragma unroll
    for (int j = 0; j < 8; j++) {
        float m = fmaxf(fmaxf(a2[0][j], a2[1][j]), fmaxf(a2[2][j], a2[3][j]));
        float s = 0.f;
        #pragma unroll
        for (int i4 = 0; i4 < 4; i4++) {
            a2[i4][j] = expf(a2[i4][j] - m);
            s += a2[i4][j];
        }
        float invs = 1.f / s;
        #pragma unroll
        for (int i4 = 0; i4 < 4; i4++) a2[i4][j] *= invs;
    }
    if (ty == 0) {
        #pragma unroll
        for (int i4 = 0; i4 < 4; i4++) {
            size_t base = ((size_t)b * 4 + i4) * Ldim + l0 + tx * 8;
            *(float4*)(g_attn + base) = make_float4(a2[i4][0], a2[i4][1], a2[i4][2], a2[i4][3]);
            *(float4*)(g_attn + base + 4) = make_float4(a2[i4][4], a2[i4][5], a2[i4][6], a2[i4][7]);
        }
    }
}

// ------------------- K2b: g_feats *= attn (in place, coalesced) -------------------
__global__ __launch_bounds__(256) void k_weight() {
    size_t idx = ((size_t)blockIdx.x * 256 + threadIdx.x) * 8;
    size_t l = idx & 4095;
    size_t rest = idx >> 12;       // b*512 + d
    int d = (int)(rest & 511);
    size_t b = rest >> 9;
    const float* ap = g_attn + ((b * 4 + (d >> 7)) << 12) + l;
    float4 a0 = *(const float4*)ap;
    float4 a1 = *(const float4*)(ap + 4);
    float* fp = g_feats + idx;
    float4 f0 = *(float4*)fp;
    float4 f1 = *(float4*)(fp + 4);
    f0.x *= a0.x; f0.y *= a0.y; f0.z *= a0.z; f0.w *= a0.w;
    f1.x *= a1.x; f1.y *= a1.y; f1.z *= a1.z; f1.w *= a1.w;
    *(float4*)fp = f0;
    *(float4*)(fp + 4) = f1;
}

// ------------------- K3: final GEMM, tile 128o x 256l, micro 8x16 -------------------
// dyn smem: ws[2][4096] + cs[2][8192] = 98304 B
__global__ __launch_bounds__(256, 1) void k_final(float* __restrict__ out) {
    extern __shared__ float sm[];
    float* wsb[2] = {sm, sm + 4096};
    float* csb[2] = {sm + 8192, sm + 16384};

    int tid = threadIdx.x;
    int lt = blockIdx.x, ot = blockIdx.y, b = blockIdx.z;
    int l0 = lt * 256, o0 = ot * 128;
    TILE_COORDS(tid, tx, ty);
    const float* fwT = g_wT + OFF_FWT;
    const float* rwT = g_wT + OFF_RWT;

    ull acc[8][8];
    #pragma unroll
    for (int i = 0; i < 8; i++)
        #pragma unroll
        for (int j = 0; j < 8; j++) acc[i][j] = 0ull;

    // stage chunk c into buffers
    auto stage = [&](int c, float* ws, float* cs) {
        const float* wsrc = (c < 16) ? fwT + (size_t)c * 32 * 512
                                     : rwT + (size_t)(c - 16) * 32 * 512;
        #pragma unroll
        for (int q = 0; q < 4; q++) {
            int idx = q * 256 + tid, kk = idx >> 5, seg = (idx & 31) << 2;
            cpa16(ws + kk * 128 + seg, wsrc + (size_t)kk * 512 + o0 + seg);
        }
        const float* csrc = (c < 16)
            ? g_feats + (((size_t)b * 512 + c * 32) << 12) + l0
            : g_xT   + (((size_t)b * 256 + (c - 16) * 32) << 12) + l0;
        #pragma unroll
        for (int q = 0; q < 8; q++) {
            int idx = q * 256 + tid, kk = idx >> 6, seg = (idx & 63) << 2;
            cpa16(cs + kk * 256 + seg, csrc + ((size_t)kk << 12) + seg);
        }
    };

    stage(0, wsb[0], csb[0]);
    CP_COMMIT();

    for (int ci = 0; ci < 24; ci++) {
        float* wsc = wsb[ci & 1];
        float* csc = csb[ci & 1];
        CP_WAIT0();
        __syncthreads();
        if (ci < 23) {
            stage(ci + 1, wsb[(ci + 1) & 1], csb[(ci + 1) & 1]);
            CP_COMMIT();
        }
        #pragma unroll 2
        for (int kk = 0; kk < 32; kk++) {
            const float* ar = wsc + kk * 128 + ty * 8;
            const float* br = csc + kk * 256 + tx * 16;
            float4 a0 = *(const float4*)ar;
            float4 a1 = *(const float4*)(ar + 4);
            ulonglong2 bb0 = *(const ulonglong2*)br;
            ulonglong2 bb1 = *(const ulonglong2*)(br + 4);
            ulonglong2 bb2 = *(const ulonglong2*)(br + 8);
            ulonglong2 bb3 = *(const ulonglong2*)(br + 12);
            ull bp[8] = {bb0.x, bb0.y, bb1.x, bb1.y, bb2.x, bb2.y, bb3.x, bb3.y};
            float av[8] = {a0.x, a0.y, a0.z, a0.w, a1.x, a1.y, a1.z, a1.w};
            #pragma unroll
            for (int i = 0; i < 8; i++) {
                ull ai = pk2(av[i]);
                #pragma unroll
                for (int j2 = 0; j2 < 8; j2++) fma2(acc[i][j2], ai, bp[j2]);
            }
        }
    }

    // epilogue: store transposed to [b][l][o], column by column (low reg pressure)
    #pragma unroll
    for (int j2 = 0; j2 < 8; j2++) {
        float2 col[8];
        #pragma unroll
        for (int i = 0; i < 8; i++) col[i] = up2(acc[i][j2]);
        size_t base0 = ((size_t)b * Ldim + l0 + tx * 16 + 2 * j2) * Ddim + o0 + ty * 8;
        *(float4*)(out + base0)     = make_float4(col[0].x, col[1].x, col[2].x, col[3].x);
        *(float4*)(out + base0 + 4) = make_float4(col[4].x, col[5].x, col[6].x, col[7].x);
        size_t base1 = base0 + Ddim;
        *(float4*)(out + base1)     = make_float4(col[0].y, col[1].y, col[2].y, col[3].y);
        *(float4*)(out + base1 + 4) = make_float4(col[4].y, col[5].y, col[6].y, col[7].y);
    }
}

// ------------------- K4: final row RMSNorm (in place) -------------------
__global__ __launch_bounds__(256) void k_norm(float* __restrict__ out,
                                              const float* __restrict__ nsc) {
    __shared__ float ns[512];
    int tid = threadIdx.x;
    ns[tid] = nsc[tid];
    ns[tid + 256] = nsc[tid + 256];
    __syncthreads();

    int warp = tid >> 5, lane = tid & 31;
    size_t row = (size_t)blockIdx.x * 8 + warp;
    float* p = out + row * Ddim;

    float4 v[4];
    float ssq = 0.f;
    #pragma unroll
    for (int q = 0; q < 4; q++) {
        v[q] = *(const float4*)(p + (q * 32 + lane) * 4);
        ssq += v[q].x * v[q].x + v[q].y * v[q].y + v[q].z * v[q].z + v[q].w * v[q].w;
    }
    #pragma unroll
    for (int off = 16; off > 0; off >>= 1)
        ssq += __shfl_xor_sync(0xFFFFFFFFu, ssq, off);
    float rms = sqrtf(ssq * (1.f / 512.f));
    float inv = 1.f / (rms + EPSF);
    #pragma unroll
    for (int q = 0; q < 4; q++) {
        int base = (q * 32 + lane) * 4;
        float4 w;
        w.x = v[q].x * ns[base + 0] * inv;
        w.y = v[q].y * ns[base + 1] * inv;
        w.z = v[q].z * ns[base + 2] * inv;
        w.w = v[q].w * ns[base + 3] * inv;
        *(float4*)(p + base) = w;
    }
}

// ------------------- launch -------------------
extern "C" void kernel_launch(void* const* d_in, const int* in_sizes, int n_in,
                              void* d_out, int out_size) {
    const float* x = (const float*)d_in[0];
    const float *dw[4], *pw[4], *cnp[4];
    if (in_sizes[2] == 768) {
        for (int i = 0; i < 4; i++) {
            dw[i]  = (const float*)d_in[1 + i];
            pw[i]  = (const float*)d_in[5 + i];
            cnp[i] = (const float*)d_in[9 + i];
        }
    } else {
        for (int i = 0; i < 4; i++) {
            dw[i]  = (const float*)d_in[1 + 3 * i];
            pw[i]  = (const float*)d_in[2 + 3 * i];
            cnp[i] = (const float*)d_in[3 + 3 * i];
        }
    }
    const float* w1  = (const float*)d_in[13];
    const float* b1  = (const float*)d_in[14];
    const float* w2  = (const float*)d_in[15];
    const float* b2  = (const float*)d_in[16];
    const float* fw  = (const float*)d_in[17];
    const float* nsc = (const float*)d_in[18];
    const float* rw  = (const float*)d_in[19];
    float* out = (float*)d_out;

    const int SM_CONV  = 75520;
    const int SM_ATTN  = 76288;
    const int SM_FINAL = 98304;
    cudaFuncSetAttribute(k_conv,  cudaFuncAttributeMaxDynamicSharedMemorySize, SM_CONV);
    cudaFuncSetAttribute(k_attn,  cudaFuncAttributeMaxDynamicSharedMemorySize, SM_ATTN);
    cudaFuncSetAttribute(k_final, cudaFuncAttributeMaxDynamicSharedMemorySize, SM_FINAL);

    k_prep<<<WT_TOTAL / 256, 256>>>(pw[0], pw[1], pw[2], pw[3], w1, fw, rw);
    k_xT<<<dim3(Ldim / 32, Cdim / 32, Bdim), 256>>>(x);
    k_conv<<<dim3(Ldim / 128, Bdim, 4), 256, SM_CONV>>>(x, dw[0], dw[1], dw[2], dw[3],
                                                        cnp[0], cnp[1], cnp[2], cnp[3]);
    k_attn<<<dim3(Ldim / 128, Bdim), 256, SM_ATTN>>>(b1, w2, b2);
    k_weight<<<(int)(((size_t)Bdim * Ddim * Ldim) / (256 * 8)), 256>>>();
    k_final<<<dim3(Ldim / 256, 4, Bdim), 256, SM_FINAL>>>(out);
    k_norm<<<(Bdim * Ldim) / 8, 256>>>(out, nsc);
}

// round 6
// speedup vs baseline: 1.0070x; 1.0070x over previous
#include <cuda_runtime.h>
#include <math.h>

#define Bdim 16
#define Ldim 4096
#define Cdim 256
#define Ddim 512
#define EPSF 1e-8f

typedef unsigned long long ull;

// ------------------- scratch (device globals; no allocs allowed) -------------------
__device__ float g_feats[(size_t)Bdim * Ddim * Ldim];   // [b][d=512][l]
__device__ float g_attn[(size_t)Bdim * 4 * Ldim];       // [b][i][l]
__device__ float g_xT[(size_t)Bdim * Cdim * Ldim];      // [b][c][l]
__device__ float g_wT[589824];                          // transposed weights

#define OFF_PWT 0        // [4][256][128]
#define OFF_W1T 131072   // [512][128]
#define OFF_FWT 196608   // [512][512]
#define OFF_RWT 458752   // [256][512]
#define WT_TOTAL 589824

// ------------------- packed f32x2 + cp.async helpers -------------------
__device__ __forceinline__ ull pk2(float x) {
    ull r; asm("mov.b64 %0, {%1, %1};" : "=l"(r) : "f"(x)); return r;
}
__device__ __forceinline__ void fma2(ull& c, ull a, ull b) {
    asm("fma.rn.f32x2 %0, %1, %2, %0;" : "+l"(c) : "l"(a), "l"(b));
}
__device__ __forceinline__ float2 up2(ull v) {
    float2 f; asm("mov.b64 {%0, %1}, %2;" : "=f"(f.x), "=f"(f.y) : "l"(v)); return f;
}
__device__ __forceinline__ void cpa16(float* dst, const float* src) {
    unsigned s = (unsigned)__cvta_generic_to_shared(dst);
    asm volatile("cp.async.cg.shared.global [%0], [%1], 16;" :: "r"(s), "l"(src));
}
#define CP_COMMIT() asm volatile("cp.async.commit_group;")
#define CP_WAIT0()  asm volatile("cp.async.wait_group 0;" ::: "memory")

// 8x8 micro-tile GEMM step (k_conv / k_attn), f32x2-packed along j.
template <int BS>
__device__ __forceinline__ void gemm_step2(const float* __restrict__ A,
                                           const float* __restrict__ Bm,
                                           int ty, int tx, ull acc[8][4]) {
    #pragma unroll 4
    for (int kk = 0; kk < 32; kk++) {
        const float* ar = A + kk * 128 + ty * 8;
        const float* br = Bm + kk * BS + tx * 8;
        float4 a0 = *(const float4*)ar;
        float4 a1 = *(const float4*)(ar + 4);
        ulonglong2 bb0 = *(const ulonglong2*)br;
        ulonglong2 bb1 = *(const ulonglong2*)(br + 4);
        ull bp[4] = {bb0.x, bb0.y, bb1.x, bb1.y};
        float av[8] = {a0.x, a0.y, a0.z, a0.w, a1.x, a1.y, a1.z, a1.w};
        #pragma unroll
        for (int i = 0; i < 8; i++) {
            ull ai = pk2(av[i]);
            #pragma unroll
            for (int j2 = 0; j2 < 4; j2++) fma2(acc[i][j2], ai, bp[j2]);
        }
    }
}

__device__ __forceinline__ void unpack_acc(const ull a[8][4], float f[8][8]) {
    #pragma unroll
    for (int i = 0; i < 8; i++)
        #pragma unroll
        for (int j2 = 0; j2 < 4; j2++) {
            float2 p = up2(a[i][j2]);
            f[i][2 * j2] = p.x;
            f[i][2 * j2 + 1] = p.y;
        }
}

// 256-thread kernels: warp footprint = 4 ty x 8 tx
#define TILE_COORDS(tid, tx, ty)                         \
    int lane_ = (tid) & 31, warp_ = (tid) >> 5;          \
    int tx = ((warp_ & 1) << 3) | (lane_ & 7);           \
    int ty = ((warp_ >> 1) << 2) | (lane_ >> 3);

// ------------------- K0: weight transposes -------------------
__global__ void k_prep(const float* __restrict__ pw1, const float* __restrict__ pw3,
                       const float* __restrict__ pw5, const float* __restrict__ pw7,
                       const float* __restrict__ w1, const float* __restrict__ fw,
                       const float* __restrict__ rw) {
    int idx = blockIdx.x * blockDim.x + threadIdx.x;
    if (idx >= WT_TOTAL) return;
    float v;
    if (idx < OFF_W1T) {
        int s = idx >> 15;
        int r = idx & 32767;
        int c = r >> 7, o = r & 127;
        const float* pw = (s == 0) ? pw1 : (s == 1) ? pw3 : (s == 2) ? pw5 : pw7;
        v = pw[o * Cdim + c];
    } else if (idx < OFF_FWT) {
        int r = idx - OFF_W1T;
        int c = r >> 7, o = r & 127;
        v = w1[o * Ddim + c];
    } else if (idx < OFF_RWT) {
        int r = idx - OFF_FWT;
        int c = r >> 9, o = r & 511;
        v = fw[o * Ddim + c];
    } else {
        int r = idx - OFF_RWT;
        int c = r >> 9, o = r & 511;
        v = rw[o * Cdim + c];
    }
    g_wT[idx] = v;
}

// ------------------- K0b: x transpose [b][l][c] -> [b][c][l] -------------------
__global__ __launch_bounds__(256) void k_xT(const float* __restrict__ x) {
    __shared__ float t[32][33];
    int b = blockIdx.z;
    int c0 = blockIdx.y * 32, l0 = blockIdx.x * 32;
    int tid = threadIdx.x;
    int tc = tid & 31, tr = tid >> 5;
    #pragma unroll
    for (int q = 0; q < 4; q++) {
        int l = tr + q * 8;
        t[l][tc] = x[((size_t)b * Ldim + l0 + l) * Cdim + c0 + tc];
    }
    __syncthreads();
    #pragma unroll
    for (int q = 0; q < 4; q++) {
        int c = tr + q * 8;
        g_xT[((size_t)b * Cdim + c0 + c) * Ldim + l0 + tc] = t[tc][c];
    }
}

// ------------------- K1: depthwise conv + pointwise + channel RMSNorm + GELU -------------------
__global__ __launch_bounds__(256, 2) void k_conv(
    const float* __restrict__ x,
    const float* __restrict__ dw1, const float* __restrict__ dw3,
    const float* __restrict__ dw5, const float* __restrict__ dw7,
    const float* __restrict__ cn1, const float* __restrict__ cn3,
    const float* __restrict__ cn5, const float* __restrict__ cn7) {
    extern __shared__ float sm[];
    float* xs  = sm;                 // [134][32]
    float* hs  = sm + 4288;          // [32][132]
    float* ws0 = sm + 8512;
    float* ws1 = sm + 12608;
    float* red = sm + 16704;         // [128][17]

    int tid = threadIdx.x;
    int lt = blockIdx.x, b = blockIdx.y, sc = blockIdx.z;
    int l0 = lt * 128;
    int k = 2 * sc + 1;
    int r = sc;
    const float* dw = (sc == 0) ? dw1 : (sc == 1) ? dw3 : (sc == 2) ? dw5 : dw7;
    const float* cn = (sc == 0) ? cn1 : (sc == 1) ? cn3 : (sc == 2) ? cn5 : cn7;
    const float* pwT = g_wT + OFF_PWT + sc * 32768;

    ull acc[8][4];
    #pragma unroll
    for (int i = 0; i < 8; i++)
        #pragma unroll
        for (int j = 0; j < 4; j++) acc[i][j] = 0ull;

    int cld = tid & 31, lg = tid >> 5;
    TILE_COORDS(tid, tx, ty);

    float xr[17];
    #pragma unroll
    for (int q = 0; q < 17; q++) {
        int i = lg + 8 * q;
        if (i < 134) {
            int gl = l0 - 3 + i;
            xr[q] = (gl >= 0 && gl < Ldim) ? x[((size_t)b * Ldim + gl) * Cdim + cld] : 0.f;
        }
    }
    #pragma unroll
    for (int q = 0; q < 4; q++) {
        int idx = q * 256 + tid, kk = idx >> 5, seg = (idx & 31) << 2;
        cpa16(ws0 + kk * 128 + seg, pwT + (size_t)kk * 128 + seg);
    }
    CP_COMMIT();

    for (int c0 = 0, ci = 0; c0 < Cdim; c0 += 32, ci++) {
        float* wsc = (ci & 1) ? ws1 : ws0;
        float* wsn = (ci & 1) ? ws0 : ws1;
        CP_WAIT0();
        #pragma unroll
        for (int q = 0; q < 17; q++) {
            int i = lg + 8 * q;
            if (i < 134) xs[i * 32 + cld] = xr[q];
        }
        __syncthreads();
        float rd[7];
        #pragma unroll
        for (int t = 0; t < 7; t++) rd[t] = (t < k) ? dw[(c0 + cld) * k + t] : 0.f;
        #pragma unroll
        for (int ii = 0; ii < 16; ii++) {
            int l = lg * 16 + ii;
            float s = 0.f;
            for (int t = 0; t < k; t++) s += rd[t] * xs[(l + 3 - r + t) * 32 + cld];
            hs[cld * 132 + l] = s;
        }
        if (c0 + 32 < Cdim) {
            #pragma unroll
            for (int q = 0; q < 17; q++) {
                int i = lg + 8 * q;
                if (i < 134) {
                    int gl = l0 - 3 + i;
                    xr[q] = (gl >= 0 && gl < Ldim)
                          ? x[((size_t)b * Ldim + gl) * Cdim + c0 + 32 + cld] : 0.f;
                }
            }
            #pragma unroll
            for (int q = 0; q < 4; q++) {
                int idx = q * 256 + tid, kk = idx >> 5, seg = (idx & 31) << 2;
                cpa16(wsn + kk * 128 + seg, pwT + (size_t)(c0 + 32 + kk) * 128 + seg);
            }
            CP_COMMIT();
        }
        __syncthreads();
        gemm_step2<132>(wsc, hs, ty, tx, acc);
        __syncthreads();
    }

    float accf[8][8];
    unpack_acc(acc, accf);

    #pragma unroll
    for (int j = 0; j < 8; j++) {
        float p = 0.f;
        #pragma unroll
        for (int i = 0; i < 8; i++) p += accf[i][j] * accf[i][j];
        red[(tx * 8 + j) * 17 + ty] = p;
    }
    __syncthreads();
    float inv[8];
    #pragma unroll
    for (int j = 0; j < 8; j++) {
        float s = 0.f;
        #pragma unroll
        for (int t = 0; t < 16; t++) s += red[(tx * 8 + j) * 17 + t];
        float rms = sqrtf(s * (1.f / 128.f));
        inv[j] = 1.f / (rms + EPSF);
    }
    float cnv[8];
    #pragma unroll
    for (int i = 0; i < 8; i++) cnv[i] = cn[ty * 8 + i];
    #pragma unroll
    for (int i = 0; i < 8; i++) {
        float v[8];
        #pragma unroll
        for (int j = 0; j < 8; j++) {
            float h = accf[i][j] * cnv[i] * inv[j];
            v[j] = h * normcdff(h);
        }
        size_t base = ((size_t)b * Ddim + sc * 128 + ty * 8 + i) * Ldim + l0 + tx * 8;
        *(float4*)(g_feats + base) = make_float4(v[0], v[1], v[2], v[3]);
        *(float4*)(g_feats + base + 4) = make_float4(v[4], v[5], v[6], v[7]);
    }
}

// ------------------- K2: attention MLP + softmax -------------------
__global__ __launch_bounds__(256, 2) void k_attn(const float* __restrict__ b1p,
                                                 const float* __restrict__ w2p,
                                                 const float* __restrict__ b2p) {
    extern __shared__ float sm[];
    float* ws0 = sm;
    float* ws1 = sm + 4096;
    float* fs0 = sm + 8192;
    float* fs1 = sm + 12288;
    float* red = sm + 16384;
    float* w2s = sm + 18560;

    int tid = threadIdx.x;
    int b = blockIdx.y;
    int l0 = blockIdx.x * 128;
    const float* w1T = g_wT + OFF_W1T;

    w2s[tid] = w2p[tid];
    w2s[tid + 256] = w2p[tid + 256];

    ull acc[8][4];
    #pragma unroll
    for (int i = 0; i < 8; i++)
        #pragma unroll
        for (int j = 0; j < 4; j++) acc[i][j] = 0ull;

    TILE_COORDS(tid, tx, ty);

    #pragma unroll
    for (int q = 0; q < 4; q++) {
        int idx = q * 256 + tid, kk = idx >> 5, seg = (idx & 31) << 2;
        cpa16(ws0 + kk * 128 + seg, w1T + (size_t)kk * 128 + seg);
        cpa16(fs0 + kk * 128 + seg, g_feats + ((size_t)b * Ddim + kk) * Ldim + l0 + seg);
    }
    CP_COMMIT();

    for (int ci = 0; ci < 16; ci++) {
        float* wsc = (ci & 1) ? ws1 : ws0;
        float* fsc = (ci & 1) ? fs1 : fs0;
        CP_WAIT0();
        __syncthreads();
        if (ci < 15) {
            float* wsn = (ci & 1) ? ws0 : ws1;
            float* fsn = (ci & 1) ? fs0 : fs1;
            int c0 = (ci + 1) * 32;
            #pragma unroll
            for (int q = 0; q < 4; q++) {
                int idx = q * 256 + tid, kk = idx >> 5, seg = (idx & 31) << 2;
                cpa16(wsn + kk * 128 + seg, w1T + (size_t)(c0 + kk) * 128 + seg);
                cpa16(fsn + kk * 128 + seg, g_feats + ((size_t)b * Ddim + c0 + kk) * Ldim + l0 + seg);
            }
            CP_COMMIT();
        }
        gemm_step2<128>(wsc, fsc, ty, tx, acc);
    }
    __syncthreads();

    float accf[8][8];
    unpack_acc(acc, accf);

    float b1v[8];
    #pragma unroll
    for (int i = 0; i < 8; i++) b1v[i] = b1p[ty * 8 + i];
    #pragma unroll
    for (int i = 0; i < 8; i++)
        #pragma unroll
        for (int j = 0; j < 8; j++) {
            float h = accf[i][j] + b1v[i];
            accf[i][j] = h * normcdff(h);
        }

    float a2[4][8];
    for (int i4 = 0; i4 < 4; i4++) {
        float wv[8];
        #pragma unroll
        for (int i = 0; i < 8; i++) wv[i] = w2s[i4 * 128 + ty * 8 + i];
        #pragma unroll
        for (int j = 0; j < 8; j++) {
            float p = 0.f;
            #pragma unroll
            for (int i = 0; i < 8; i++) p += wv[i] * accf[i][j];
            red[(tx * 8 + j) * 17 + ty] = p;
        }
        __syncthreads();
        float b2v = b2p[i4];
        #pragma unroll
        for (int j = 0; j < 8; j++) {
            float s = 0.f;
            #pragma unroll
            for (int t = 0; t < 16; t++) s += red[(tx * 8 + j) * 17 + t];
            a2[i4][j] = s + b2v;
        }
        __syncthreads();
    }

    #pragma unroll
    for (int j = 0; j < 8; j++) {
        float m = fmaxf(fmaxf(a2[0][j], a2[1][j]), fmaxf(a2[2][j], a2[3][j]));
        float s = 0.f;
        #pragma unroll
        for (int i4 = 0; i4 < 4; i4++) {
            a2[i4][j] = expf(a2[i4][j] - m);
            s += a2[i4][j];
        }
        float invs = 1.f / s;
        #pragma unroll
        for (int i4 = 0; i4 < 4; i4++) a2[i4][j] *= invs;
    }
    if (ty == 0) {
        #pragma unroll
        for (int i4 = 0; i4 < 4; i4++) {
            size_t base = ((size_t)b * 4 + i4) * Ldim + l0 + tx * 8;
            *(float4*)(g_attn + base) = make_float4(a2[i4][0], a2[i4][1], a2[i4][2], a2[i4][3]);
            *(float4*)(g_attn + base + 4) = make_float4(a2[i4][4], a2[i4][5], a2[i4][6], a2[i4][7]);
        }
    }
}

// ------------------- K2b: g_feats *= attn (in place, coalesced) -------------------
__global__ __launch_bounds__(256) void k_weight() {
    size_t idx = ((size_t)blockIdx.x * 256 + threadIdx.x) * 8;
    size_t l = idx & 4095;
    size_t rest = idx >> 12;       // b*512 + d
    int d = (int)(rest & 511);
    size_t b = rest >> 9;
    const float* ap = g_attn + ((b * 4 + (d >> 7)) << 12) + l;
    float4 a0 = *(const float4*)ap;
    float4 a1 = *(const float4*)(ap + 4);
    float* fp = g_feats + idx;
    float4 f0 = *(float4*)fp;
    float4 f1 = *(float4*)(fp + 4);
    f0.x *= a0.x; f0.y *= a0.y; f0.z *= a0.z; f0.w *= a0.w;
    f1.x *= a1.x; f1.y *= a1.y; f1.z *= a1.z; f1.w *= a1.w;
    *(float4*)fp = f0;
    *(float4*)(fp + 4) = f1;
}

// ------------------- K3: final GEMM, 128 threads, tile 128o x 128l, micro 8x16 -------------------
// dyn smem: ws[2][4096] + cs[2][4096] floats = 65536 B;  2 CTAs/SM
__global__ __launch_bounds__(128, 2) void k_final(float* __restrict__ out) {
    extern __shared__ float sm[];
    float* wsb[2] = {sm, sm + 4096};
    float* csb[2] = {sm + 8192, sm + 12288};

    int tid = threadIdx.x;
    int lt = blockIdx.x, ot = blockIdx.y, b = blockIdx.z;
    int l0 = lt * 128, o0 = ot * 128;
    // 4 warps; footprint 4 ty x 8 tx; thread grid 16 ty x 8 tx
    int lane = tid & 31, warp = tid >> 5;
    int tx = lane & 7;
    int ty = (warp << 2) | (lane >> 3);
    const float* fwT = g_wT + OFF_FWT;
    const float* rwT = g_wT + OFF_RWT;

    ull acc[8][8];
    #pragma unroll
    for (int i = 0; i < 8; i++)
        #pragma unroll
        for (int j = 0; j < 8; j++) acc[i][j] = 0ull;

    auto stage = [&](int c, float* ws, float* cs) {
        const float* wsrc = (c < 16) ? fwT + (size_t)c * 32 * 512
                                     : rwT + (size_t)(c - 16) * 32 * 512;
        const float* csrc = (c < 16)
            ? g_feats + (((size_t)b * 512 + c * 32) << 12) + l0
            : g_xT   + (((size_t)b * 256 + (c - 16) * 32) << 12) + l0;
        #pragma unroll
        for (int q = 0; q < 8; q++) {
            int idx = q * 128 + tid, kk = idx >> 5, seg = (idx & 31) << 2;
            cpa16(ws + kk * 128 + seg, wsrc + (size_t)kk * 512 + o0 + seg);
            cpa16(cs + kk * 128 + seg, csrc + ((size_t)kk << 12) + seg);
        }
    };

    stage(0, wsb[0], csb[0]);
    CP_COMMIT();

    for (int ci = 0; ci < 24; ci++) {
        float* wsc = wsb[ci & 1];
        float* csc = csb[ci & 1];
        CP_WAIT0();
        __syncthreads();
        if (ci < 23) {
            stage(ci + 1, wsb[(ci + 1) & 1], csb[(ci + 1) & 1]);
            CP_COMMIT();
        }
        #pragma unroll 2
        for (int kk = 0; kk < 32; kk++) {
            const float* ar = wsc + kk * 128 + ty * 8;
            float4 a0 = *(const float4*)ar;
            float4 a1 = *(const float4*)(ar + 4);
            float av[8] = {a0.x, a0.y, a0.z, a0.w, a1.x, a1.y, a1.z, a1.w};
            const float* br = csc + kk * 128 + tx * 16;
            // first 8 j (4 packed)
            {
                ulonglong2 bb0 = *(const ulonglong2*)br;
                ulonglong2 bb1 = *(const ulonglong2*)(br + 4);
                ull bp[4] = {bb0.x, bb0.y, bb1.x, bb1.y};
                #pragma unroll
                for (int i = 0; i < 8; i++) {
                    ull ai = pk2(av[i]);
                    #pragma unroll
                    for (int j2 = 0; j2 < 4; j2++) fma2(acc[i][j2], ai, bp[j2]);
                }
            }
            // second 8 j
            {
                ulonglong2 bb2 = *(const ulonglong2*)(br + 8);
                ulonglong2 bb3 = *(const ulonglong2*)(br + 12);
                ull bp[4] = {bb2.x, bb2.y, bb3.x, bb3.y};
                #pragma unroll
                for (int i = 0; i < 8; i++) {
                    ull ai = pk2(av[i]);
                    #pragma unroll
                    for (int j2 = 0; j2 < 4; j2++) fma2(acc[i][4 + j2], ai, bp[j2]);
                }
            }
        }
        __syncthreads();
    }

    // epilogue: store transposed to [b][l][o]
    #pragma unroll
    for (int j2 = 0; j2 < 8; j2++) {
        float2 col[8];
        #pragma unroll
        for (int i = 0; i < 8; i++) col[i] = up2(acc[i][j2]);
        size_t base0 = ((size_t)b * Ldim + l0 + tx * 16 + 2 * j2) * Ddim + o0 + ty * 8;
        *(float4*)(out + base0)     = make_float4(col[0].x, col[1].x, col[2].x, col[3].x);
        *(float4*)(out + base0 + 4) = make_float4(col[4].x, col[5].x, col[6].x, col[7].x);
        size_t base1 = base0 + Ddim;
        *(float4*)(out + base1)     = make_float4(col[0].y, col[1].y, col[2].y, col[3].y);
        *(float4*)(out + base1 + 4) = make_float4(col[4].y, col[5].y, col[6].y, col[7].y);
    }
}

// ------------------- K4: final row RMSNorm (in place) -------------------
__global__ __launch_bounds__(256) void k_norm(float* __restrict__ out,
                                              const float* __restrict__ nsc) {
    __shared__ float ns[512];
    int tid = threadIdx.x;
    ns[tid] = nsc[tid];
    ns[tid + 256] = nsc[tid + 256];
    __syncthreads();

    int warp = tid >> 5, lane = tid & 31;
    size_t row = (size_t)blockIdx.x * 8 + warp;
    float* p = out + row * Ddim;

    float4 v[4];
    float ssq = 0.f;
    #pragma unroll
    for (int q = 0; q < 4; q++) {
        v[q] = *(const float4*)(p + (q * 32 + lane) * 4);
        ssq += v[q].x * v[q].x + v[q].y * v[q].y + v[q].z * v[q].z + v[q].w * v[q].w;
    }
    #pragma unroll
    for (int off = 16; off > 0; off >>= 1)
        ssq += __shfl_xor_sync(0xFFFFFFFFu, ssq, off);
    float rms = sqrtf(ssq * (1.f / 512.f));
    float inv = 1.f / (rms + EPSF);
    #pragma unroll
    for (int q = 0; q < 4; q++) {
        int base = (q * 32 + lane) * 4;
        float4 w;
        w.x = v[q].x * ns[base + 0] * inv;
        w.y = v[q].y * ns[base + 1] * inv;
        w.z = v[q].z * ns[base + 2] * inv;
        w.w = v[q].w * ns[base + 3] * inv;
        *(float4*)(p + base) = w;
    }
}

// ------------------- launch -------------------
extern "C" void kernel_launch(void* const* d_in, const int* in_sizes, int n_in,
                              void* d_out, int out_size) {
    const float* x = (const float*)d_in[0];
    const float *dw[4], *pw[4], *cnp[4];
    if (in_sizes[2] == 768) {
        for (int i = 0; i < 4; i++) {
            dw[i]  = (const float*)d_in[1 + i];
            pw[i]  = (const float*)d_in[5 + i];
            cnp[i] = (const float*)d_in[9 + i];
        }
    } else {
        for (int i = 0; i < 4; i++) {
            dw[i]  = (const float*)d_in[1 + 3 * i];
            pw[i]  = (const float*)d_in[2 + 3 * i];
            cnp[i] = (const float*)d_in[3 + 3 * i];
        }
    }
    const float* w1  = (const float*)d_in[13];
    const float* b1  = (const float*)d_in[14];
    const float* w2  = (const float*)d_in[15];
    const float* b2  = (const float*)d_in[16];
    const float* fw  = (const float*)d_in[17];
    const float* nsc = (const float*)d_in[18];
    const float* rw  = (const float*)d_in[19];
    float* out = (float*)d_out;

    const int SM_CONV  = 75520;
    const int SM_ATTN  = 76288;
    const int SM_FINAL = 65536;
    cudaFuncSetAttribute(k_conv,  cudaFuncAttributeMaxDynamicSharedMemorySize, SM_CONV);
    cudaFuncSetAttribute(k_attn,  cudaFuncAttributeMaxDynamicSharedMemorySize, SM_ATTN);
    cudaFuncSetAttribute(k_final, cudaFuncAttributeMaxDynamicSharedMemorySize, SM_FINAL);

    k_prep<<<WT_TOTAL / 256, 256>>>(pw[0], pw[1], pw[2], pw[3], w1, fw, rw);
    k_xT<<<dim3(Ldim / 32, Cdim / 32, Bdim), 256>>>(x);
    k_conv<<<dim3(Ldim / 128, Bdim, 4), 256, SM_CONV>>>(x, dw[0], dw[1], dw[2], dw[3],
                                                        cnp[0], cnp[1], cnp[2], cnp[3]);
    k_attn<<<dim3(Ldim / 128, Bdim), 256, SM_ATTN>>>(b1, w2, b2);
    k_weight<<<(int)(((size_t)Bdim * Ddim * Ldim) / (256 * 8)), 256>>>();
    k_final<<<dim3(Ldim / 128, 4, Bdim), 128, SM_FINAL>>>(out);
    k_norm<<<(Bdim * Ldim) / 8, 256>>>(out, nsc);
}

// round 7
// speedup vs baseline: 1.3908x; 1.3812x over previous
#include <cuda_runtime.h>
#include <math.h>

#define Bdim 16
#define Ldim 4096
#define Cdim 256
#define Ddim 512
#define EPSF 1e-8f

typedef unsigned long long ull;

// ------------------- scratch (device globals; no allocs allowed) -------------------
__device__ float g_feats[(size_t)Bdim * Ddim * Ldim];   // [b][d=512][l]
__device__ float g_attn[(size_t)Bdim * 4 * Ldim];       // [b][i][l]
__device__ float g_wT[589824];                          // transposed weights

#define OFF_PWT 0        // [4][256][128]
#define OFF_W1T 131072   // [512][128]
#define OFF_FWT 196608   // [512][512]
#define OFF_RWT 458752   // [256][512]
#define WT_TOTAL 589824

// ------------------- packed f32x2 + cp.async helpers -------------------
__device__ __forceinline__ ull pk2(float x) {
    ull r; asm("mov.b64 %0, {%1, %1};" : "=l"(r) : "f"(x)); return r;
}
__device__ __forceinline__ void fma2(ull& c, ull a, ull b) {
    asm("fma.rn.f32x2 %0, %1, %2, %0;" : "+l"(c) : "l"(a), "l"(b));
}
__device__ __forceinline__ float2 up2(ull v) {
    float2 f; asm("mov.b64 {%0, %1}, %2;" : "=f"(f.x), "=f"(f.y) : "l"(v)); return f;
}
__device__ __forceinline__ void cpa16(float* dst, const float* src) {
    unsigned s = (unsigned)__cvta_generic_to_shared(dst);
    asm volatile("cp.async.cg.shared.global [%0], [%1], 16;" :: "r"(s), "l"(src));
}
#define CP_COMMIT() asm volatile("cp.async.commit_group;")
#define CP_WAIT0()  asm volatile("cp.async.wait_group 0;" ::: "memory")

// 8x8 micro-tile GEMM step over a 32-deep k-chunk, f32x2-packed along j.
template <int BS>
__device__ __forceinline__ void gemm_step2(const float* __restrict__ A,
                                           const float* __restrict__ Bm,
                                           int ty, int tx, ull acc[8][4]) {
    #pragma unroll 8
    for (int kk = 0; kk < 32; kk++) {
        const float* ar = A + kk * 128 + ty * 8;
        const float* br = Bm + kk * BS + tx * 8;
        float4 a0 = *(const float4*)ar;
        float4 a1 = *(const float4*)(ar + 4);
        ulonglong2 bb0 = *(const ulonglong2*)br;
        ulonglong2 bb1 = *(const ulonglong2*)(br + 4);
        ull bp[4] = {bb0.x, bb0.y, bb1.x, bb1.y};
        float av[8] = {a0.x, a0.y, a0.z, a0.w, a1.x, a1.y, a1.z, a1.w};
        #pragma unroll
        for (int i = 0; i < 8; i++) {
            ull ai = pk2(av[i]);
            #pragma unroll
            for (int j2 = 0; j2 < 4; j2++) fma2(acc[i][j2], ai, bp[j2]);
        }
    }
}

__device__ __forceinline__ void unpack_acc(const ull a[8][4], float f[8][8]) {
    #pragma unroll
    for (int i = 0; i < 8; i++)
        #pragma unroll
        for (int j2 = 0; j2 < 4; j2++) {
            float2 p = up2(a[i][j2]);
            f[i][2 * j2] = p.x;
            f[i][2 * j2 + 1] = p.y;
        }
}

// warp footprint = 4 ty x 8 tx
#define TILE_COORDS(tid, tx, ty)                         \
    int lane_ = (tid) & 31, warp_ = (tid) >> 5;          \
    int tx = ((warp_ & 1) << 3) | (lane_ & 7);           \
    int ty = ((warp_ >> 1) << 2) | (lane_ >> 3);

// ------------------- K0: weight transposes -------------------
__global__ void k_prep(const float* __restrict__ pw1, const float* __restrict__ pw3,
                       const float* __restrict__ pw5, const float* __restrict__ pw7,
                       const float* __restrict__ w1, const float* __restrict__ fw,
                       const float* __restrict__ rw) {
    int idx = blockIdx.x * blockDim.x + threadIdx.x;
    if (idx >= WT_TOTAL) return;
    float v;
    if (idx < OFF_W1T) {
        int s = idx >> 15;
        int r = idx & 32767;
        int c = r >> 7, o = r & 127;
        const float* pw = (s == 0) ? pw1 : (s == 1) ? pw3 : (s == 2) ? pw5 : pw7;
        v = pw[o * Cdim + c];
    } else if (idx < OFF_FWT) {
        int r = idx - OFF_W1T;
        int c = r >> 7, o = r & 127;
        v = w1[o * Ddim + c];
    } else if (idx < OFF_RWT) {
        int r = idx - OFF_FWT;
        int c = r >> 9, o = r & 511;
        v = fw[o * Ddim + c];
    } else {
        int r = idx - OFF_RWT;
        int c = r >> 9, o = r & 511;
        v = rw[o * Cdim + c];
    }
    g_wT[idx] = v;
}

// ------------------- K1: depthwise conv + pointwise + channel RMSNorm + GELU -------------------
__global__ __launch_bounds__(256, 2) void k_conv(
    const float* __restrict__ x,
    const float* __restrict__ dw1, const float* __restrict__ dw3,
    const float* __restrict__ dw5, const float* __restrict__ dw7,
    const float* __restrict__ cn1, const float* __restrict__ cn3,
    const float* __restrict__ cn5, const float* __restrict__ cn7) {
    extern __shared__ float sm[];
    float* xs  = sm;                 // [134][32]
    float* hs  = sm + 4288;          // [32][132]
    float* ws0 = sm + 8512;
    float* ws1 = sm + 12608;
    float* red = sm + 16704;         // [128][17]

    int tid = threadIdx.x;
    int lt = blockIdx.x, b = blockIdx.y, sc = blockIdx.z;
    int l0 = lt * 128;
    int k = 2 * sc + 1;
    int r = sc;
    const float* dw = (sc == 0) ? dw1 : (sc == 1) ? dw3 : (sc == 2) ? dw5 : dw7;
    const float* cn = (sc == 0) ? cn1 : (sc == 1) ? cn3 : (sc == 2) ? cn5 : cn7;
    const float* pwT = g_wT + OFF_PWT + sc * 32768;

    ull acc[8][4];
    #pragma unroll
    for (int i = 0; i < 8; i++)
        #pragma unroll
        for (int j = 0; j < 4; j++) acc[i][j] = 0ull;

    int cld = tid & 31, lg = tid >> 5;
    TILE_COORDS(tid, tx, ty);

    float xr[17];
    #pragma unroll
    for (int q = 0; q < 17; q++) {
        int i = lg + 8 * q;
        if (i < 134) {
            int gl = l0 - 3 + i;
            xr[q] = (gl >= 0 && gl < Ldim) ? x[((size_t)b * Ldim + gl) * Cdim + cld] : 0.f;
        }
    }
    #pragma unroll
    for (int q = 0; q < 4; q++) {
        int idx = q * 256 + tid, kk = idx >> 5, seg = (idx & 31) << 2;
        cpa16(ws0 + kk * 128 + seg, pwT + (size_t)kk * 128 + seg);
    }
    CP_COMMIT();

    for (int c0 = 0, ci = 0; c0 < Cdim; c0 += 32, ci++) {
        float* wsc = (ci & 1) ? ws1 : ws0;
        float* wsn = (ci & 1) ? ws0 : ws1;
        CP_WAIT0();
        #pragma unroll
        for (int q = 0; q < 17; q++) {
            int i = lg + 8 * q;
            if (i < 134) xs[i * 32 + cld] = xr[q];
        }
        __syncthreads();
        float rd[7];
        #pragma unroll
        for (int t = 0; t < 7; t++) rd[t] = (t < k) ? dw[(c0 + cld) * k + t] : 0.f;
        #pragma unroll
        for (int ii = 0; ii < 16; ii++) {
            int l = lg * 16 + ii;
            float s = 0.f;
            for (int t = 0; t < k; t++) s += rd[t] * xs[(l + 3 - r + t) * 32 + cld];
            hs[cld * 132 + l] = s;
        }
        if (c0 + 32 < Cdim) {
            #pragma unroll
            for (int q = 0; q < 17; q++) {
                int i = lg + 8 * q;
                if (i < 134) {
                    int gl = l0 - 3 + i;
                    xr[q] = (gl >= 0 && gl < Ldim)
                          ? x[((size_t)b * Ldim + gl) * Cdim + c0 + 32 + cld] : 0.f;
                }
            }
            #pragma unroll
            for (int q = 0; q < 4; q++) {
                int idx = q * 256 + tid, kk = idx >> 5, seg = (idx & 31) << 2;
                cpa16(wsn + kk * 128 + seg, pwT + (size_t)(c0 + 32 + kk) * 128 + seg);
            }
            CP_COMMIT();
        }
        __syncthreads();
        gemm_step2<132>(wsc, hs, ty, tx, acc);
        __syncthreads();
    }

    float accf[8][8];
    unpack_acc(acc, accf);

    #pragma unroll
    for (int j = 0; j < 8; j++) {
        float p = 0.f;
        #pragma unroll
        for (int i = 0; i < 8; i++) p += accf[i][j] * accf[i][j];
        red[(tx * 8 + j) * 17 + ty] = p;
    }
    __syncthreads();
    float inv[8];
    #pragma unroll
    for (int j = 0; j < 8; j++) {
        float s = 0.f;
        #pragma unroll
        for (int t = 0; t < 16; t++) s += red[(tx * 8 + j) * 17 + t];
        float rms = sqrtf(s * (1.f / 128.f));
        inv[j] = 1.f / (rms + EPSF);
    }
    float cnv[8];
    #pragma unroll
    for (int i = 0; i < 8; i++) cnv[i] = cn[ty * 8 + i];
    #pragma unroll
    for (int i = 0; i < 8; i++) {
        float v[8];
        #pragma unroll
        for (int j = 0; j < 8; j++) {
            float h = accf[i][j] * cnv[i] * inv[j];
            v[j] = h * normcdff(h);
        }
        size_t base = ((size_t)b * Ddim + sc * 128 + ty * 8 + i) * Ldim + l0 + tx * 8;
        *(float4*)(g_feats + base) = make_float4(v[0], v[1], v[2], v[3]);
        *(float4*)(g_feats + base + 4) = make_float4(v[4], v[5], v[6], v[7]);
    }
}

// ------------------- K2: attention MLP + softmax -------------------
__global__ __launch_bounds__(256, 2) void k_attn(const float* __restrict__ b1p,
                                                 const float* __restrict__ w2p,
                                                 const float* __restrict__ b2p) {
    extern __shared__ float sm[];
    float* ws0 = sm;
    float* ws1 = sm + 4096;
    float* fs0 = sm + 8192;
    float* fs1 = sm + 12288;
    float* w2s = sm + 18560;

    int tid = threadIdx.x;
    int b = blockIdx.y;
    int l0 = blockIdx.x * 128;
    const float* w1T = g_wT + OFF_W1T;

    w2s[tid] = w2p[tid];
    w2s[tid + 256] = w2p[tid + 256];

    ull acc[8][4];
    #pragma unroll
    for (int i = 0; i < 8; i++)
        #pragma unroll
        for (int j = 0; j < 4; j++) acc[i][j] = 0ull;

    TILE_COORDS(tid, tx, ty);

    #pragma unroll
    for (int q = 0; q < 4; q++) {
        int idx = q * 256 + tid, kk = idx >> 5, seg = (idx & 31) << 2;
        cpa16(ws0 + kk * 128 + seg, w1T + (size_t)kk * 128 + seg);
        cpa16(fs0 + kk * 128 + seg, g_feats + ((size_t)b * Ddim + kk) * Ldim + l0 + seg);
    }
    CP_COMMIT();

    for (int ci = 0; ci < 16; ci++) {
        float* wsc = (ci & 1) ? ws1 : ws0;
        float* fsc = (ci & 1) ? fs1 : fs0;
        CP_WAIT0();
        __syncthreads();
        if (ci < 15) {
            float* wsn = (ci & 1) ? ws0 : ws1;
            float* fsn = (ci & 1) ? fs0 : fs1;
            int c0 = (ci + 1) * 32;
            #pragma unroll
            for (int q = 0; q < 4; q++) {
                int idx = q * 256 + tid, kk = idx >> 5, seg = (idx & 31) << 2;
                cpa16(wsn + kk * 128 + seg, w1T + (size_t)(c0 + kk) * 128 + seg);
                cpa16(fsn + kk * 128 + seg, g_feats + ((size_t)b * Ddim + c0 + kk) * Ldim + l0 + seg);
            }
            CP_COMMIT();
        }
        gemm_step2<128>(wsc, fsc, ty, tx, acc);
    }
    __syncthreads();   // mainloop smem (ws/fs) dead after this point

    float accf[8][8];
    unpack_acc(acc, accf);

    float b1v[8];
    #pragma unroll
    for (int i = 0; i < 8; i++) b1v[i] = b1p[ty * 8 + i];
    #pragma unroll
    for (int i = 0; i < 8; i++)
        #pragma unroll
        for (int j = 0; j < 8; j++) {
            float h = accf[i][j] + b1v[i];
            accf[i][j] = h * normcdff(h);
        }

    // fused w2 reduce for all 4 scales in ONE smem pass (red4 overlays dead ws/fs)
    float* red4 = sm;   // [4][128][17] floats = 8704 < 16384 dead floats
    #pragma unroll
    for (int i4 = 0; i4 < 4; i4++) {
        float wv[8];
        #pragma unroll
        for (int i = 0; i < 8; i++) wv[i] = w2s[i4 * 128 + ty * 8 + i];
        #pragma unroll
        for (int j = 0; j < 8; j++) {
            float p = 0.f;
            #pragma unroll
            for (int i = 0; i < 8; i++) p += wv[i] * accf[i][j];
            red4[i4 * 2176 + (tx * 8 + j) * 17 + ty] = p;
        }
    }
    __syncthreads();
    float a2[4][8];
    #pragma unroll
    for (int i4 = 0; i4 < 4; i4++) {
        float b2v = b2p[i4];
        #pragma unroll
        for (int j = 0; j < 8; j++) {
            float s = 0.f;
            #pragma unroll
            for (int t = 0; t < 16; t++) s += red4[i4 * 2176 + (tx * 8 + j) * 17 + t];
            a2[i4][j] = s + b2v;
        }
    }

    #pragma unroll
    for (int j = 0; j < 8; j++) {
        float m = fmaxf(fmaxf(a2[0][j], a2[1][j]), fmaxf(a2[2][j], a2[3][j]));
        float s = 0.f;
        #pragma unroll
        for (int i4 = 0; i4 < 4; i4++) {
            a2[i4][j] = expf(a2[i4][j] - m);
            s += a2[i4][j];
        }
        float invs = 1.f / s;
        #pragma unroll
        for (int i4 = 0; i4 < 4; i4++) a2[i4][j] *= invs;
    }
    if (ty == 0) {
        #pragma unroll
        for (int i4 = 0; i4 < 4; i4++) {
            size_t base = ((size_t)b * 4 + i4) * Ldim + l0 + tx * 8;
            *(float4*)(g_attn + base) = make_float4(a2[i4][0], a2[i4][1], a2[i4][2], a2[i4][3]);
            *(float4*)(g_attn + base + 4) = make_float4(a2[i4][4], a2[i4][5], a2[i4][6], a2[i4][7]);
        }
    }
}

// ------------------- K3: final GEMM (feats*attn || x) + residual, pre-norm -------------------
// dyn smem: ws[2][4096] | cs[4224] | am[512] = 51712 B
__global__ __launch_bounds__(256, 2) void k_final(const float* __restrict__ x,
                                                  float* __restrict__ out) {
    extern __shared__ float sm[];
    float* ws0 = sm;
    float* ws1 = sm + 4096;
    float* cs  = sm + 8192;   // [32][132]
    float* am  = sm + 12416;  // [4][128]

    int tid = threadIdx.x;
    int lt = blockIdx.x, ot = blockIdx.y, b = blockIdx.z;
    int l0 = lt * 128, o0 = ot * 128;

    am[tid]       = g_attn[((size_t)b * 4 + (tid >> 7)) * Ldim + l0 + (tid & 127)];
    am[tid + 256] = g_attn[((size_t)b * 4 + 2 + (tid >> 7)) * Ldim + l0 + (tid & 127)];

    ull acc[8][4];
    #pragma unroll
    for (int i = 0; i < 8; i++)
        #pragma unroll
        for (int j = 0; j < 4; j++) acc[i][j] = 0ull;

    int lw = tid & 127, kk0 = tid >> 7;
    int cld = tid & 31, lg = tid >> 5;
    TILE_COORDS(tid, tx, ty);
    const float* fwT = g_wT + OFF_FWT;
    const float* rwT = g_wT + OFF_RWT;

    float rg[16];
    // prefetch chunk 0 (phase 1)
    #pragma unroll
    for (int q = 0; q < 16; q++) {
        int kk = kk0 + 2 * q;
        rg[q] = g_feats[((size_t)b * Ddim + kk) * Ldim + l0 + lw];
    }
    #pragma unroll
    for (int q = 0; q < 4; q++) {
        int idx = q * 256 + tid, kk = idx >> 5, seg = (idx & 31) << 2;
        cpa16(ws0 + kk * 128 + seg, fwT + (size_t)kk * 512 + o0 + seg);
    }
    CP_COMMIT();
    __syncthreads();   // am visible

    for (int ci = 0; ci < 24; ci++) {
        float* wsc = (ci & 1) ? ws1 : ws0;
        CP_WAIT0();
        // STS current chunk
        if (ci < 16) {
            float amv = am[(ci >> 2) * 128 + lw];
            #pragma unroll
            for (int q = 0; q < 16; q++) cs[(kk0 + 2 * q) * 132 + lw] = rg[q] * amv;
        } else {
            #pragma unroll
            for (int q = 0; q < 16; q++) cs[cld * 132 + lg + 8 * q] = rg[q];
        }
        __syncthreads();
        // prefetch next chunk
        if (ci < 23) {
            int cn = ci + 1;
            if (cn < 16) {
                #pragma unroll
                for (int q = 0; q < 16; q++) {
                    int kk = kk0 + 2 * q;
                    rg[q] = g_feats[((size_t)b * Ddim + cn * 32 + kk) * Ldim + l0 + lw];
                }
            } else {
                #pragma unroll
                for (int q = 0; q < 16; q++) {
                    int lr = lg + 8 * q;
                    rg[q] = x[((size_t)b * Ldim + l0 + lr) * Cdim + (cn - 16) * 32 + cld];
                }
            }
            float* wsn = (ci & 1) ? ws0 : ws1;
            const float* srcb = (cn < 16) ? fwT + (size_t)cn * 32 * 512
                                          : rwT + (size_t)(cn - 16) * 32 * 512;
            #pragma unroll
            for (int q = 0; q < 4; q++) {
                int idx = q * 256 + tid, kk = idx >> 5, seg = (idx & 31) << 2;
                cpa16(wsn + kk * 128 + seg, srcb + (size_t)kk * 512 + o0 + seg);
            }
            CP_COMMIT();
        }
        gemm_step2<132>(wsc, cs, ty, tx, acc);
        __syncthreads();
    }

    float accf[8][8];
    unpack_acc(acc, accf);

    // store transposed to [b][l][o]
    #pragma unroll
    for (int j = 0; j < 8; j++) {
        size_t base = ((size_t)b * Ldim + l0 + tx * 8 + j) * Ddim + o0 + ty * 8;
        *(float4*)(out + base)     = make_float4(accf[0][j], accf[1][j], accf[2][j], accf[3][j]);
        *(float4*)(out + base + 4) = make_float4(accf[4][j], accf[5][j], accf[6][j], accf[7][j]);
    }
}

// ------------------- K4: final row RMSNorm (in place) -------------------
__global__ __launch_bounds__(256) void k_norm(float* __restrict__ out,
                                              const float* __restrict__ nsc) {
    __shared__ float ns[512];
    int tid = threadIdx.x;
    ns[tid] = nsc[tid];
    ns[tid + 256] = nsc[tid + 256];
    __syncthreads();

    int warp = tid >> 5, lane = tid & 31;
    size_t row = (size_t)blockIdx.x * 8 + warp;
    float* p = out + row * Ddim;

    float4 v[4];
    float ssq = 0.f;
    #pragma unroll
    for (int q = 0; q < 4; q++) {
        v[q] = *(const float4*)(p + (q * 32 + lane) * 4);
        ssq += v[q].x * v[q].x + v[q].y * v[q].y + v[q].z * v[q].z + v[q].w * v[q].w;
    }
    #pragma unroll
    for (int off = 16; off > 0; off >>= 1)
        ssq += __shfl_xor_sync(0xFFFFFFFFu, ssq, off);
    float rms = sqrtf(ssq * (1.f / 512.f));
    float inv = 1.f / (rms + EPSF);
    #pragma unroll
    for (int q = 0; q < 4; q++) {
        int base = (q * 32 + lane) * 4;
        float4 w;
        w.x = v[q].x * ns[base + 0] * inv;
        w.y = v[q].y * ns[base + 1] * inv;
        w.z = v[q].z * ns[base + 2] * inv;
        w.w = v[q].w * ns[base + 3] * inv;
        *(float4*)(p + base) = w;
    }
}

// ------------------- launch -------------------
extern "C" void kernel_launch(void* const* d_in, const int* in_sizes, int n_in,
                              void* d_out, int out_size) {
    const float* x = (const float*)d_in[0];
    const float *dw[4], *pw[4], *cnp[4];
    if (in_sizes[2] == 768) {
        for (int i = 0; i < 4; i++) {
            dw[i]  = (const float*)d_in[1 + i];
            pw[i]  = (const float*)d_in[5 + i];
            cnp[i] = (const float*)d_in[9 + i];
        }
    } else {
        for (int i = 0; i < 4; i++) {
            dw[i]  = (const float*)d_in[1 + 3 * i];
            pw[i]  = (const float*)d_in[2 + 3 * i];
            cnp[i] = (const float*)d_in[3 + 3 * i];
        }
    }
    const float* w1  = (const float*)d_in[13];
    const float* b1  = (const float*)d_in[14];
    const float* w2  = (const float*)d_in[15];
    const float* b2  = (const float*)d_in[16];
    const float* fw  = (const float*)d_in[17];
    const float* nsc = (const float*)d_in[18];
    const float* rw  = (const float*)d_in[19];
    float* out = (float*)d_out;

    const int SM_CONV  = 75520;
    const int SM_ATTN  = 76288;
    const int SM_FINAL = 51712;
    cudaFuncSetAttribute(k_conv,  cudaFuncAttributeMaxDynamicSharedMemorySize, SM_CONV);
    cudaFuncSetAttribute(k_attn,  cudaFuncAttributeMaxDynamicSharedMemorySize, SM_ATTN);
    cudaFuncSetAttribute(k_final, cudaFuncAttributeMaxDynamicSharedMemorySize, SM_FINAL);

    k_prep<<<WT_TOTAL / 256, 256>>>(pw[0], pw[1], pw[2], pw[3], w1, fw, rw);
    k_conv<<<dim3(Ldim / 128, Bdim, 4), 256, SM_CONV>>>(x, dw[0], dw[1], dw[2], dw[3],
                                                        cnp[0], cnp[1], cnp[2], cnp[3]);
    k_attn<<<dim3(Ldim / 128, Bdim), 256, SM_ATTN>>>(b1, w2, b2);
    k_final<<<dim3(Ldim / 128, 4, Bdim), 256, SM_FINAL>>>(x, out);
    k_norm<<<(Bdim * Ldim) / 8, 256>>>(out, nsc);
}

// round 9
// speedup vs baseline: 1.8607x; 1.3378x over previous
#include <cuda_runtime.h>
#include <cuda_bf16.h>
#include <math.h>
#include <stdint.h>

#define Bdim 16
#define Ldim 4096
#define Cdim 256
#define Ddim 512
#define EPSF 1e-8f

typedef unsigned long long ull;

// ------------------- scratch (device globals; no allocs allowed) -------------------
__device__ float g_feats[(size_t)Bdim * Ddim * Ldim];   // [b][d=512][l] f32
__device__ float g_attn[(size_t)Bdim * 4 * Ldim];       // [b][i][l]
__device__ float g_wT[196608];                          // transposed weights (scalar kernels)
__device__ __nv_bfloat16 gA_hi[(size_t)Bdim * Ldim * 768];  // [b][l][768]: feats*attn | x
__device__ __nv_bfloat16 gA_lo[(size_t)Bdim * Ldim * 768];
__device__ __nv_bfloat16 gB_hi[512 * 768];                  // [o][768]: fw | rw
__device__ __nv_bfloat16 gB_lo[512 * 768];

#define OFF_PWT 0        // [4][256][128]
#define OFF_W1T 131072   // [512][128]
#define OFF_WEND 196608

// ------------------- packed f32x2 + cp.async helpers -------------------
__device__ __forceinline__ ull pk2(float x) {
    ull r; asm("mov.b64 %0, {%1, %1};" : "=l"(r) : "f"(x)); return r;
}
__device__ __forceinline__ void fma2(ull& c, ull a, ull b) {
    asm("fma.rn.f32x2 %0, %1, %2, %0;" : "+l"(c) : "l"(a), "l"(b));
}
__device__ __forceinline__ float2 up2(ull v) {
    float2 f; asm("mov.b64 {%0, %1}, %2;" : "=f"(f.x), "=f"(f.y) : "l"(v)); return f;
}
__device__ __forceinline__ void cpa16(void* dst, const void* src) {
    unsigned s = (unsigned)__cvta_generic_to_shared(dst);
    asm volatile("cp.async.cg.shared.global [%0], [%1], 16;" :: "r"(s), "l"(src));
}
#define CP_COMMIT() asm volatile("cp.async.commit_group;")
#define CP_WAIT0()  asm volatile("cp.async.wait_group 0;" ::: "memory")

__device__ __forceinline__ uint32_t smem_u32(const void* p) {
    uint32_t a;
    asm("{ .reg .u64 t; cvta.to.shared.u64 t, %1; cvt.u32.u64 %0, t; }" : "=r"(a) : "l"(p));
    return a;
}

// ------------------- mma.sync / ldmatrix helpers (baseline PTX, sm_80+) -------------------
__device__ __forceinline__ void ldm_x4(uint32_t r[4], uint32_t addr) {
    asm volatile("ldmatrix.sync.aligned.m8n8.x4.shared.b16 {%0,%1,%2,%3}, [%4];"
                 : "=r"(r[0]), "=r"(r[1]), "=r"(r[2]), "=r"(r[3]) : "r"(addr));
}
__device__ __forceinline__ void mma_bf16(float c[4], const uint32_t a[4],
                                         uint32_t b0, uint32_t b1) {
    asm volatile("mma.sync.aligned.m16n8k16.row.col.f32.bf16.bf16.f32 "
                 "{%0,%1,%2,%3}, {%4,%5,%6,%7}, {%8,%9}, {%0,%1,%2,%3};"
                 : "+f"(c[0]), "+f"(c[1]), "+f"(c[2]), "+f"(c[3])
                 : "r"(a[0]), "r"(a[1]), "r"(a[2]), "r"(a[3]), "r"(b0), "r"(b1));
}

// ------------------- scalar 8x8 GEMM step (k_conv / k_attn) -------------------
template <int BS>
__device__ __forceinline__ void gemm_step2(const float* __restrict__ A,
                                           const float* __restrict__ Bm,
                                           int ty, int tx, ull acc[8][4]) {
    #pragma unroll 8
    for (int kk = 0; kk < 32; kk++) {
        const float* ar = A + kk * 128 + ty * 8;
        const float* br = Bm + kk * BS + tx * 8;
        float4 a0 = *(const float4*)ar;
        float4 a1 = *(const float4*)(ar + 4);
        ulonglong2 bb0 = *(const ulonglong2*)br;
        ulonglong2 bb1 = *(const ulonglong2*)(br + 4);
        ull bp[4] = {bb0.x, bb0.y, bb1.x, bb1.y};
        float av[8] = {a0.x, a0.y, a0.z, a0.w, a1.x, a1.y, a1.z, a1.w};
        #pragma unroll
        for (int i = 0; i < 8; i++) {
            ull ai = pk2(av[i]);
            #pragma unroll
            for (int j2 = 0; j2 < 4; j2++) fma2(acc[i][j2], ai, bp[j2]);
        }
    }
}

__device__ __forceinline__ void unpack_acc(const ull a[8][4], float f[8][8]) {
    #pragma unroll
    for (int i = 0; i < 8; i++)
        #pragma unroll
        for (int j2 = 0; j2 < 4; j2++) {
            float2 p = up2(a[i][j2]);
            f[i][2 * j2] = p.x;
            f[i][2 * j2 + 1] = p.y;
        }
}

#define TILE_COORDS(tid, tx, ty)                         \
    int lane_ = (tid) & 31, warp_ = (tid) >> 5;          \
    int tx = ((warp_ & 1) << 3) | (lane_ & 7);           \
    int ty = ((warp_ >> 1) << 2) | (lane_ >> 3);

__device__ __forceinline__ void split_bf16(float v, __nv_bfloat16& hi, __nv_bfloat16& lo) {
    hi = __float2bfloat16(v);
    lo = __float2bfloat16(v - __bfloat162float(hi));
}

// ------------------- K0: weight transposes (scalar path) -------------------
__global__ void k_prep(const float* __restrict__ pw1, const float* __restrict__ pw3,
                       const float* __restrict__ pw5, const float* __restrict__ pw7,
                       const float* __restrict__ w1) {
    int idx = blockIdx.x * blockDim.x + threadIdx.x;
    if (idx >= OFF_WEND) return;
    float v;
    if (idx < OFF_W1T) {
        int s = idx >> 15;
        int r = idx & 32767;
        int c = r >> 7, o = r & 127;
        const float* pw = (s == 0) ? pw1 : (s == 1) ? pw3 : (s == 2) ? pw5 : pw7;
        v = pw[o * Cdim + c];
    } else {
        int r = idx - OFF_W1T;
        int c = r >> 7, o = r & 127;
        v = w1[o * Ddim + c];
    }
    g_wT[idx] = v;
}

// ------------------- K0b: weight split: gB = [fw | rw] hi/lo bf16 -------------------
__global__ void k_prepW(const float* __restrict__ fw, const float* __restrict__ rw) {
    int idx = blockIdx.x * blockDim.x + threadIdx.x;   // 512*768
    if (idx >= 512 * 768) return;
    int o = idx / 768, d = idx % 768;
    float v = (d < 512) ? fw[o * 512 + d] : rw[o * 256 + (d - 512)];
    __nv_bfloat16 hi, lo;
    split_bf16(v, hi, lo);
    gB_hi[idx] = hi;
    gB_lo[idx] = lo;
}

// ------------------- K0c: x split into gA cols [512,768) -------------------
__global__ __launch_bounds__(256) void k_xsplit(const float* __restrict__ x) {
    size_t i = ((size_t)blockIdx.x * 256 + threadIdx.x) * 4;
    int c = (int)(i & 255);
    size_t l = (i >> 8) & 4095;
    size_t b = i >> 20;
    float4 v = *(const float4*)(x + i);
    size_t base = (b * 4096 + l) * 768 + 512 + c;
    float vv[4] = {v.x, v.y, v.z, v.w};
    #pragma unroll
    for (int t = 0; t < 4; t++) {
        __nv_bfloat16 hi, lo;
        split_bf16(vv[t], hi, lo);
        gA_hi[base + t] = hi;
        gA_lo[base + t] = lo;
    }
}

// ------------------- K1: depthwise conv + pointwise + channel RMSNorm + GELU -------------------
__global__ __launch_bounds__(256, 2) void k_conv(
    const float* __restrict__ x,
    const float* __restrict__ dw1, const float* __restrict__ dw3,
    const float* __restrict__ dw5, const float* __restrict__ dw7,
    const float* __restrict__ cn1, const float* __restrict__ cn3,
    const float* __restrict__ cn5, const float* __restrict__ cn7) {
    extern __shared__ float sm[];
    float* xs  = sm;                 // [134][32]
    float* hs  = sm + 4288;          // [32][132]
    float* ws0 = sm + 8512;
    float* ws1 = sm + 12608;
    float* red = sm + 16704;         // [128][17]

    int tid = threadIdx.x;
    int lt = blockIdx.x, b = blockIdx.y, sc = blockIdx.z;
    int l0 = lt * 128;
    int k = 2 * sc + 1;
    int r = sc;
    const float* dw = (sc == 0) ? dw1 : (sc == 1) ? dw3 : (sc == 2) ? dw5 : dw7;
    const float* cn = (sc == 0) ? cn1 : (sc == 1) ? cn3 : (sc == 2) ? cn5 : cn7;
    const float* pwT = g_wT + OFF_PWT + sc * 32768;

    ull acc[8][4];
    #pragma unroll
    for (int i = 0; i < 8; i++)
        #pragma unroll
        for (int j = 0; j < 4; j++) acc[i][j] = 0ull;

    int cld = tid & 31, lg = tid >> 5;
    TILE_COORDS(tid, tx, ty);

    float xr[17];
    #pragma unroll
    for (int q = 0; q < 17; q++) {
        int i = lg + 8 * q;
        if (i < 134) {
            int gl = l0 - 3 + i;
            xr[q] = (gl >= 0 && gl < Ldim) ? x[((size_t)b * Ldim + gl) * Cdim + cld] : 0.f;
        }
    }
    #pragma unroll
    for (int q = 0; q < 4; q++) {
        int idx = q * 256 + tid, kk = idx >> 5, seg = (idx & 31) << 2;
        cpa16(ws0 + kk * 128 + seg, pwT + (size_t)kk * 128 + seg);
    }
    CP_COMMIT();

    for (int c0 = 0, ci = 0; c0 < Cdim; c0 += 32, ci++) {
        float* wsc = (ci & 1) ? ws1 : ws0;
        float* wsn = (ci & 1) ? ws0 : ws1;
        CP_WAIT0();
        #pragma unroll
        for (int q = 0; q < 17; q++) {
            int i = lg + 8 * q;
            if (i < 134) xs[i * 32 + cld] = xr[q];
        }
        __syncthreads();
        float rd[7];
        #pragma unroll
        for (int t = 0; t < 7; t++) rd[t] = (t < k) ? dw[(c0 + cld) * k + t] : 0.f;
        #pragma unroll
        for (int ii = 0; ii < 16; ii++) {
            int l = lg * 16 + ii;
            float s = 0.f;
            for (int t = 0; t < k; t++) s += rd[t] * xs[(l + 3 - r + t) * 32 + cld];
            hs[cld * 132 + l] = s;
        }
        if (c0 + 32 < Cdim) {
            #pragma unroll
            for (int q = 0; q < 17; q++) {
                int i = lg + 8 * q;
                if (i < 134) {
                    int gl = l0 - 3 + i;
                    xr[q] = (gl >= 0 && gl < Ldim)
                          ? x[((size_t)b * Ldim + gl) * Cdim + c0 + 32 + cld] : 0.f;
                }
            }
            #pragma unroll
            for (int q = 0; q < 4; q++) {
                int idx = q * 256 + tid, kk = idx >> 5, seg = (idx & 31) << 2;
                cpa16(wsn + kk * 128 + seg, pwT + (size_t)(c0 + 32 + kk) * 128 + seg);
            }
            CP_COMMIT();
        }
        __syncthreads();
        gemm_step2<132>(wsc, hs, ty, tx, acc);
        __syncthreads();
    }

    float accf[8][8];
    unpack_acc(acc, accf);

    #pragma unroll
    for (int j = 0; j < 8; j++) {
        float p = 0.f;
        #pragma unroll
        for (int i = 0; i < 8; i++) p += accf[i][j] * accf[i][j];
        red[(tx * 8 + j) * 17 + ty] = p;
    }
    __syncthreads();
    float inv[8];
    #pragma unroll
    for (int j = 0; j < 8; j++) {
        float s = 0.f;
        #pragma unroll
        for (int t = 0; t < 16; t++) s += red[(tx * 8 + j) * 17 + t];
        float rms = sqrtf(s * (1.f / 128.f));
        inv[j] = 1.f / (rms + EPSF);
    }
    float cnv[8];
    #pragma unroll
    for (int i = 0; i < 8; i++) cnv[i] = cn[ty * 8 + i];
    #pragma unroll
    for (int i = 0; i < 8; i++) {
        float v[8];
        #pragma unroll
        for (int j = 0; j < 8; j++) {
            float h = accf[i][j] * cnv[i] * inv[j];
            v[j] = h * normcdff(h);
        }
        size_t base = ((size_t)b * Ddim + sc * 128 + ty * 8 + i) * Ldim + l0 + tx * 8;
        *(float4*)(g_feats + base) = make_float4(v[0], v[1], v[2], v[3]);
        *(float4*)(g_feats + base + 4) = make_float4(v[4], v[5], v[6], v[7]);
    }
}

// ------------------- K2: attention MLP + softmax -------------------
__global__ __launch_bounds__(256, 2) void k_attn(const float* __restrict__ b1p,
                                                 const float* __restrict__ w2p,
                                                 const float* __restrict__ b2p) {
    extern __shared__ float sm[];
    float* ws0 = sm;
    float* ws1 = sm + 4096;
    float* fs0 = sm + 8192;
    float* fs1 = sm + 12288;
    float* w2s = sm + 18560;

    int tid = threadIdx.x;
    int b = blockIdx.y;
    int l0 = blockIdx.x * 128;
    const float* w1T = g_wT + OFF_W1T;

    w2s[tid] = w2p[tid];
    w2s[tid + 256] = w2p[tid + 256];

    ull acc[8][4];
    #pragma unroll
    for (int i = 0; i < 8; i++)
        #pragma unroll
        for (int j = 0; j < 4; j++) acc[i][j] = 0ull;

    TILE_COORDS(tid, tx, ty);

    #pragma unroll
    for (int q = 0; q < 4; q++) {
        int idx = q * 256 + tid, kk = idx >> 5, seg = (idx & 31) << 2;
        cpa16(ws0 + kk * 128 + seg, w1T + (size_t)kk * 128 + seg);
        cpa16(fs0 + kk * 128 + seg, g_feats + ((size_t)b * Ddim + kk) * Ldim + l0 + seg);
    }
    CP_COMMIT();

    for (int ci = 0; ci < 16; ci++) {
        float* wsc = (ci & 1) ? ws1 : ws0;
        float* fsc = (ci & 1) ? fs1 : fs0;
        CP_WAIT0();
        __syncthreads();
        if (ci < 15) {
            float* wsn = (ci & 1) ? ws0 : ws1;
            float* fsn = (ci & 1) ? fs0 : fs1;
            int c0 = (ci + 1) * 32;
            #pragma unroll
            for (int q = 0; q < 4; q++) {
                int idx = q * 256 + tid, kk = idx >> 5, seg = (idx & 31) << 2;
                cpa16(wsn + kk * 128 + seg, w1T + (size_t)(c0 + kk) * 128 + seg);
                cpa16(fsn + kk * 128 + seg, g_feats + ((size_t)b * Ddim + c0 + kk) * Ldim + l0 + seg);
            }
            CP_COMMIT();
        }
        gemm_step2<128>(wsc, fsc, ty, tx, acc);
    }
    __syncthreads();

    float accf[8][8];
    unpack_acc(acc, accf);

    float b1v[8];
    #pragma unroll
    for (int i = 0; i < 8; i++) b1v[i] = b1p[ty * 8 + i];
    #pragma unroll
    for (int i = 0; i < 8; i++)
        #pragma unroll
        for (int j = 0; j < 8; j++) {
            float h = accf[i][j] + b1v[i];
            accf[i][j] = h * normcdff(h);
        }

    float* red4 = sm;   // overlay dead ws/fs
    #pragma unroll
    for (int i4 = 0; i4 < 4; i4++) {
        float wv[8];
        #pragma unroll
        for (int i = 0; i < 8; i++) wv[i] = w2s[i4 * 128 + ty * 8 + i];
        #pragma unroll
        for (int j = 0; j < 8; j++) {
            float p = 0.f;
            #pragma unroll
            for (int i = 0; i < 8; i++) p += wv[i] * accf[i][j];
            red4[i4 * 2176 + (tx * 8 + j) * 17 + ty] = p;
        }
    }
    __syncthreads();
    float a2[4][8];
    #pragma unroll
    for (int i4 = 0; i4 < 4; i4++) {
        float b2v = b2p[i4];
        #pragma unroll
        for (int j = 0; j < 8; j++) {
            float s = 0.f;
            #pragma unroll
            for (int t = 0; t < 16; t++) s += red4[i4 * 2176 + (tx * 8 + j) * 17 + t];
            a2[i4][j] = s + b2v;
        }
    }

    #pragma unroll
    for (int j = 0; j < 8; j++) {
        float m = fmaxf(fmaxf(a2[0][j], a2[1][j]), fmaxf(a2[2][j], a2[3][j]));
        float s = 0.f;
        #pragma unroll
        for (int i4 = 0; i4 < 4; i4++) {
            a2[i4][j] = expf(a2[i4][j] - m);
            s += a2[i4][j];
        }
        float invs = 1.f / s;
        #pragma unroll
        for (int i4 = 0; i4 < 4; i4++) a2[i4][j] *= invs;
    }
    if (ty == 0) {
        #pragma unroll
        for (int i4 = 0; i4 < 4; i4++) {
            size_t base = ((size_t)b * 4 + i4) * Ldim + l0 + tx * 8;
            *(float4*)(g_attn + base) = make_float4(a2[i4][0], a2[i4][1], a2[i4][2], a2[i4][3]);
            *(float4*)(g_attn + base + 4) = make_float4(a2[i4][4], a2[i4][5], a2[i4][6], a2[i4][7]);
        }
    }
}

// ------------------- K2b: weighted feats -> transposed bf16 hi/lo gA cols [0,512) -------------------
__global__ __launch_bounds__(256) void k_wfeats() {
    __shared__ float t[32][33];
    int b = blockIdx.z;
    int d0 = blockIdx.y * 32, l0 = blockIdx.x * 32;
    int tid = threadIdx.x;
    int tc = tid & 31, tr = tid >> 5;
    int s = d0 >> 7;
    #pragma unroll
    for (int q = 0; q < 4; q++) {
        int d = tr + q * 8;
        t[d][tc] = g_feats[((size_t)b * Ddim + d0 + d) * Ldim + l0 + tc];
    }
    __syncthreads();
    #pragma unroll
    for (int q = 0; q < 4; q++) {
        int lrow = tr + q * 8;
        float av = g_attn[((size_t)b * 4 + s) * Ldim + l0 + lrow];
        float v = t[tc][lrow] * av;
        __nv_bfloat16 hi, lo;
        split_bf16(v, hi, lo);
        size_t o = ((size_t)b * Ldim + l0 + lrow) * 768 + d0 + tc;
        gA_hi[o] = hi;
        gA_lo[o] = lo;
    }
}

// ------------------- K3: mma.sync bf16x3 final GEMM -------------------
// CTA tile M=128(l) x N=64(o), warp grid 4x2, warp tile 32x32; K chunks of 32.
// smem rows padded to 80B; per buffer: Ah 10240 | Al 10240 | Bh 5120 | Bl 5120 = 30720B; x2 = 61440B.
__global__ __launch_bounds__(256, 2) void k_final_mma(float* __restrict__ out) {
    extern __shared__ char smc[];
    int tid = threadIdx.x, lane = tid & 31, warp = tid >> 5;
    int wm = warp >> 1, wn = warp & 1;
    int lt = blockIdx.x, ot = blockIdx.y, b = blockIdx.z;
    int l0 = lt * 128, o0 = ot * 64;

    const __nv_bfloat16* Ahg = gA_hi + ((size_t)b * Ldim + l0) * 768;
    const __nv_bfloat16* Alg = gA_lo + ((size_t)b * Ldim + l0) * 768;
    const __nv_bfloat16* Bhg = gB_hi + (size_t)o0 * 768;
    const __nv_bfloat16* Blg = gB_lo + (size_t)o0 * 768;

    float c[2][4][4];
    #pragma unroll
    for (int t = 0; t < 2; t++)
        #pragma unroll
        for (int n = 0; n < 4; n++)
            #pragma unroll
            for (int q = 0; q < 4; q++) c[t][n][q] = 0.f;

    auto stage = [&](int kc, int bs) {
        char* base = smc + bs * 30720;
        int k0 = kc * 32;
        #pragma unroll
        for (int q = 0; q < 2; q++) {        // A hi/lo: 128 rows x 4 segs
            int idx = q * 256 + tid, row = idx >> 2, seg = idx & 3;
            size_t go = (size_t)row * 768 + k0 + seg * 8;
            cpa16(base + row * 80 + seg * 16, Ahg + go);
            cpa16(base + 10240 + row * 80 + seg * 16, Alg + go);
        }
        {                                    // B hi/lo: 64 rows x 4 segs
            int row = tid >> 2, seg = tid & 3;
            size_t go = (size_t)row * 768 + k0 + seg * 8;
            cpa16(base + 20480 + row * 80 + seg * 16, Bhg + go);
            cpa16(base + 25600 + row * 80 + seg * 16, Blg + go);
        }
    };

    uint32_t sb = smem_u32(smc);
    stage(0, 0);
    CP_COMMIT();

    for (int ci = 0; ci < 24; ci++) {
        CP_WAIT0();
        __syncthreads();
        if (ci < 23) {
            stage(ci + 1, (ci + 1) & 1);
            CP_COMMIT();
        }
        uint32_t buf = sb + (ci & 1) * 30720;
        #pragma unroll
        for (int s = 0; s < 2; s++) {
            int k0 = s * 16;
            // A fragments: rows = l, plain ldmatrix.x4
            uint32_t ah[2][4], al[2][4];
            #pragma unroll
            for (int t = 0; t < 2; t++) {
                int row = wm * 32 + t * 16 + (lane & 15);
                uint32_t col = (uint32_t)(k0 + ((lane >> 4) << 3));
                uint32_t ad = buf + row * 80 + col * 2;
                ldm_x4(ah[t], ad);
                ldm_x4(al[t], ad + 10240);
            }
            // B fragments: rows = o, plain ldmatrix.x4 (2 n8-tiles per call)
            uint32_t bh[2][4], bl[2][4];
            int quad = lane >> 3, rr = lane & 7;
            #pragma unroll
            for (int p = 0; p < 2; p++) {
                int n = wn * 32 + p * 16 + ((quad >> 1) << 3) + rr;
                uint32_t kcol = (uint32_t)(k0 + ((quad & 1) << 3));
                uint32_t bd = buf + 20480 + n * 80 + kcol * 2;
                ldm_x4(bh[p], bd);
                ldm_x4(bl[p], bd + 5120);
            }
            #pragma unroll
            for (int t = 0; t < 2; t++)
                #pragma unroll
                for (int nt = 0; nt < 4; nt++) {
                    int p = nt >> 1, w2 = (nt & 1) * 2;
                    mma_bf16(c[t][nt], ah[t], bh[p][w2], bh[p][w2 + 1]);
                    mma_bf16(c[t][nt], ah[t], bl[p][w2], bl[p][w2 + 1]);
                    mma_bf16(c[t][nt], al[t], bh[p][w2], bh[p][w2 + 1]);
                }
        }
    }

    // epilogue: c0,c1 -> row gid, cols tig*2,+1; c2,c3 -> row gid+8
    int gid = lane >> 2, tig = lane & 3;
    #pragma unroll
    for (int t = 0; t < 2; t++) {
        size_t r0 = (size_t)b * Ldim + l0 + wm * 32 + t * 16 + gid;
        #pragma unroll
        for (int nt = 0; nt < 4; nt++) {
            int o = o0 + wn * 32 + nt * 8 + tig * 2;
            *(float2*)(out + r0 * Ddim + o)       = make_float2(c[t][nt][0], c[t][nt][1]);
            *(float2*)(out + (r0 + 8) * Ddim + o) = make_float2(c[t][nt][2], c[t][nt][3]);
        }
    }
}

// ------------------- K4: final row RMSNorm (in place) -------------------
__global__ __launch_bounds__(256) void k_norm(float* __restrict__ out,
                                              const float* __restrict__ nsc) {
    __shared__ float ns[512];
    int tid = threadIdx.x;
    ns[tid] = nsc[tid];
    ns[tid + 256] = nsc[tid + 256];
    __syncthreads();

    int warp = tid >> 5, lane = tid & 31;
    size_t row = (size_t)blockIdx.x * 8 + warp;
    float* p = out + row * Ddim;

    float4 v[4];
    float ssq = 0.f;
    #pragma unroll
    for (int q = 0; q < 4; q++) {
        v[q] = *(const float4*)(p + (q * 32 + lane) * 4);
        ssq += v[q].x * v[q].x + v[q].y * v[q].y + v[q].z * v[q].z + v[q].w * v[q].w;
    }
    #pragma unroll
    for (int off = 16; off > 0; off >>= 1)
        ssq += __shfl_xor_sync(0xFFFFFFFFu, ssq, off);
    float rms = sqrtf(ssq * (1.f / 512.f));
    float inv = 1.f / (rms + EPSF);
    #pragma unroll
    for (int q = 0; q < 4; q++) {
        int base = (q * 32 + lane) * 4;
        float4 w;
        w.x = v[q].x * ns[base + 0] * inv;
        w.y = v[q].y * ns[base + 1] * inv;
        w.z = v[q].z * ns[base + 2] * inv;
        w.w = v[q].w * ns[base + 3] * inv;
        *(float4*)(p + base) = w;
    }
}

// ------------------- launch -------------------
extern "C" void kernel_launch(void* const* d_in, const int* in_sizes, int n_in,
                              void* d_out, int out_size) {
    const float* x = (const float*)d_in[0];
    const float *dw[4], *pw[4], *cnp[4];
    if (in_sizes[2] == 768) {
        for (int i = 0; i < 4; i++) {
            dw[i]  = (const float*)d_in[1 + i];
            pw[i]  = (const float*)d_in[5 + i];
            cnp[i] = (const float*)d_in[9 + i];
        }
    } else {
        for (int i = 0; i < 4; i++) {
            dw[i]  = (const float*)d_in[1 + 3 * i];
            pw[i]  = (const float*)d_in[2 + 3 * i];
            cnp[i] = (const float*)d_in[3 + 3 * i];
        }
    }
    const float* w1  = (const float*)d_in[13];
    const float* b1  = (const float*)d_in[14];
    const float* w2  = (const float*)d_in[15];
    const float* b2  = (const float*)d_in[16];
    const float* fw  = (const float*)d_in[17];
    const float* nsc = (const float*)d_in[18];
    const float* rw  = (const float*)d_in[19];
    float* out = (float*)d_out;

    const int SM_CONV  = 75520;
    const int SM_ATTN  = 76288;
    const int SM_MMA   = 61440;
    cudaFuncSetAttribute(k_conv,      cudaFuncAttributeMaxDynamicSharedMemorySize, SM_CONV);
    cudaFuncSetAttribute(k_attn,      cudaFuncAttributeMaxDynamicSharedMemorySize, SM_ATTN);
    cudaFuncSetAttribute(k_final_mma, cudaFuncAttributeMaxDynamicSharedMemorySize, SM_MMA);

    k_prep<<<OFF_WEND / 256, 256>>>(pw[0], pw[1], pw[2], pw[3], w1);
    k_prepW<<<(512 * 768) / 256, 256>>>(fw, rw);
    k_xsplit<<<(int)(((size_t)Bdim * Ldim * Cdim) / (4 * 256)), 256>>>(x);
    k_conv<<<dim3(Ldim / 128, Bdim, 4), 256, SM_CONV>>>(x, dw[0], dw[1], dw[2], dw[3],
                                                        cnp[0], cnp[1], cnp[2], cnp[3]);
    k_attn<<<dim3(Ldim / 128, Bdim), 256, SM_ATTN>>>(b1, w2, b2);
    k_wfeats<<<dim3(Ldim / 32, Ddim / 32, Bdim), 256>>>();
    k_final_mma<<<dim3(Ldim / 128, Ddim / 64, Bdim), 256, SM_MMA>>>(out);
    k_norm<<<(Bdim * Ldim) / 8, 256>>>(out, nsc);
}

// round 10
// speedup vs baseline: 2.4341x; 1.3082x over previous
#include <cuda_runtime.h>
#include <cuda_bf16.h>
#include <math.h>
#include <stdint.h>

#define Bdim 16
#define Ldim 4096
#define Cdim 256
#define Ddim 512
#define EPSF 1e-8f

typedef unsigned long long ull;

// ------------------- scratch (device globals; no allocs allowed) -------------------
__device__ float g_attn[(size_t)Bdim * 4 * Ldim];           // [b][i][l]
__device__ __nv_bfloat16 gF_hi[(size_t)Bdim * Ldim * 512];  // feats (post-gelu) [b][l][512]
__device__ __nv_bfloat16 gF_lo[(size_t)Bdim * Ldim * 512];
__device__ __nv_bfloat16 gA_hi[(size_t)Bdim * Ldim * 768];  // [b][l][768]: feats*attn | x
__device__ __nv_bfloat16 gA_lo[(size_t)Bdim * Ldim * 768];
__device__ __nv_bfloat16 gB_hi[512 * 768];                  // [o][768]: fw | rw
__device__ __nv_bfloat16 gB_lo[512 * 768];
__device__ __nv_bfloat16 pwB_hi[4 * 128 * 256];             // [sc][o][c]
__device__ __nv_bfloat16 pwB_lo[4 * 128 * 256];
__device__ __nv_bfloat16 w1B_hi[128 * 512];                 // [dh][d]
__device__ __nv_bfloat16 w1B_lo[128 * 512];

// ------------------- helpers -------------------
__device__ __forceinline__ void cpa16(void* dst, const void* src) {
    unsigned s = (unsigned)__cvta_generic_to_shared(dst);
    asm volatile("cp.async.cg.shared.global [%0], [%1], 16;" :: "r"(s), "l"(src));
}
#define CP_COMMIT() asm volatile("cp.async.commit_group;")
#define CP_WAIT0()  asm volatile("cp.async.wait_group 0;" ::: "memory")

__device__ __forceinline__ uint32_t smem_u32(const void* p) {
    uint32_t a;
    asm("{ .reg .u64 t; cvta.to.shared.u64 t, %1; cvt.u32.u64 %0, t; }" : "=r"(a) : "l"(p));
    return a;
}
__device__ __forceinline__ void ldm_x4(uint32_t r[4], uint32_t addr) {
    asm volatile("ldmatrix.sync.aligned.m8n8.x4.shared.b16 {%0,%1,%2,%3}, [%4];"
                 : "=r"(r[0]), "=r"(r[1]), "=r"(r[2]), "=r"(r[3]) : "r"(addr));
}
__device__ __forceinline__ void mma_bf16(float c[4], const uint32_t a[4],
                                         uint32_t b0, uint32_t b1) {
    asm volatile("mma.sync.aligned.m16n8k16.row.col.f32.bf16.bf16.f32 "
                 "{%0,%1,%2,%3}, {%4,%5,%6,%7}, {%8,%9}, {%0,%1,%2,%3};"
                 : "+f"(c[0]), "+f"(c[1]), "+f"(c[2]), "+f"(c[3])
                 : "r"(a[0]), "r"(a[1]), "r"(a[2]), "r"(a[3]), "r"(b0), "r"(b1));
}
__device__ __forceinline__ void split_bf16(float v, __nv_bfloat16& hi, __nv_bfloat16& lo) {
    hi = __float2bfloat16(v);
    lo = __float2bfloat16(v - __bfloat162float(hi));
}
__device__ __forceinline__ uint32_t pack_bf2(__nv_bfloat16 a, __nv_bfloat16 b) {
    uint16_t ua = *(uint16_t*)&a, ub = *(uint16_t*)&b;
    return (uint32_t)ua | ((uint32_t)ub << 16);
}

// ------------------- K0: split all tensor-path weights to bf16 hi/lo -------------------
__global__ void k_prepW(const float* __restrict__ pw1, const float* __restrict__ pw3,
                        const float* __restrict__ pw5, const float* __restrict__ pw7,
                        const float* __restrict__ w1,
                        const float* __restrict__ fw, const float* __restrict__ rw) {
    int idx = blockIdx.x * blockDim.x + threadIdx.x;
    if (idx >= 589824) return;
    float v;
    __nv_bfloat16 hi, lo;
    if (idx < 131072) {                       // pwB[sc][o][c]
        int s = idx >> 15, r = idx & 32767;
        int o = r >> 8, c = r & 255;
        const float* pw = (s == 0) ? pw1 : (s == 1) ? pw3 : (s == 2) ? pw5 : pw7;
        v = pw[o * 256 + c];
        split_bf16(v, hi, lo);
        pwB_hi[idx] = hi; pwB_lo[idx] = lo;
    } else if (idx < 196608) {                // w1B[dh][d]
        int r = idx - 131072;
        v = w1[r];
        split_bf16(v, hi, lo);
        w1B_hi[r] = hi; w1B_lo[r] = lo;
    } else {                                  // gB[o][768] = fw | rw
        int r = idx - 196608;
        int o = r / 768, d = r % 768;
        v = (d < 512) ? fw[o * 512 + d] : rw[o * 256 + (d - 512)];
        split_bf16(v, hi, lo);
        gB_hi[r] = hi; gB_lo[r] = lo;
    }
}

// ------------------- K0b: x split into gA cols [512,768) -------------------
__global__ __launch_bounds__(256) void k_xsplit(const float* __restrict__ x) {
    size_t i = ((size_t)blockIdx.x * 256 + threadIdx.x) * 4;
    int c = (int)(i & 255);
    size_t l = (i >> 8) & 4095;
    size_t b = i >> 20;
    float4 v = *(const float4*)(x + i);
    size_t base = (b * 4096 + l) * 768 + 512 + c;
    float vv[4] = {v.x, v.y, v.z, v.w};
    #pragma unroll
    for (int t = 0; t < 4; t++) {
        __nv_bfloat16 hi, lo;
        split_bf16(vv[t], hi, lo);
        gA_hi[base + t] = hi;
        gA_lo[base + t] = lo;
    }
}

// ------------------- K1: conv (scalar) + pointwise (mma bf16x3) + RMSNorm + GELU -------------------
// smem bytes: XS 0 (17152) | AH 17152 (10240) | AL 27392 (10240) | PW0 37632 (20480) | PW1 58112 (20480)
// total 78592; red[128][2] overlays XS in epilogue.
#define KC_XS  0
#define KC_AH  17152
#define KC_AL  27392
#define KC_PW0 37632
#define KC_PW1 58112
#define KC_SM  78592
__global__ __launch_bounds__(256, 2) void k_conv(
    const float* __restrict__ x,
    const float* __restrict__ dw1, const float* __restrict__ dw3,
    const float* __restrict__ dw5, const float* __restrict__ dw7,
    const float* __restrict__ cn1, const float* __restrict__ cn3,
    const float* __restrict__ cn5, const float* __restrict__ cn7) {
    extern __shared__ char smc[];
    float* xs = (float*)(smc + KC_XS);

    int tid = threadIdx.x, lane = tid & 31, warp = tid >> 5;
    int wm = warp >> 1, wn = warp & 1;
    int lt = blockIdx.x, b = blockIdx.y, sc = blockIdx.z;
    int l0 = lt * 128;
    int k = 2 * sc + 1, r = sc;
    bool edge = (lt == 0) || (lt == Ldim / 128 - 1);
    const float* dw = (sc == 0) ? dw1 : (sc == 1) ? dw3 : (sc == 2) ? dw5 : dw7;
    const float* cn = (sc == 0) ? cn1 : (sc == 1) ? cn3 : (sc == 2) ? cn5 : cn7;
    const __nv_bfloat16* pwh = pwB_hi + sc * 32768;
    const __nv_bfloat16* pwl = pwB_lo + sc * 32768;
    uint32_t sb = smem_u32(smc);

    int cld = tid & 31, lg = tid >> 5;

    float c[2][8][4];
    #pragma unroll
    for (int t = 0; t < 2; t++)
        #pragma unroll
        for (int n = 0; n < 8; n++)
            #pragma unroll
            for (int q = 0; q < 4; q++) c[t][n][q] = 0.f;

    auto stage_x = [&](int c0) {
        if (!edge) {
            for (int u = tid; u < 1072; u += 256) {
                int i = u >> 3, seg = u & 7;
                cpa16(smc + KC_XS + i * 128 + seg * 16,
                      x + ((size_t)b * Ldim + l0 - 3 + i) * Cdim + c0 + seg * 4);
            }
        } else {
            for (int u = tid; u < 4288; u += 256) {
                int i = u >> 5, cc = u & 31;
                int gl = l0 - 3 + i;
                xs[u] = (gl >= 0 && gl < Ldim)
                      ? x[((size_t)b * Ldim + gl) * Cdim + c0 + cc] : 0.f;
            }
        }
    };
    auto stage_pw = [&](int c0, int buf) {
        char* base = smc + (buf ? KC_PW1 : KC_PW0);
        for (int u = tid; u < 512; u += 256) {
            int o = u >> 2, seg = u & 3;
            cpa16(base + o * 80 + seg * 16, pwh + (size_t)o * 256 + c0 + seg * 8);
            cpa16(base + 10240 + o * 80 + seg * 16, pwl + (size_t)o * 256 + c0 + seg * 8);
        }
    };

    stage_x(0);
    stage_pw(0, 0);
    CP_COMMIT();

    for (int ci = 0; ci < 8; ci++) {
        int c0 = ci * 32;
        CP_WAIT0();
        __syncthreads();
        // depthwise conv -> A (bf16 hi/lo), layout [l][c] row stride 80B
        float rd[7];
        #pragma unroll
        for (int t = 0; t < 7; t++) rd[t] = (t < k) ? dw[(c0 + cld) * k + t] : 0.f;
        #pragma unroll
        for (int ii = 0; ii < 16; ii++) {
            int l = lg * 16 + ii;
            float s = 0.f;
            for (int t = 0; t < k; t++) s += rd[t] * xs[(l + 3 - r + t) * 32 + cld];
            __nv_bfloat16 hi, lo;
            split_bf16(s, hi, lo);
            *(__nv_bfloat16*)(smc + KC_AH + l * 80 + cld * 2) = hi;
            *(__nv_bfloat16*)(smc + KC_AL + l * 80 + cld * 2) = lo;
        }
        __syncthreads();
        if (ci < 7) {
            stage_x(c0 + 32);
            stage_pw(c0 + 32, (ci + 1) & 1);
            CP_COMMIT();
        }
        uint32_t pwbuf = sb + ((ci & 1) ? KC_PW1 : KC_PW0);
        int quad = lane >> 3, rr = lane & 7;
        #pragma unroll
        for (int s = 0; s < 2; s++) {
            int k0 = s * 16;
            uint32_t ah[2][4], al[2][4];
            #pragma unroll
            for (int t = 0; t < 2; t++) {
                int row = wm * 32 + t * 16 + (lane & 15);
                uint32_t ad = sb + KC_AH + row * 80 + (k0 + ((lane >> 4) << 3)) * 2;
                ldm_x4(ah[t], ad);
                ldm_x4(al[t], ad + (KC_AL - KC_AH));
            }
            uint32_t bh[4][4], bl[4][4];
            #pragma unroll
            for (int p = 0; p < 4; p++) {
                int n = wn * 64 + p * 16 + ((quad >> 1) << 3) + rr;
                uint32_t bd = pwbuf + n * 80 + (k0 + ((quad & 1) << 3)) * 2;
                ldm_x4(bh[p], bd);
                ldm_x4(bl[p], bd + 10240);
            }
            #pragma unroll
            for (int t = 0; t < 2; t++)
                #pragma unroll
                for (int nt = 0; nt < 8; nt++) {
                    int p = nt >> 1, w2 = (nt & 1) * 2;
                    mma_bf16(c[t][nt], ah[t], bh[p][w2], bh[p][w2 + 1]);
                    mma_bf16(c[t][nt], ah[t], bl[p][w2], bl[p][w2 + 1]);
                    mma_bf16(c[t][nt], al[t], bh[p][w2], bh[p][w2 + 1]);
                }
        }
    }
    __syncthreads();

    // epilogue: RMSNorm over o (128 per-scale channels), cn scale, exact GELU, write gF hi/lo
    float* red = (float*)(smc + KC_XS);   // [128][2]
    int gid = lane >> 2, tig = lane & 3;
    #pragma unroll
    for (int t = 0; t < 2; t++) {
        float p0 = 0.f, p1 = 0.f;
        #pragma unroll
        for (int nt = 0; nt < 8; nt++) {
            p0 += c[t][nt][0] * c[t][nt][0] + c[t][nt][1] * c[t][nt][1];
            p1 += c[t][nt][2] * c[t][nt][2] + c[t][nt][3] * c[t][nt][3];
        }
        p0 += __shfl_xor_sync(0xFFFFFFFFu, p0, 1);
        p0 += __shfl_xor_sync(0xFFFFFFFFu, p0, 2);
        p1 += __shfl_xor_sync(0xFFFFFFFFu, p1, 1);
        p1 += __shfl_xor_sync(0xFFFFFFFFu, p1, 2);
        if (tig == 0) {
            int r0 = wm * 32 + t * 16 + gid;
            red[r0 * 2 + wn] = p0;
            red[(r0 + 8) * 2 + wn] = p1;
        }
    }
    __syncthreads();
    #pragma unroll
    for (int t = 0; t < 2; t++) {
        int r0 = wm * 32 + t * 16 + gid;
        float inv0 = 1.f / (sqrtf((red[r0 * 2] + red[r0 * 2 + 1]) * (1.f / 128.f)) + EPSF);
        float inv1 = 1.f / (sqrtf((red[(r0 + 8) * 2] + red[(r0 + 8) * 2 + 1]) * (1.f / 128.f)) + EPSF);
        #pragma unroll
        for (int nt = 0; nt < 8; nt++) {
            int o = wn * 64 + nt * 8 + tig * 2;
            float cn0 = cn[o], cn1 = cn[o + 1];
            float h00 = c[t][nt][0] * cn0 * inv0, h01 = c[t][nt][1] * cn1 * inv0;
            float h10 = c[t][nt][2] * cn0 * inv1, h11 = c[t][nt][3] * cn1 * inv1;
            h00 *= normcdff(h00); h01 *= normcdff(h01);
            h10 *= normcdff(h10); h11 *= normcdff(h11);
            __nv_bfloat16 hh, hl;
            size_t row0 = ((size_t)b * Ldim + l0 + r0) * 512 + sc * 128 + o;
            size_t row1 = row0 + 8 * 512;
            __nv_bfloat16 a0h, a0l, a1h, a1l;
            split_bf16(h00, a0h, a0l); split_bf16(h01, a1h, a1l);
            *(uint32_t*)(gF_hi + row0) = pack_bf2(a0h, a1h);
            *(uint32_t*)(gF_lo + row0) = pack_bf2(a0l, a1l);
            split_bf16(h10, a0h, a0l); split_bf16(h11, a1h, a1l);
            *(uint32_t*)(gF_hi + row1) = pack_bf2(a0h, a1h);
            *(uint32_t*)(gF_lo + row1) = pack_bf2(a0l, a1l);
            (void)hh; (void)hl;
        }
    }
}

// ------------------- K2: attention MLP (mma bf16x3) + softmax -------------------
// smem: A0 0 (20480) | A1 20480 | B0 40960 (20480) | B1 61440 | W2S 81920 (2048) -> 83968
#define KA_A0  0
#define KA_A1  20480
#define KA_B0  40960
#define KA_B1  61440
#define KA_W2  81920
#define KA_SM  83968
__global__ __launch_bounds__(256, 2) void k_attn(const float* __restrict__ b1p,
                                                 const float* __restrict__ w2p,
                                                 const float* __restrict__ b2p) {
    extern __shared__ char smc[];
    float* w2s = (float*)(smc + KA_W2);
    int tid = threadIdx.x, lane = tid & 31, warp = tid >> 5;
    int wm = warp >> 1, wn = warp & 1;
    int b = blockIdx.y;
    int l0 = blockIdx.x * 128;
    uint32_t sb = smem_u32(smc);
    size_t bL = (size_t)b * Ldim + l0;

    w2s[tid] = w2p[tid];
    w2s[tid + 256] = w2p[tid + 256];

    float c[2][8][4];
    #pragma unroll
    for (int t = 0; t < 2; t++)
        #pragma unroll
        for (int n = 0; n < 8; n++)
            #pragma unroll
            for (int q = 0; q < 4; q++) c[t][n][q] = 0.f;

    auto stage = [&](int c0, int buf) {
        char* ab = smc + (buf ? KA_A1 : KA_A0);
        char* bb = smc + (buf ? KA_B1 : KA_B0);
        for (int u = tid; u < 512; u += 256) {
            int row = u >> 2, seg = u & 3;
            size_t ao = (bL + row) * 512 + c0 + seg * 8;
            cpa16(ab + row * 80 + seg * 16, gF_hi + ao);
            cpa16(ab + 10240 + row * 80 + seg * 16, gF_lo + ao);
            size_t bo = (size_t)row * 512 + c0 + seg * 8;
            cpa16(bb + row * 80 + seg * 16, w1B_hi + bo);
            cpa16(bb + 10240 + row * 80 + seg * 16, w1B_lo + bo);
        }
    };

    stage(0, 0);
    CP_COMMIT();

    for (int ci = 0; ci < 16; ci++) {
        CP_WAIT0();
        __syncthreads();
        if (ci < 15) {
            stage((ci + 1) * 32, (ci + 1) & 1);
            CP_COMMIT();
        }
        uint32_t abuf = sb + ((ci & 1) ? KA_A1 : KA_A0);
        uint32_t bbuf = sb + ((ci & 1) ? KA_B1 : KA_B0);
        int quad = lane >> 3, rr = lane & 7;
        #pragma unroll
        for (int s = 0; s < 2; s++) {
            int k0 = s * 16;
            uint32_t ah[2][4], al[2][4];
            #pragma unroll
            for (int t = 0; t < 2; t++) {
                int row = wm * 32 + t * 16 + (lane & 15);
                uint32_t ad = abuf + row * 80 + (k0 + ((lane >> 4) << 3)) * 2;
                ldm_x4(ah[t], ad);
                ldm_x4(al[t], ad + 10240);
            }
            uint32_t bh[4][4], bl[4][4];
            #pragma unroll
            for (int p = 0; p < 4; p++) {
                int n = wn * 64 + p * 16 + ((quad >> 1) << 3) + rr;
                uint32_t bd = bbuf + n * 80 + (k0 + ((quad & 1) << 3)) * 2;
                ldm_x4(bh[p], bd);
                ldm_x4(bl[p], bd + 10240);
            }
            #pragma unroll
            for (int t = 0; t < 2; t++)
                #pragma unroll
                for (int nt = 0; nt < 8; nt++) {
                    int p = nt >> 1, w2 = (nt & 1) * 2;
                    mma_bf16(c[t][nt], ah[t], bh[p][w2], bh[p][w2 + 1]);
                    mma_bf16(c[t][nt], ah[t], bl[p][w2], bl[p][w2 + 1]);
                    mma_bf16(c[t][nt], al[t], bh[p][w2], bh[p][w2 + 1]);
                }
        }
    }
    __syncthreads();

    // bias + gelu + w2 reduce (4 scales) + softmax
    float* red4 = (float*)smc;   // [4][128][2] = 4096 B, overlays A0
    int gid = lane >> 2, tig = lane & 3;
    float part[4][2][2];         // [i4][t][row01]
    #pragma unroll
    for (int i4 = 0; i4 < 4; i4++)
        #pragma unroll
        for (int t = 0; t < 2; t++) { part[i4][t][0] = 0.f; part[i4][t][1] = 0.f; }
    #pragma unroll
    for (int t = 0; t < 2; t++)
        #pragma unroll
        for (int nt = 0; nt < 8; nt++) {
            int dh = wn * 64 + nt * 8 + tig * 2;
            float b10 = b1p[dh], b11 = b1p[dh + 1];
            float g00 = c[t][nt][0] + b10, g01 = c[t][nt][1] + b11;
            float g10 = c[t][nt][2] + b10, g11 = c[t][nt][3] + b11;
            g00 *= normcdff(g00); g01 *= normcdff(g01);
            g10 *= normcdff(g10); g11 *= normcdff(g11);
            #pragma unroll
            for (int i4 = 0; i4 < 4; i4++) {
                float w0 = w2s[i4 * 128 + dh], w1v = w2s[i4 * 128 + dh + 1];
                part[i4][t][0] += w0 * g00 + w1v * g01;
                part[i4][t][1] += w0 * g10 + w1v * g11;
            }
        }
    #pragma unroll
    for (int i4 = 0; i4 < 4; i4++)
        #pragma unroll
        for (int t = 0; t < 2; t++)
            #pragma unroll
            for (int rr2 = 0; rr2 < 2; rr2++) {
                float p = part[i4][t][rr2];
                p += __shfl_xor_sync(0xFFFFFFFFu, p, 1);
                p += __shfl_xor_sync(0xFFFFFFFFu, p, 2);
                part[i4][t][rr2] = p;
            }
    if (tig == 0) {
        #pragma unroll
        for (int i4 = 0; i4 < 4; i4++)
            #pragma unroll
            for (int t = 0; t < 2; t++) {
                int r0 = wm * 32 + t * 16 + gid;
                red4[(i4 * 128 + r0) * 2 + wn] = part[i4][t][0];
                red4[(i4 * 128 + r0 + 8) * 2 + wn] = part[i4][t][1];
            }
    }
    __syncthreads();
    if (wn == 0 && tig == 0) {
        #pragma unroll
        for (int t = 0; t < 2; t++)
            #pragma unroll
            for (int rr2 = 0; rr2 < 2; rr2++) {
                int l = wm * 32 + t * 16 + gid + rr2 * 8;
                float a2[4];
                #pragma unroll
                for (int i4 = 0; i4 < 4; i4++)
                    a2[i4] = red4[(i4 * 128 + l) * 2] + red4[(i4 * 128 + l) * 2 + 1] + b2p[i4];
                float m = fmaxf(fmaxf(a2[0], a2[1]), fmaxf(a2[2], a2[3]));
                float s = 0.f;
                #pragma unroll
                for (int i4 = 0; i4 < 4; i4++) { a2[i4] = expf(a2[i4] - m); s += a2[i4]; }
                float invs = 1.f / s;
                #pragma unroll
                for (int i4 = 0; i4 < 4; i4++)
                    g_attn[((size_t)b * 4 + i4) * Ldim + l0 + l] = a2[i4] * invs;
            }
    }
}

// ------------------- K2b: gA[:, :512] = gF * attn (elementwise, layouts agree) -------------------
__global__ __launch_bounds__(256) void k_wfeats() {
    size_t u = ((size_t)blockIdx.x * 256 + threadIdx.x) * 8;
    int d = (int)(u & 511);
    size_t l = (u >> 9) & 4095;
    size_t b = u >> 21;
    float a = g_attn[((b << 2) + (d >> 7)) * Ldim + l];
    size_t fo = (b * 4096 + l) * 512 + d;
    uint4 vh = *(const uint4*)(gF_hi + fo);
    uint4 vl = *(const uint4*)(gF_lo + fo);
    const __nv_bfloat16* ph = (const __nv_bfloat16*)&vh;
    const __nv_bfloat16* pl = (const __nv_bfloat16*)&vl;
    uint4 oh, ol;
    __nv_bfloat16* qh = (__nv_bfloat16*)&oh;
    __nv_bfloat16* ql = (__nv_bfloat16*)&ol;
    #pragma unroll
    for (int e = 0; e < 8; e++) {
        float f = (__bfloat162float(ph[e]) + __bfloat162float(pl[e])) * a;
        split_bf16(f, qh[e], ql[e]);
    }
    size_t ao = (b * 4096 + l) * 768 + d;
    *(uint4*)(gA_hi + ao) = oh;
    *(uint4*)(gA_lo + ao) = ol;
}

// ------------------- K3: mma.sync bf16x3 final GEMM (unchanged from R9) -------------------
__global__ __launch_bounds__(256, 2) void k_final_mma(float* __restrict__ out) {
    extern __shared__ char smc[];
    int tid = threadIdx.x, lane = tid & 31, warp = tid >> 5;
    int wm = warp >> 1, wn = warp & 1;
    int lt = blockIdx.x, ot = blockIdx.y, b = blockIdx.z;
    int l0 = lt * 128, o0 = ot * 64;

    const __nv_bfloat16* Ahg = gA_hi + ((size_t)b * Ldim + l0) * 768;
    const __nv_bfloat16* Alg = gA_lo + ((size_t)b * Ldim + l0) * 768;
    const __nv_bfloat16* Bhg = gB_hi + (size_t)o0 * 768;
    const __nv_bfloat16* Blg = gB_lo + (size_t)o0 * 768;

    float c[2][4][4];
    #pragma unroll
    for (int t = 0; t < 2; t++)
        #pragma unroll
        for (int n = 0; n < 4; n++)
            #pragma unroll
            for (int q = 0; q < 4; q++) c[t][n][q] = 0.f;

    auto stage = [&](int kc, int bs) {
        char* base = smc + bs * 30720;
        int k0 = kc * 32;
        #pragma unroll
        for (int q = 0; q < 2; q++) {
            int idx = q * 256 + tid, row = idx >> 2, seg = idx & 3;
            size_t go = (size_t)row * 768 + k0 + seg * 8;
            cpa16(base + row * 80 + seg * 16, Ahg + go);
            cpa16(base + 10240 + row * 80 + seg * 16, Alg + go);
        }
        {
            int row = tid >> 2, seg = tid & 3;
            size_t go = (size_t)row * 768 + k0 + seg * 8;
            cpa16(base + 20480 + row * 80 + seg * 16, Bhg + go);
            cpa16(base + 25600 + row * 80 + seg * 16, Blg + go);
        }
    };

    uint32_t sb = smem_u32(smc);
    stage(0, 0);
    CP_COMMIT();

    for (int ci = 0; ci < 24; ci++) {
        CP_WAIT0();
        __syncthreads();
        if (ci < 23) {
            stage(ci + 1, (ci + 1) & 1);
            CP_COMMIT();
        }
        uint32_t buf = sb + (ci & 1) * 30720;
        #pragma unroll
        for (int s = 0; s < 2; s++) {
            int k0 = s * 16;
            uint32_t ah[2][4], al[2][4];
            #pragma unroll
            for (int t = 0; t < 2; t++) {
                int row = wm * 32 + t * 16 + (lane & 15);
                uint32_t ad = buf + row * 80 + (k0 + ((lane >> 4) << 3)) * 2;
                ldm_x4(ah[t], ad);
                ldm_x4(al[t], ad + 10240);
            }
            uint32_t bh[2][4], bl[2][4];
            int quad = lane >> 3, rr = lane & 7;
            #pragma unroll
            for (int p = 0; p < 2; p++) {
                int n = wn * 32 + p * 16 + ((quad >> 1) << 3) + rr;
                uint32_t bd = buf + 20480 + n * 80 + (k0 + ((quad & 1) << 3)) * 2;
                ldm_x4(bh[p], bd);
                ldm_x4(bl[p], bd + 5120);
            }
            #pragma unroll
            for (int t = 0; t < 2; t++)
                #pragma unroll
                for (int nt = 0; nt < 4; nt++) {
                    int p = nt >> 1, w2 = (nt & 1) * 2;
                    mma_bf16(c[t][nt], ah[t], bh[p][w2], bh[p][w2 + 1]);
                    mma_bf16(c[t][nt], ah[t], bl[p][w2], bl[p][w2 + 1]);
                    mma_bf16(c[t][nt], al[t], bh[p][w2], bh[p][w2 + 1]);
                }
        }
    }

    int gid = lane >> 2, tig = lane & 3;
    #pragma unroll
    for (int t = 0; t < 2; t++) {
        size_t r0 = (size_t)b * Ldim + l0 + wm * 32 + t * 16 + gid;
        #pragma unroll
        for (int nt = 0; nt < 4; nt++) {
            int o = o0 + wn * 32 + nt * 8 + tig * 2;
            *(float2*)(out + r0 * Ddim + o)       = make_float2(c[t][nt][0], c[t][nt][1]);
            *(float2*)(out + (r0 + 8) * Ddim + o) = make_float2(c[t][nt][2], c[t][nt][3]);
        }
    }
}

// ------------------- K4: final row RMSNorm (in place) -------------------
__global__ __launch_bounds__(256) void k_norm(float* __restrict__ out,
                                              const float* __restrict__ nsc) {
    __shared__ float ns[512];
    int tid = threadIdx.x;
    ns[tid] = nsc[tid];
    ns[tid + 256] = nsc[tid + 256];
    __syncthreads();

    int warp = tid >> 5, lane = tid & 31;
    size_t row = (size_t)blockIdx.x * 8 + warp;
    float* p = out + row * Ddim;

    float4 v[4];
    float ssq = 0.f;
    #pragma unroll
    for (int q = 0; q < 4; q++) {
        v[q] = *(const float4*)(p + (q * 32 + lane) * 4);
        ssq += v[q].x * v[q].x + v[q].y * v[q].y + v[q].z * v[q].z + v[q].w * v[q].w;
    }
    #pragma unroll
    for (int off = 16; off > 0; off >>= 1)
        ssq += __shfl_xor_sync(0xFFFFFFFFu, ssq, off);
    float rms = sqrtf(ssq * (1.f / 512.f));
    float inv = 1.f / (rms + EPSF);
    #pragma unroll
    for (int q = 0; q < 4; q++) {
        int base = (q * 32 + lane) * 4;
        float4 w;
        w.x = v[q].x * ns[base + 0] * inv;
        w.y = v[q].y * ns[base + 1] * inv;
        w.z = v[q].z * ns[base + 2] * inv;
        w.w = v[q].w * ns[base + 3] * inv;
        *(float4*)(p + base) = w;
    }
}

// ------------------- launch -------------------
extern "C" void kernel_launch(void* const* d_in, const int* in_sizes, int n_in,
                              void* d_out, int out_size) {
    const float* x = (const float*)d_in[0];
    const float *dw[4], *pw[4], *cnp[4];
    if (in_sizes[2] == 768) {
        for (int i = 0; i < 4; i++) {
            dw[i]  = (const float*)d_in[1 + i];
            pw[i]  = (const float*)d_in[5 + i];
            cnp[i] = (const float*)d_in[9 + i];
        }
    } else {
        for (int i = 0; i < 4; i++) {
            dw[i]  = (const float*)d_in[1 + 3 * i];
            pw[i]  = (const float*)d_in[2 + 3 * i];
            cnp[i] = (const float*)d_in[3 + 3 * i];
        }
    }
    const float* w1  = (const float*)d_in[13];
    const float* b1  = (const float*)d_in[14];
    const float* w2  = (const float*)d_in[15];
    const float* b2  = (const float*)d_in[16];
    const float* fw  = (const float*)d_in[17];
    const float* nsc = (const float*)d_in[18];
    const float* rw  = (const float*)d_in[19];
    float* out = (float*)d_out;

    const int SM_MMA = 61440;
    cudaFuncSetAttribute(k_conv,      cudaFuncAttributeMaxDynamicSharedMemorySize, KC_SM);
    cudaFuncSetAttribute(k_attn,      cudaFuncAttributeMaxDynamicSharedMemorySize, KA_SM);
    cudaFuncSetAttribute(k_final_mma, cudaFuncAttributeMaxDynamicSharedMemorySize, SM_MMA);

    k_prepW<<<589824 / 256, 256>>>(pw[0], pw[1], pw[2], pw[3], w1, fw, rw);
    k_xsplit<<<(int)(((size_t)Bdim * Ldim * Cdim) / (4 * 256)), 256>>>(x);
    k_conv<<<dim3(Ldim / 128, Bdim, 4), 256, KC_SM>>>(x, dw[0], dw[1], dw[2], dw[3],
                                                      cnp[0], cnp[1], cnp[2], cnp[3]);
    k_attn<<<dim3(Ldim / 128, Bdim), 256, KA_SM>>>(b1, w2, b2);
    k_wfeats<<<(int)(((size_t)Bdim * Ldim * 512) / (8 * 256)), 256>>>();
    k_final_mma<<<dim3(Ldim / 128, Ddim / 64, Bdim), 256, SM_MMA>>>(out);
    k_norm<<<(Bdim * Ldim) / 8, 256>>>(out, nsc);
}

// round 11
// speedup vs baseline: 2.4936x; 1.0245x over previous
#include <cuda_runtime.h>
#include <cuda_bf16.h>
#include <math.h>
#include <stdint.h>

#define Bdim 16
#define Ldim 4096
#define Cdim 256
#define Ddim 512
#define EPSF 1e-8f

typedef unsigned long long ull;

// ------------------- scratch (device globals; no allocs allowed) -------------------
__device__ float g_attn[(size_t)Bdim * 4 * Ldim];           // [b][i][l]
__device__ __nv_bfloat16 gF_hi[(size_t)Bdim * Ldim * 512];  // feats (post-gelu) [b][l][512]
__device__ __nv_bfloat16 gF_lo[(size_t)Bdim * Ldim * 512];
__device__ __nv_bfloat16 gA_hi[(size_t)Bdim * Ldim * 768];  // [b][l][768]: feats*attn | x
__device__ __nv_bfloat16 gA_lo[(size_t)Bdim * Ldim * 768];
__device__ __nv_bfloat16 gB_hi[512 * 768];                  // [o][768]: fw | rw
__device__ __nv_bfloat16 gB_lo[512 * 768];
__device__ __nv_bfloat16 pwB_hi[4 * 128 * 256];             // [sc][o][c]
__device__ __nv_bfloat16 pwB_lo[4 * 128 * 256];
__device__ __nv_bfloat16 w1B_hi[128 * 512];                 // [dh][d]
__device__ __nv_bfloat16 w1B_lo[128 * 512];

// ------------------- helpers -------------------
__device__ __forceinline__ void cpa16(void* dst, const void* src) {
    unsigned s = (unsigned)__cvta_generic_to_shared(dst);
    asm volatile("cp.async.cg.shared.global [%0], [%1], 16;" :: "r"(s), "l"(src));
}
#define CP_COMMIT() asm volatile("cp.async.commit_group;")
#define CP_WAIT0()  asm volatile("cp.async.wait_group 0;" ::: "memory")

__device__ __forceinline__ uint32_t smem_u32(const void* p) {
    uint32_t a;
    asm("{ .reg .u64 t; cvta.to.shared.u64 t, %1; cvt.u32.u64 %0, t; }" : "=r"(a) : "l"(p));
    return a;
}
__device__ __forceinline__ void ldm_x4(uint32_t r[4], uint32_t addr) {
    asm volatile("ldmatrix.sync.aligned.m8n8.x4.shared.b16 {%0,%1,%2,%3}, [%4];"
                 : "=r"(r[0]), "=r"(r[1]), "=r"(r[2]), "=r"(r[3]) : "r"(addr));
}
__device__ __forceinline__ void mma_bf16(float c[4], const uint32_t a[4],
                                         uint32_t b0, uint32_t b1) {
    asm volatile("mma.sync.aligned.m16n8k16.row.col.f32.bf16.bf16.f32 "
                 "{%0,%1,%2,%3}, {%4,%5,%6,%7}, {%8,%9}, {%0,%1,%2,%3};"
                 : "+f"(c[0]), "+f"(c[1]), "+f"(c[2]), "+f"(c[3])
                 : "r"(a[0]), "r"(a[1]), "r"(a[2]), "r"(a[3]), "r"(b0), "r"(b1));
}
__device__ __forceinline__ void split_bf16(float v, __nv_bfloat16& hi, __nv_bfloat16& lo) {
    hi = __float2bfloat16(v);
    lo = __float2bfloat16(v - __bfloat162float(hi));
}
__device__ __forceinline__ uint32_t pack_bf2(__nv_bfloat16 a, __nv_bfloat16 b) {
    uint16_t ua = *(uint16_t*)&a, ub = *(uint16_t*)&b;
    return (uint32_t)ua | ((uint32_t)ub << 16);
}

// ------------------- K0: split all tensor-path weights to bf16 hi/lo -------------------
__global__ void k_prepW(const float* __restrict__ pw1, const float* __restrict__ pw3,
                        const float* __restrict__ pw5, const float* __restrict__ pw7,
                        const float* __restrict__ w1,
                        const float* __restrict__ fw, const float* __restrict__ rw) {
    int idx = blockIdx.x * blockDim.x + threadIdx.x;
    if (idx >= 589824) return;
    float v;
    __nv_bfloat16 hi, lo;
    if (idx < 131072) {                       // pwB[sc][o][c]
        int s = idx >> 15, r = idx & 32767;
        int o = r >> 8, c = r & 255;
        const float* pw = (s == 0) ? pw1 : (s == 1) ? pw3 : (s == 2) ? pw5 : pw7;
        v = pw[o * 256 + c];
        split_bf16(v, hi, lo);
        pwB_hi[idx] = hi; pwB_lo[idx] = lo;
    } else if (idx < 196608) {                // w1B[dh][d]
        int r = idx - 131072;
        v = w1[r];
        split_bf16(v, hi, lo);
        w1B_hi[r] = hi; w1B_lo[r] = lo;
    } else {                                  // gB[o][768] = fw | rw
        int r = idx - 196608;
        int o = r / 768, d = r % 768;
        v = (d < 512) ? fw[o * 512 + d] : rw[o * 256 + (d - 512)];
        split_bf16(v, hi, lo);
        gB_hi[r] = hi; gB_lo[r] = lo;
    }
}

// ------------------- K0b: x split into gA cols [512,768) -------------------
__global__ __launch_bounds__(256) void k_xsplit(const float* __restrict__ x) {
    size_t i = ((size_t)blockIdx.x * 256 + threadIdx.x) * 4;
    int c = (int)(i & 255);
    size_t l = (i >> 8) & 4095;
    size_t b = i >> 20;
    float4 v = *(const float4*)(x + i);
    size_t base = (b * 4096 + l) * 768 + 512 + c;
    float vv[4] = {v.x, v.y, v.z, v.w};
    #pragma unroll
    for (int t = 0; t < 4; t++) {
        __nv_bfloat16 hi, lo;
        split_bf16(vv[t], hi, lo);
        gA_hi[base + t] = hi;
        gA_lo[base + t] = lo;
    }
}

// ------------------- K1: conv (scalar) + pointwise (mma bf16x3) + RMSNorm + GELU -------------------
#define KC_XS  0
#define KC_AH  17152
#define KC_AL  27392
#define KC_PW0 37632
#define KC_PW1 58112
#define KC_SM  78592
__global__ __launch_bounds__(256, 2) void k_conv(
    const float* __restrict__ x,
    const float* __restrict__ dw1, const float* __restrict__ dw3,
    const float* __restrict__ dw5, const float* __restrict__ dw7,
    const float* __restrict__ cn1, const float* __restrict__ cn3,
    const float* __restrict__ cn5, const float* __restrict__ cn7) {
    extern __shared__ char smc[];
    float* xs = (float*)(smc + KC_XS);

    int tid = threadIdx.x, lane = tid & 31, warp = tid >> 5;
    int wm = warp >> 1, wn = warp & 1;
    int lt = blockIdx.x, b = blockIdx.y, sc = blockIdx.z;
    int l0 = lt * 128;
    int k = 2 * sc + 1, r = sc;
    bool edge = (lt == 0) || (lt == Ldim / 128 - 1);
    const float* dw = (sc == 0) ? dw1 : (sc == 1) ? dw3 : (sc == 2) ? dw5 : dw7;
    const float* cn = (sc == 0) ? cn1 : (sc == 1) ? cn3 : (sc == 2) ? cn5 : cn7;
    const __nv_bfloat16* pwh = pwB_hi + sc * 32768;
    const __nv_bfloat16* pwl = pwB_lo + sc * 32768;
    uint32_t sb = smem_u32(smc);

    int cld = tid & 31, lg = tid >> 5;

    float c[2][8][4];
    #pragma unroll
    for (int t = 0; t < 2; t++)
        #pragma unroll
        for (int n = 0; n < 8; n++)
            #pragma unroll
            for (int q = 0; q < 4; q++) c[t][n][q] = 0.f;

    auto stage_x = [&](int c0) {
        if (!edge) {
            for (int u = tid; u < 1072; u += 256) {
                int i = u >> 3, seg = u & 7;
                cpa16(smc + KC_XS + i * 128 + seg * 16,
                      x + ((size_t)b * Ldim + l0 - 3 + i) * Cdim + c0 + seg * 4);
            }
        } else {
            for (int u = tid; u < 4288; u += 256) {
                int i = u >> 5, cc = u & 31;
                int gl = l0 - 3 + i;
                xs[u] = (gl >= 0 && gl < Ldim)
                      ? x[((size_t)b * Ldim + gl) * Cdim + c0 + cc] : 0.f;
            }
        }
    };
    auto stage_pw = [&](int c0, int buf) {
        char* base = smc + (buf ? KC_PW1 : KC_PW0);
        for (int u = tid; u < 512; u += 256) {
            int o = u >> 2, seg = u & 3;
            cpa16(base + o * 80 + seg * 16, pwh + (size_t)o * 256 + c0 + seg * 8);
            cpa16(base + 10240 + o * 80 + seg * 16, pwl + (size_t)o * 256 + c0 + seg * 8);
        }
    };

    stage_x(0);
    stage_pw(0, 0);
    CP_COMMIT();

    for (int ci = 0; ci < 8; ci++) {
        int c0 = ci * 32;
        CP_WAIT0();
        __syncthreads();
        float rd[7];
        #pragma unroll
        for (int t = 0; t < 7; t++) rd[t] = (t < k) ? dw[(c0 + cld) * k + t] : 0.f;
        #pragma unroll
        for (int ii = 0; ii < 16; ii++) {
            int l = lg * 16 + ii;
            float s = 0.f;
            for (int t = 0; t < k; t++) s += rd[t] * xs[(l + 3 - r + t) * 32 + cld];
            __nv_bfloat16 hi, lo;
            split_bf16(s, hi, lo);
            *(__nv_bfloat16*)(smc + KC_AH + l * 80 + cld * 2) = hi;
            *(__nv_bfloat16*)(smc + KC_AL + l * 80 + cld * 2) = lo;
        }
        __syncthreads();
        if (ci < 7) {
            stage_x(c0 + 32);
            stage_pw(c0 + 32, (ci + 1) & 1);
            CP_COMMIT();
        }
        uint32_t pwbuf = sb + ((ci & 1) ? KC_PW1 : KC_PW0);
        int quad = lane >> 3, rr = lane & 7;
        #pragma unroll
        for (int s = 0; s < 2; s++) {
            int k0 = s * 16;
            uint32_t ah[2][4], al[2][4];
            #pragma unroll
            for (int t = 0; t < 2; t++) {
                int row = wm * 32 + t * 16 + (lane & 15);
                uint32_t ad = sb + KC_AH + row * 80 + (k0 + ((lane >> 4) << 3)) * 2;
                ldm_x4(ah[t], ad);
                ldm_x4(al[t], ad + (KC_AL - KC_AH));
            }
            uint32_t bh[4][4], bl[4][4];
            #pragma unroll
            for (int p = 0; p < 4; p++) {
                int n = wn * 64 + p * 16 + ((quad >> 1) << 3) + rr;
                uint32_t bd = pwbuf + n * 80 + (k0 + ((quad & 1) << 3)) * 2;
                ldm_x4(bh[p], bd);
                ldm_x4(bl[p], bd + 10240);
            }
            #pragma unroll
            for (int t = 0; t < 2; t++)
                #pragma unroll
                for (int nt = 0; nt < 8; nt++) {
                    int p = nt >> 1, w2 = (nt & 1) * 2;
                    mma_bf16(c[t][nt], ah[t], bh[p][w2], bh[p][w2 + 1]);
                    mma_bf16(c[t][nt], ah[t], bl[p][w2], bl[p][w2 + 1]);
                    mma_bf16(c[t][nt], al[t], bh[p][w2], bh[p][w2 + 1]);
                }
        }
    }
    __syncthreads();

    float* red = (float*)(smc + KC_XS);   // [128][2]
    int gid = lane >> 2, tig = lane & 3;
    #pragma unroll
    for (int t = 0; t < 2; t++) {
        float p0 = 0.f, p1 = 0.f;
        #pragma unroll
        for (int nt = 0; nt < 8; nt++) {
            p0 += c[t][nt][0] * c[t][nt][0] + c[t][nt][1] * c[t][nt][1];
            p1 += c[t][nt][2] * c[t][nt][2] + c[t][nt][3] * c[t][nt][3];
        }
        p0 += __shfl_xor_sync(0xFFFFFFFFu, p0, 1);
        p0 += __shfl_xor_sync(0xFFFFFFFFu, p0, 2);
        p1 += __shfl_xor_sync(0xFFFFFFFFu, p1, 1);
        p1 += __shfl_xor_sync(0xFFFFFFFFu, p1, 2);
        if (tig == 0) {
            int r0 = wm * 32 + t * 16 + gid;
            red[r0 * 2 + wn] = p0;
            red[(r0 + 8) * 2 + wn] = p1;
        }
    }
    __syncthreads();
    #pragma unroll
    for (int t = 0; t < 2; t++) {
        int r0 = wm * 32 + t * 16 + gid;
        float inv0 = 1.f / (sqrtf((red[r0 * 2] + red[r0 * 2 + 1]) * (1.f / 128.f)) + EPSF);
        float inv1 = 1.f / (sqrtf((red[(r0 + 8) * 2] + red[(r0 + 8) * 2 + 1]) * (1.f / 128.f)) + EPSF);
        #pragma unroll
        for (int nt = 0; nt < 8; nt++) {
            int o = wn * 64 + nt * 8 + tig * 2;
            float cn0 = cn[o], cn1 = cn[o + 1];
            float h00 = c[t][nt][0] * cn0 * inv0, h01 = c[t][nt][1] * cn1 * inv0;
            float h10 = c[t][nt][2] * cn0 * inv1, h11 = c[t][nt][3] * cn1 * inv1;
            h00 *= normcdff(h00); h01 *= normcdff(h01);
            h10 *= normcdff(h10); h11 *= normcdff(h11);
            size_t row0 = ((size_t)b * Ldim + l0 + r0) * 512 + sc * 128 + o;
            size_t row1 = row0 + 8 * 512;
            __nv_bfloat16 a0h, a0l, a1h, a1l;
            split_bf16(h00, a0h, a0l); split_bf16(h01, a1h, a1l);
            *(uint32_t*)(gF_hi + row0) = pack_bf2(a0h, a1h);
            *(uint32_t*)(gF_lo + row0) = pack_bf2(a0l, a1l);
            split_bf16(h10, a0h, a0l); split_bf16(h11, a1h, a1l);
            *(uint32_t*)(gF_hi + row1) = pack_bf2(a0h, a1h);
            *(uint32_t*)(gF_lo + row1) = pack_bf2(a0l, a1l);
        }
    }
}

// ------------------- K2: attention MLP (mma bf16x3) + softmax -------------------
#define KA_A0  0
#define KA_A1  20480
#define KA_B0  40960
#define KA_B1  61440
#define KA_W2  81920
#define KA_SM  83968
__global__ __launch_bounds__(256, 2) void k_attn(const float* __restrict__ b1p,
                                                 const float* __restrict__ w2p,
                                                 const float* __restrict__ b2p) {
    extern __shared__ char smc[];
    float* w2s = (float*)(smc + KA_W2);
    int tid = threadIdx.x, lane = tid & 31, warp = tid >> 5;
    int wm = warp >> 1, wn = warp & 1;
    int b = blockIdx.y;
    int l0 = blockIdx.x * 128;
    uint32_t sb = smem_u32(smc);
    size_t bL = (size_t)b * Ldim + l0;

    w2s[tid] = w2p[tid];
    w2s[tid + 256] = w2p[tid + 256];

    float c[2][8][4];
    #pragma unroll
    for (int t = 0; t < 2; t++)
        #pragma unroll
        for (int n = 0; n < 8; n++)
            #pragma unroll
            for (int q = 0; q < 4; q++) c[t][n][q] = 0.f;

    auto stage = [&](int c0, int buf) {
        char* ab = smc + (buf ? KA_A1 : KA_A0);
        char* bb = smc + (buf ? KA_B1 : KA_B0);
        for (int u = tid; u < 512; u += 256) {
            int row = u >> 2, seg = u & 3;
            size_t ao = (bL + row) * 512 + c0 + seg * 8;
            cpa16(ab + row * 80 + seg * 16, gF_hi + ao);
            cpa16(ab + 10240 + row * 80 + seg * 16, gF_lo + ao);
            size_t bo = (size_t)row * 512 + c0 + seg * 8;
            cpa16(bb + row * 80 + seg * 16, w1B_hi + bo);
            cpa16(bb + 10240 + row * 80 + seg * 16, w1B_lo + bo);
        }
    };

    stage(0, 0);
    CP_COMMIT();

    for (int ci = 0; ci < 16; ci++) {
        CP_WAIT0();
        __syncthreads();
        if (ci < 15) {
            stage((ci + 1) * 32, (ci + 1) & 1);
            CP_COMMIT();
        }
        uint32_t abuf = sb + ((ci & 1) ? KA_A1 : KA_A0);
        uint32_t bbuf = sb + ((ci & 1) ? KA_B1 : KA_B0);
        int quad = lane >> 3, rr = lane & 7;
        #pragma unroll
        for (int s = 0; s < 2; s++) {
            int k0 = s * 16;
            uint32_t ah[2][4], al[2][4];
            #pragma unroll
            for (int t = 0; t < 2; t++) {
                int row = wm * 32 + t * 16 + (lane & 15);
                uint32_t ad = abuf + row * 80 + (k0 + ((lane >> 4) << 3)) * 2;
                ldm_x4(ah[t], ad);
                ldm_x4(al[t], ad + 10240);
            }
            uint32_t bh[4][4], bl[4][4];
            #pragma unroll
            for (int p = 0; p < 4; p++) {
                int n = wn * 64 + p * 16 + ((quad >> 1) << 3) + rr;
                uint32_t bd = bbuf + n * 80 + (k0 + ((quad & 1) << 3)) * 2;
                ldm_x4(bh[p], bd);
                ldm_x4(bl[p], bd + 10240);
            }
            #pragma unroll
            for (int t = 0; t < 2; t++)
                #pragma unroll
                for (int nt = 0; nt < 8; nt++) {
                    int p = nt >> 1, w2 = (nt & 1) * 2;
                    mma_bf16(c[t][nt], ah[t], bh[p][w2], bh[p][w2 + 1]);
                    mma_bf16(c[t][nt], ah[t], bl[p][w2], bl[p][w2 + 1]);
                    mma_bf16(c[t][nt], al[t], bh[p][w2], bh[p][w2 + 1]);
                }
        }
    }
    __syncthreads();

    float* red4 = (float*)smc;   // [4][128][2]
    int gid = lane >> 2, tig = lane & 3;
    float part[4][2][2];
    #pragma unroll
    for (int i4 = 0; i4 < 4; i4++)
        #pragma unroll
        for (int t = 0; t < 2; t++) { part[i4][t][0] = 0.f; part[i4][t][1] = 0.f; }
    #pragma unroll
    for (int t = 0; t < 2; t++)
        #pragma unroll
        for (int nt = 0; nt < 8; nt++) {
            int dh = wn * 64 + nt * 8 + tig * 2;
            float b10 = b1p[dh], b11 = b1p[dh + 1];
            float g00 = c[t][nt][0] + b10, g01 = c[t][nt][1] + b11;
            float g10 = c[t][nt][2] + b10, g11 = c[t][nt][3] + b11;
            g00 *= normcdff(g00); g01 *= normcdff(g01);
            g10 *= normcdff(g10); g11 *= normcdff(g11);
            #pragma unroll
            for (int i4 = 0; i4 < 4; i4++) {
                float w0 = w2s[i4 * 128 + dh], w1v = w2s[i4 * 128 + dh + 1];
                part[i4][t][0] += w0 * g00 + w1v * g01;
                part[i4][t][1] += w0 * g10 + w1v * g11;
            }
        }
    #pragma unroll
    for (int i4 = 0; i4 < 4; i4++)
        #pragma unroll
        for (int t = 0; t < 2; t++)
            #pragma unroll
            for (int rr2 = 0; rr2 < 2; rr2++) {
                float p = part[i4][t][rr2];
                p += __shfl_xor_sync(0xFFFFFFFFu, p, 1);
                p += __shfl_xor_sync(0xFFFFFFFFu, p, 2);
                part[i4][t][rr2] = p;
            }
    if (tig == 0) {
        #pragma unroll
        for (int i4 = 0; i4 < 4; i4++)
            #pragma unroll
            for (int t = 0; t < 2; t++) {
                int r0 = wm * 32 + t * 16 + gid;
                red4[(i4 * 128 + r0) * 2 + wn] = part[i4][t][0];
                red4[(i4 * 128 + r0 + 8) * 2 + wn] = part[i4][t][1];
            }
    }
    __syncthreads();
    if (wn == 0 && tig == 0) {
        #pragma unroll
        for (int t = 0; t < 2; t++)
            #pragma unroll
            for (int rr2 = 0; rr2 < 2; rr2++) {
                int l = wm * 32 + t * 16 + gid + rr2 * 8;
                float a2[4];
                #pragma unroll
                for (int i4 = 0; i4 < 4; i4++)
                    a2[i4] = red4[(i4 * 128 + l) * 2] + red4[(i4 * 128 + l) * 2 + 1] + b2p[i4];
                float m = fmaxf(fmaxf(a2[0], a2[1]), fmaxf(a2[2], a2[3]));
                float s = 0.f;
                #pragma unroll
                for (int i4 = 0; i4 < 4; i4++) { a2[i4] = expf(a2[i4] - m); s += a2[i4]; }
                float invs = 1.f / s;
                #pragma unroll
                for (int i4 = 0; i4 < 4; i4++)
                    g_attn[((size_t)b * 4 + i4) * Ldim + l0 + l] = a2[i4] * invs;
            }
    }
}

// ------------------- K2b: gA[:, :512] = gF * attn (elementwise) -------------------
__global__ __launch_bounds__(256) void k_wfeats() {
    size_t u = ((size_t)blockIdx.x * 256 + threadIdx.x) * 8;
    int d = (int)(u & 511);
    size_t l = (u >> 9) & 4095;
    size_t b = u >> 21;
    float a = g_attn[((b << 2) + (d >> 7)) * Ldim + l];
    size_t fo = (b * 4096 + l) * 512 + d;
    uint4 vh = *(const uint4*)(gF_hi + fo);
    uint4 vl = *(const uint4*)(gF_lo + fo);
    const __nv_bfloat16* ph = (const __nv_bfloat16*)&vh;
    const __nv_bfloat16* pl = (const __nv_bfloat16*)&vl;
    uint4 oh, ol;
    __nv_bfloat16* qh = (__nv_bfloat16*)&oh;
    __nv_bfloat16* ql = (__nv_bfloat16*)&ol;
    #pragma unroll
    for (int e = 0; e < 8; e++) {
        float f = (__bfloat162float(ph[e]) + __bfloat162float(pl[e])) * a;
        split_bf16(f, qh[e], ql[e]);
    }
    size_t ao = (b * 4096 + l) * 768 + d;
    *(uint4*)(gA_hi + ao) = oh;
    *(uint4*)(gA_lo + ao) = ol;
}

// ------------------- K3: mma.sync bf16x3 final GEMM, tile 128l x 128o -------------------
// smem: A0 0 | A1 20480 | B0 40960 | B1 61440  = 81920 B; 2 CTAs/SM
#define KF_A0 0
#define KF_A1 20480
#define KF_B0 40960
#define KF_B1 61440
#define KF_SM 81920
__global__ __launch_bounds__(256, 2) void k_final_mma(float* __restrict__ out) {
    extern __shared__ char smc[];
    int tid = threadIdx.x, lane = tid & 31, warp = tid >> 5;
    int wm = warp >> 1, wn = warp & 1;
    int ot = blockIdx.x, lt = blockIdx.y, b = blockIdx.z;   // ot fastest -> L2 reuse of A
    int l0 = lt * 128, o0 = ot * 128;
    uint32_t sb = smem_u32(smc);

    const __nv_bfloat16* Ahg = gA_hi + ((size_t)b * Ldim + l0) * 768;
    const __nv_bfloat16* Alg = gA_lo + ((size_t)b * Ldim + l0) * 768;
    const __nv_bfloat16* Bhg = gB_hi + (size_t)o0 * 768;
    const __nv_bfloat16* Blg = gB_lo + (size_t)o0 * 768;

    float c[2][8][4];
    #pragma unroll
    for (int t = 0; t < 2; t++)
        #pragma unroll
        for (int n = 0; n < 8; n++)
            #pragma unroll
            for (int q = 0; q < 4; q++) c[t][n][q] = 0.f;

    auto stage = [&](int c0, int buf) {
        char* ab = smc + (buf ? KF_A1 : KF_A0);
        char* bb = smc + (buf ? KF_B1 : KF_B0);
        for (int u = tid; u < 512; u += 256) {
            int row = u >> 2, seg = u & 3;
            size_t ao = (size_t)row * 768 + c0 + seg * 8;
            cpa16(ab + row * 80 + seg * 16, Ahg + ao);
            cpa16(ab + 10240 + row * 80 + seg * 16, Alg + ao);
            cpa16(bb + row * 80 + seg * 16, Bhg + ao);
            cpa16(bb + 10240 + row * 80 + seg * 16, Blg + ao);
        }
    };

    stage(0, 0);
    CP_COMMIT();

    for (int ci = 0; ci < 24; ci++) {
        CP_WAIT0();
        __syncthreads();
        if (ci < 23) {
            stage((ci + 1) * 32, (ci + 1) & 1);
            CP_COMMIT();
        }
        uint32_t abuf = sb + ((ci & 1) ? KF_A1 : KF_A0);
        uint32_t bbuf = sb + ((ci & 1) ? KF_B1 : KF_B0);
        int quad = lane >> 3, rr = lane & 7;
        #pragma unroll
        for (int s = 0; s < 2; s++) {
            int k0 = s * 16;
            uint32_t ah[2][4], al[2][4];
            #pragma unroll
            for (int t = 0; t < 2; t++) {
                int row = wm * 32 + t * 16 + (lane & 15);
                uint32_t ad = abuf + row * 80 + (k0 + ((lane >> 4) << 3)) * 2;
                ldm_x4(ah[t], ad);
                ldm_x4(al[t], ad + 10240);
            }
            uint32_t bh[4][4], bl[4][4];
            #pragma unroll
            for (int p = 0; p < 4; p++) {
                int n = wn * 64 + p * 16 + ((quad >> 1) << 3) + rr;
                uint32_t bd = bbuf + n * 80 + (k0 + ((quad & 1) << 3)) * 2;
                ldm_x4(bh[p], bd);
                ldm_x4(bl[p], bd + 10240);
            }
            #pragma unroll
            for (int t = 0; t < 2; t++)
                #pragma unroll
                for (int nt = 0; nt < 8; nt++) {
                    int p = nt >> 1, w2 = (nt & 1) * 2;
                    mma_bf16(c[t][nt], ah[t], bh[p][w2], bh[p][w2 + 1]);
                    mma_bf16(c[t][nt], ah[t], bl[p][w2], bl[p][w2 + 1]);
                    mma_bf16(c[t][nt], al[t], bh[p][w2], bh[p][w2 + 1]);
                }
        }
    }

    int gid = lane >> 2, tig = lane & 3;
    #pragma unroll
    for (int t = 0; t < 2; t++) {
        size_t r0 = (size_t)b * Ldim + l0 + wm * 32 + t * 16 + gid;
        #pragma unroll
        for (int nt = 0; nt < 8; nt++) {
            int o = o0 + wn * 64 + nt * 8 + tig * 2;
            *(float2*)(out + r0 * Ddim + o)       = make_float2(c[t][nt][0], c[t][nt][1]);
            *(float2*)(out + (r0 + 8) * Ddim + o) = make_float2(c[t][nt][2], c[t][nt][3]);
        }
    }
}

// ------------------- K4: final row RMSNorm (in place) -------------------
__global__ __launch_bounds__(256) void k_norm(float* __restrict__ out,
                                              const float* __restrict__ nsc) {
    __shared__ float ns[512];
    int tid = threadIdx.x;
    ns[tid] = nsc[tid];
    ns[tid + 256] = nsc[tid + 256];
    __syncthreads();

    int warp = tid >> 5, lane = tid & 31;
    size_t row = (size_t)blockIdx.x * 8 + warp;
    float* p = out + row * Ddim;

    float4 v[4];
    float ssq = 0.f;
    #pragma unroll
    for (int q = 0; q < 4; q++) {
        v[q] = *(const float4*)(p + (q * 32 + lane) * 4);
        ssq += v[q].x * v[q].x + v[q].y * v[q].y + v[q].z * v[q].z + v[q].w * v[q].w;
    }
    #pragma unroll
    for (int off = 16; off > 0; off >>= 1)
        ssq += __shfl_xor_sync(0xFFFFFFFFu, ssq, off);
    float rms = sqrtf(ssq * (1.f / 512.f));
    float inv = 1.f / (rms + EPSF);
    #pragma unroll
    for (int q = 0; q < 4; q++) {
        int base = (q * 32 + lane) * 4;
        float4 w;
        w.x = v[q].x * ns[base + 0] * inv;
        w.y = v[q].y * ns[base + 1] * inv;
        w.z = v[q].z * ns[base + 2] * inv;
        w.w = v[q].w * ns[base + 3] * inv;
        *(float4*)(p + base) = w;
    }
}

// ------------------- launch -------------------
extern "C" void kernel_launch(void* const* d_in, const int* in_sizes, int n_in,
                              void* d_out, int out_size) {
    const float* x = (const float*)d_in[0];
    const float *dw[4], *pw[4], *cnp[4];
    if (in_sizes[2] == 768) {
        for (int i = 0; i < 4; i++) {
            dw[i]  = (const float*)d_in[1 + i];
            pw[i]  = (const float*)d_in[5 + i];
            cnp[i] = (const float*)d_in[9 + i];
        }
    } else {
        for (int i = 0; i < 4; i++) {
            dw[i]  = (const float*)d_in[1 + 3 * i];
            pw[i]  = (const float*)d_in[2 + 3 * i];
            cnp[i] = (const float*)d_in[3 + 3 * i];
        }
    }
    const float* w1  = (const float*)d_in[13];
    const float* b1  = (const float*)d_in[14];
    const float* w2  = (const float*)d_in[15];
    const float* b2  = (const float*)d_in[16];
    const float* fw  = (const float*)d_in[17];
    const float* nsc = (const float*)d_in[18];
    const float* rw  = (const float*)d_in[19];
    float* out = (float*)d_out;

    cudaFuncSetAttribute(k_conv,      cudaFuncAttributeMaxDynamicSharedMemorySize, KC_SM);
    cudaFuncSetAttribute(k_attn,      cudaFuncAttributeMaxDynamicSharedMemorySize, KA_SM);
    cudaFuncSetAttribute(k_final_mma, cudaFuncAttributeMaxDynamicSharedMemorySize, KF_SM);

    k_prepW<<<589824 / 256, 256>>>(pw[0], pw[1], pw[2], pw[3], w1, fw, rw);
    k_xsplit<<<(int)(((size_t)Bdim * Ldim * Cdim) / (4 * 256)), 256>>>(x);
    k_conv<<<dim3(Ldim / 128, Bdim, 4), 256, KC_SM>>>(x, dw[0], dw[1], dw[2], dw[3],
                                                      cnp[0], cnp[1], cnp[2], cnp[3]);
    k_attn<<<dim3(Ldim / 128, Bdim), 256, KA_SM>>>(b1, w2, b2);
    k_wfeats<<<(int)(((size_t)Bdim * Ldim * 512) / (8 * 256)), 256>>>();
    k_final_mma<<<dim3(Ddim / 128, Ldim / 128, Bdim), 256, KF_SM>>>(out);
    k_norm<<<(Bdim * Ldim) / 8, 256>>>(out, nsc);
}

// round 12
// speedup vs baseline: 2.5452x; 1.0207x over previous
#include <cuda_runtime.h>
#include <cuda_bf16.h>
#include <math.h>
#include <stdint.h>

#define Bdim 16
#define Ldim 4096
#define Cdim 256
#define Ddim 512
#define EPSF 1e-8f

typedef unsigned long long ull;

// ------------------- scratch (device globals; no allocs allowed) -------------------
__device__ float g_attn[(size_t)Bdim * 4 * Ldim];           // [b][i][l]
__device__ __nv_bfloat16 gF_hi[(size_t)Bdim * Ldim * 512];  // feats (post-gelu) [b][l][512]
__device__ __nv_bfloat16 gF_lo[(size_t)Bdim * Ldim * 512];
__device__ __nv_bfloat16 gB_hi[512 * 768];                  // [o][768]: fw | rw
__device__ __nv_bfloat16 gB_lo[512 * 768];
__device__ __nv_bfloat16 pwB_hi[4 * 128 * 256];             // [sc][o][c]
__device__ __nv_bfloat16 pwB_lo[4 * 128 * 256];
__device__ __nv_bfloat16 w1B_hi[128 * 512];                 // [dh][d]
__device__ __nv_bfloat16 w1B_lo[128 * 512];

// ------------------- helpers -------------------
__device__ __forceinline__ void cpa16(void* dst, const void* src) {
    unsigned s = (unsigned)__cvta_generic_to_shared(dst);
    asm volatile("cp.async.cg.shared.global [%0], [%1], 16;" :: "r"(s), "l"(src));
}
#define CP_COMMIT() asm volatile("cp.async.commit_group;")
#define CP_WAIT0()  asm volatile("cp.async.wait_group 0;" ::: "memory")

__device__ __forceinline__ uint32_t smem_u32(const void* p) {
    uint32_t a;
    asm("{ .reg .u64 t; cvta.to.shared.u64 t, %1; cvt.u32.u64 %0, t; }" : "=r"(a) : "l"(p));
    return a;
}
__device__ __forceinline__ void ldm_x4(uint32_t r[4], uint32_t addr) {
    asm volatile("ldmatrix.sync.aligned.m8n8.x4.shared.b16 {%0,%1,%2,%3}, [%4];"
                 : "=r"(r[0]), "=r"(r[1]), "=r"(r[2]), "=r"(r[3]) : "r"(addr));
}
__device__ __forceinline__ void mma_bf16(float c[4], const uint32_t a[4],
                                         uint32_t b0, uint32_t b1) {
    asm volatile("mma.sync.aligned.m16n8k16.row.col.f32.bf16.bf16.f32 "
                 "{%0,%1,%2,%3}, {%4,%5,%6,%7}, {%8,%9}, {%0,%1,%2,%3};"
                 : "+f"(c[0]), "+f"(c[1]), "+f"(c[2]), "+f"(c[3])
                 : "r"(a[0]), "r"(a[1]), "r"(a[2]), "r"(a[3]), "r"(b0), "r"(b1));
}
__device__ __forceinline__ void split_bf16(float v, __nv_bfloat16& hi, __nv_bfloat16& lo) {
    hi = __float2bfloat16(v);
    lo = __float2bfloat16(v - __bfloat162float(hi));
}
__device__ __forceinline__ uint32_t pack_bf2(__nv_bfloat16 a, __nv_bfloat16 b) {
    uint16_t ua = *(uint16_t*)&a, ub = *(uint16_t*)&b;
    return (uint32_t)ua | ((uint32_t)ub << 16);
}

// ------------------- K0: split all tensor-path weights to bf16 hi/lo -------------------
__global__ void k_prepW(const float* __restrict__ pw1, const float* __restrict__ pw3,
                        const float* __restrict__ pw5, const float* __restrict__ pw7,
                        const float* __restrict__ w1,
                        const float* __restrict__ fw, const float* __restrict__ rw) {
    int idx = blockIdx.x * blockDim.x + threadIdx.x;
    if (idx >= 589824) return;
    float v;
    __nv_bfloat16 hi, lo;
    if (idx < 131072) {
        int s = idx >> 15, r = idx & 32767;
        int o = r >> 8, c = r & 255;
        const float* pw = (s == 0) ? pw1 : (s == 1) ? pw3 : (s == 2) ? pw5 : pw7;
        v = pw[o * 256 + c];
        split_bf16(v, hi, lo);
        pwB_hi[idx] = hi; pwB_lo[idx] = lo;
    } else if (idx < 196608) {
        int r = idx - 131072;
        v = w1[r];
        split_bf16(v, hi, lo);
        w1B_hi[r] = hi; w1B_lo[r] = lo;
    } else {
        int r = idx - 196608;
        int o = r / 768, d = r % 768;
        v = (d < 512) ? fw[o * 512 + d] : rw[o * 256 + (d - 512)];
        split_bf16(v, hi, lo);
        gB_hi[r] = hi; gB_lo[r] = lo;
    }
}

// ------------------- K1: conv (scalar) + pointwise (mma bf16x3) + RMSNorm + GELU -------------------
#define KC_XS  0
#define KC_AH  17152
#define KC_AL  27392
#define KC_PW0 37632
#define KC_PW1 58112
#define KC_SM  78592
__global__ __launch_bounds__(256, 2) void k_conv(
    const float* __restrict__ x,
    const float* __restrict__ dw1, const float* __restrict__ dw3,
    const float* __restrict__ dw5, const float* __restrict__ dw7,
    const float* __restrict__ cn1, const float* __restrict__ cn3,
    const float* __restrict__ cn5, const float* __restrict__ cn7) {
    extern __shared__ char smc[];
    float* xs = (float*)(smc + KC_XS);

    int tid = threadIdx.x, lane = tid & 31, warp = tid >> 5;
    int wm = warp >> 1, wn = warp & 1;
    int lt = blockIdx.x, b = blockIdx.y, sc = blockIdx.z;
    int l0 = lt * 128;
    int k = 2 * sc + 1, r = sc;
    bool edge = (lt == 0) || (lt == Ldim / 128 - 1);
    const float* dw = (sc == 0) ? dw1 : (sc == 1) ? dw3 : (sc == 2) ? dw5 : dw7;
    const float* cn = (sc == 0) ? cn1 : (sc == 1) ? cn3 : (sc == 2) ? cn5 : cn7;
    const __nv_bfloat16* pwh = pwB_hi + sc * 32768;
    const __nv_bfloat16* pwl = pwB_lo + sc * 32768;
    uint32_t sb = smem_u32(smc);

    int cld = tid & 31, lg = tid >> 5;

    float c[2][8][4];
    #pragma unroll
    for (int t = 0; t < 2; t++)
        #pragma unroll
        for (int n = 0; n < 8; n++)
            #pragma unroll
            for (int q = 0; q < 4; q++) c[t][n][q] = 0.f;

    auto stage_x = [&](int c0) {
        if (!edge) {
            for (int u = tid; u < 1072; u += 256) {
                int i = u >> 3, seg = u & 7;
                cpa16(smc + KC_XS + i * 128 + seg * 16,
                      x + ((size_t)b * Ldim + l0 - 3 + i) * Cdim + c0 + seg * 4);
            }
        } else {
            for (int u = tid; u < 4288; u += 256) {
                int i = u >> 5, cc = u & 31;
                int gl = l0 - 3 + i;
                xs[u] = (gl >= 0 && gl < Ldim)
                      ? x[((size_t)b * Ldim + gl) * Cdim + c0 + cc] : 0.f;
            }
        }
    };
    auto stage_pw = [&](int c0, int buf) {
        char* base = smc + (buf ? KC_PW1 : KC_PW0);
        for (int u = tid; u < 512; u += 256) {
            int o = u >> 2, seg = u & 3;
            cpa16(base + o * 80 + seg * 16, pwh + (size_t)o * 256 + c0 + seg * 8);
            cpa16(base + 10240 + o * 80 + seg * 16, pwl + (size_t)o * 256 + c0 + seg * 8);
        }
    };

    stage_x(0);
    stage_pw(0, 0);
    CP_COMMIT();

    for (int ci = 0; ci < 8; ci++) {
        int c0 = ci * 32;
        CP_WAIT0();
        __syncthreads();
        float rd[7];
        #pragma unroll
        for (int t = 0; t < 7; t++) rd[t] = (t < k) ? dw[(c0 + cld) * k + t] : 0.f;
        #pragma unroll
        for (int ii = 0; ii < 16; ii++) {
            int l = lg * 16 + ii;
            float s = 0.f;
            for (int t = 0; t < k; t++) s += rd[t] * xs[(l + 3 - r + t) * 32 + cld];
            __nv_bfloat16 hi, lo;
            split_bf16(s, hi, lo);
            *(__nv_bfloat16*)(smc + KC_AH + l * 80 + cld * 2) = hi;
            *(__nv_bfloat16*)(smc + KC_AL + l * 80 + cld * 2) = lo;
        }
        __syncthreads();
        if (ci < 7) {
            stage_x(c0 + 32);
            stage_pw(c0 + 32, (ci + 1) & 1);
            CP_COMMIT();
        }
        uint32_t pwbuf = sb + ((ci & 1) ? KC_PW1 : KC_PW0);
        int quad = lane >> 3, rr = lane & 7;
        #pragma unroll
        for (int s = 0; s < 2; s++) {
            int k0 = s * 16;
            uint32_t ah[2][4], al[2][4];
            #pragma unroll
            for (int t = 0; t < 2; t++) {
                int row = wm * 32 + t * 16 + (lane & 15);
                uint32_t ad = sb + KC_AH + row * 80 + (k0 + ((lane >> 4) << 3)) * 2;
                ldm_x4(ah[t], ad);
                ldm_x4(al[t], ad + (KC_AL - KC_AH));
            }
            uint32_t bh[4][4], bl[4][4];
            #pragma unroll
            for (int p = 0; p < 4; p++) {
                int n = wn * 64 + p * 16 + ((quad >> 1) << 3) + rr;
                uint32_t bd = pwbuf + n * 80 + (k0 + ((quad & 1) << 3)) * 2;
                ldm_x4(bh[p], bd);
                ldm_x4(bl[p], bd + 10240);
            }
            #pragma unroll
            for (int t = 0; t < 2; t++)
                #pragma unroll
                for (int nt = 0; nt < 8; nt++) {
                    int p = nt >> 1, w2 = (nt & 1) * 2;
                    mma_bf16(c[t][nt], ah[t], bh[p][w2], bh[p][w2 + 1]);
                    mma_bf16(c[t][nt], ah[t], bl[p][w2], bl[p][w2 + 1]);
                    mma_bf16(c[t][nt], al[t], bh[p][w2], bh[p][w2 + 1]);
                }
        }
    }
    __syncthreads();

    float* red = (float*)(smc + KC_XS);   // [128][2]
    int gid = lane >> 2, tig = lane & 3;
    #pragma unroll
    for (int t = 0; t < 2; t++) {
        float p0 = 0.f, p1 = 0.f;
        #pragma unroll
        for (int nt = 0; nt < 8; nt++) {
            p0 += c[t][nt][0] * c[t][nt][0] + c[t][nt][1] * c[t][nt][1];
            p1 += c[t][nt][2] * c[t][nt][2] + c[t][nt][3] * c[t][nt][3];
        }
        p0 += __shfl_xor_sync(0xFFFFFFFFu, p0, 1);
        p0 += __shfl_xor_sync(0xFFFFFFFFu, p0, 2);
        p1 += __shfl_xor_sync(0xFFFFFFFFu, p1, 1);
        p1 += __shfl_xor_sync(0xFFFFFFFFu, p1, 2);
        if (tig == 0) {
            int r0 = wm * 32 + t * 16 + gid;
            red[r0 * 2 + wn] = p0;
            red[(r0 + 8) * 2 + wn] = p1;
        }
    }
    __syncthreads();
    #pragma unroll
    for (int t = 0; t < 2; t++) {
        int r0 = wm * 32 + t * 16 + gid;
        float inv0 = 1.f / (sqrtf((red[r0 * 2] + red[r0 * 2 + 1]) * (1.f / 128.f)) + EPSF);
        float inv1 = 1.f / (sqrtf((red[(r0 + 8) * 2] + red[(r0 + 8) * 2 + 1]) * (1.f / 128.f)) + EPSF);
        #pragma unroll
        for (int nt = 0; nt < 8; nt++) {
            int o = wn * 64 + nt * 8 + tig * 2;
            float cn0 = cn[o], cn1 = cn[o + 1];
            float h00 = c[t][nt][0] * cn0 * inv0, h01 = c[t][nt][1] * cn1 * inv0;
            float h10 = c[t][nt][2] * cn0 * inv1, h11 = c[t][nt][3] * cn1 * inv1;
            h00 *= normcdff(h00); h01 *= normcdff(h01);
            h10 *= normcdff(h10); h11 *= normcdff(h11);
            size_t row0 = ((size_t)b * Ldim + l0 + r0) * 512 + sc * 128 + o;
            size_t row1 = row0 + 8 * 512;
            __nv_bfloat16 a0h, a0l, a1h, a1l;
            split_bf16(h00, a0h, a0l); split_bf16(h01, a1h, a1l);
            *(uint32_t*)(gF_hi + row0) = pack_bf2(a0h, a1h);
            *(uint32_t*)(gF_lo + row0) = pack_bf2(a0l, a1l);
            split_bf16(h10, a0h, a0l); split_bf16(h11, a1h, a1l);
            *(uint32_t*)(gF_hi + row1) = pack_bf2(a0h, a1h);
            *(uint32_t*)(gF_lo + row1) = pack_bf2(a0l, a1l);
        }
    }
}

// ------------------- K2: attention MLP (mma bf16x3) + softmax -------------------
#define KA_A0  0
#define KA_A1  20480
#define KA_B0  40960
#define KA_B1  61440
#define KA_W2  81920
#define KA_SM  83968
__global__ __launch_bounds__(256, 2) void k_attn(const float* __restrict__ b1p,
                                                 const float* __restrict__ w2p,
                                                 const float* __restrict__ b2p) {
    extern __shared__ char smc[];
    float* w2s = (float*)(smc + KA_W2);
    int tid = threadIdx.x, lane = tid & 31, warp = tid >> 5;
    int wm = warp >> 1, wn = warp & 1;
    int b = blockIdx.y;
    int l0 = blockIdx.x * 128;
    uint32_t sb = smem_u32(smc);
    size_t bL = (size_t)b * Ldim + l0;

    w2s[tid] = w2p[tid];
    w2s[tid + 256] = w2p[tid + 256];

    float c[2][8][4];
    #pragma unroll
    for (int t = 0; t < 2; t++)
        #pragma unroll
        for (int n = 0; n < 8; n++)
            #pragma unroll
            for (int q = 0; q < 4; q++) c[t][n][q] = 0.f;

    auto stage = [&](int c0, int buf) {
        char* ab = smc + (buf ? KA_A1 : KA_A0);
        char* bb = smc + (buf ? KA_B1 : KA_B0);
        for (int u = tid; u < 512; u += 256) {
            int row = u >> 2, seg = u & 3;
            size_t ao = (bL + row) * 512 + c0 + seg * 8;
            cpa16(ab + row * 80 + seg * 16, gF_hi + ao);
            cpa16(ab + 10240 + row * 80 + seg * 16, gF_lo + ao);
            size_t bo = (size_t)row * 512 + c0 + seg * 8;
            cpa16(bb + row * 80 + seg * 16, w1B_hi + bo);
            cpa16(bb + 10240 + row * 80 + seg * 16, w1B_lo + bo);
        }
    };

    stage(0, 0);
    CP_COMMIT();

    for (int ci = 0; ci < 16; ci++) {
        CP_WAIT0();
        __syncthreads();
        if (ci < 15) {
            stage((ci + 1) * 32, (ci + 1) & 1);
            CP_COMMIT();
        }
        uint32_t abuf = sb + ((ci & 1) ? KA_A1 : KA_A0);
        uint32_t bbuf = sb + ((ci & 1) ? KA_B1 : KA_B0);
        int quad = lane >> 3, rr = lane & 7;
        #pragma unroll
        for (int s = 0; s < 2; s++) {
            int k0 = s * 16;
            uint32_t ah[2][4], al[2][4];
            #pragma unroll
            for (int t = 0; t < 2; t++) {
                int row = wm * 32 + t * 16 + (lane & 15);
                uint32_t ad = abuf + row * 80 + (k0 + ((lane >> 4) << 3)) * 2;
                ldm_x4(ah[t], ad);
                ldm_x4(al[t], ad + 10240);
            }
            uint32_t bh[4][4], bl[4][4];
            #pragma unroll
            for (int p = 0; p < 4; p++) {
                int n = wn * 64 + p * 16 + ((quad >> 1) << 3) + rr;
                uint32_t bd = bbuf + n * 80 + (k0 + ((quad & 1) << 3)) * 2;
                ldm_x4(bh[p], bd);
                ldm_x4(bl[p], bd + 10240);
            }
            #pragma unroll
            for (int t = 0; t < 2; t++)
                #pragma unroll
                for (int nt = 0; nt < 8; nt++) {
                    int p = nt >> 1, w2 = (nt & 1) * 2;
                    mma_bf16(c[t][nt], ah[t], bh[p][w2], bh[p][w2 + 1]);
                    mma_bf16(c[t][nt], ah[t], bl[p][w2], bl[p][w2 + 1]);
                    mma_bf16(c[t][nt], al[t], bh[p][w2], bh[p][w2 + 1]);
                }
        }
    }
    __syncthreads();

    float* red4 = (float*)smc;
    int gid = lane >> 2, tig = lane & 3;
    float part[4][2][2];
    #pragma unroll
    for (int i4 = 0; i4 < 4; i4++)
        #pragma unroll
        for (int t = 0; t < 2; t++) { part[i4][t][0] = 0.f; part[i4][t][1] = 0.f; }
    #pragma unroll
    for (int t = 0; t < 2; t++)
        #pragma unroll
        for (int nt = 0; nt < 8; nt++) {
            int dh = wn * 64 + nt * 8 + tig * 2;
            float b10 = b1p[dh], b11 = b1p[dh + 1];
            float g00 = c[t][nt][0] + b10, g01 = c[t][nt][1] + b11;
            float g10 = c[t][nt][2] + b10, g11 = c[t][nt][3] + b11;
            g00 *= normcdff(g00); g01 *= normcdff(g01);
            g10 *= normcdff(g10); g11 *= normcdff(g11);
            #pragma unroll
            for (int i4 = 0; i4 < 4; i4++) {
                float w0 = w2s[i4 * 128 + dh], w1v = w2s[i4 * 128 + dh + 1];
                part[i4][t][0] += w0 * g00 + w1v * g01;
                part[i4][t][1] += w0 * g10 + w1v * g11;
            }
        }
    #pragma unroll
    for (int i4 = 0; i4 < 4; i4++)
        #pragma unroll
        for (int t = 0; t < 2; t++)
            #pragma unroll
            for (int rr2 = 0; rr2 < 2; rr2++) {
                float p = part[i4][t][rr2];
                p += __shfl_xor_sync(0xFFFFFFFFu, p, 1);
                p += __shfl_xor_sync(0xFFFFFFFFu, p, 2);
                part[i4][t][rr2] = p;
            }
    if (tig == 0) {
        #pragma unroll
        for (int i4 = 0; i4 < 4; i4++)
            #pragma unroll
            for (int t = 0; t < 2; t++) {
                int r0 = wm * 32 + t * 16 + gid;
                red4[(i4 * 128 + r0) * 2 + wn] = part[i4][t][0];
                red4[(i4 * 128 + r0 + 8) * 2 + wn] = part[i4][t][1];
            }
    }
    __syncthreads();
    if (wn == 0 && tig == 0) {
        #pragma unroll
        for (int t = 0; t < 2; t++)
            #pragma unroll
            for (int rr2 = 0; rr2 < 2; rr2++) {
                int l = wm * 32 + t * 16 + gid + rr2 * 8;
                float a2[4];
                #pragma unroll
                for (int i4 = 0; i4 < 4; i4++)
                    a2[i4] = red4[(i4 * 128 + l) * 2] + red4[(i4 * 128 + l) * 2 + 1] + b2p[i4];
                float m = fmaxf(fmaxf(a2[0], a2[1]), fmaxf(a2[2], a2[3]));
                float s = 0.f;
                #pragma unroll
                for (int i4 = 0; i4 < 4; i4++) { a2[i4] = expf(a2[i4] - m); s += a2[i4]; }
                float invs = 1.f / s;
                #pragma unroll
                for (int i4 = 0; i4 < 4; i4++)
                    g_attn[((size_t)b * 4 + i4) * Ldim + l0 + l] = a2[i4] * invs;
            }
    }
}

// ------------------- K3: fused final GEMM: A staged from gF*attn | x, B cp.async -------------------
// smem: A0 0 (20480) | A1 20480 | B0 40960 | B1 61440 | attn 81920 (2048) = 83968
#define KF_A0 0
#define KF_A1 20480
#define KF_B0 40960
#define KF_B1 61440
#define KF_AT 81920
#define KF_SM 83968
__global__ __launch_bounds__(256, 2) void k_final_mma(const float* __restrict__ x,
                                                      float* __restrict__ out) {
    extern __shared__ char smc[];
    float* atts = (float*)(smc + KF_AT);
    int tid = threadIdx.x, lane = tid & 31, warp = tid >> 5;
    int wm = warp >> 1, wn = warp & 1;
    int ot = blockIdx.x, lt = blockIdx.y, b = blockIdx.z;   // ot fastest -> L2 reuse of A
    int l0 = lt * 128, o0 = ot * 128;
    uint32_t sb = smem_u32(smc);

    atts[tid]       = g_attn[((size_t)b * 4 + (tid >> 7)) * Ldim + l0 + (tid & 127)];
    atts[tid + 256] = g_attn[((size_t)b * 4 + 2 + (tid >> 7)) * Ldim + l0 + (tid & 127)];

    int arow = tid >> 1, aseg = tid & 1;
    size_t xrow = (size_t)b * Ldim + l0 + arow;
    const __nv_bfloat16* Bhg = gB_hi + (size_t)o0 * 768;
    const __nv_bfloat16* Blg = gB_lo + (size_t)o0 * 768;

    float c[2][8][4];
    #pragma unroll
    for (int t = 0; t < 2; t++)
        #pragma unroll
        for (int n = 0; n < 8; n++)
            #pragma unroll
            for (int q = 0; q < 4; q++) c[t][n][q] = 0.f;

    uint4 r0, r1, r2, r3;
    auto prefetch = [&](int c0) {
        if (c0 < 512) {
            size_t base = xrow * 512 + c0 + aseg * 16;
            r0 = *(const uint4*)(gF_hi + base);
            r1 = *(const uint4*)(gF_hi + base + 8);
            r2 = *(const uint4*)(gF_lo + base);
            r3 = *(const uint4*)(gF_lo + base + 8);
        } else {
            size_t base = xrow * 256 + (c0 - 512) + aseg * 16;
            r0 = *(const uint4*)(x + base);
            r1 = *(const uint4*)(x + base + 4);
            r2 = *(const uint4*)(x + base + 8);
            r3 = *(const uint4*)(x + base + 12);
        }
    };
    auto sts_a = [&](int c0, int buf) {
        char* ab = smc + (buf ? KF_A1 : KF_A0);
        float f[16];
        uint4 rr4[4] = {r0, r1, r2, r3};
        if (c0 < 512) {
            float av = atts[((c0 >> 7) << 7) + arow];
            const __nv_bfloat16* ph = (const __nv_bfloat16*)&rr4[0];   // r0,r1 = hi x16
            const __nv_bfloat16* pl = (const __nv_bfloat16*)&rr4[2];   // r2,r3 = lo x16
            #pragma unroll
            for (int e = 0; e < 16; e++)
                f[e] = (__bfloat162float(ph[e]) + __bfloat162float(pl[e])) * av;
        } else {
            const float* pf = (const float*)rr4;
            #pragma unroll
            for (int e = 0; e < 16; e++) f[e] = pf[e];
        }
        uint32_t oh[8], ol[8];
        #pragma unroll
        for (int e2 = 0; e2 < 8; e2++) {
            __nv_bfloat16 h0, lo0, h1, lo1;
            split_bf16(f[2 * e2], h0, lo0);
            split_bf16(f[2 * e2 + 1], h1, lo1);
            oh[e2] = pack_bf2(h0, h1);
            ol[e2] = pack_bf2(lo0, lo1);
        }
        char* dh = ab + arow * 80 + aseg * 32;
        *(uint4*)dh        = make_uint4(oh[0], oh[1], oh[2], oh[3]);
        *(uint4*)(dh + 16) = make_uint4(oh[4], oh[5], oh[6], oh[7]);
        char* dl = dh + 10240;
        *(uint4*)dl        = make_uint4(ol[0], ol[1], ol[2], ol[3]);
        *(uint4*)(dl + 16) = make_uint4(ol[4], ol[5], ol[6], ol[7]);
    };
    auto stage_b = [&](int c0, int buf) {
        char* bb = smc + (buf ? KF_B1 : KF_B0);
        for (int u = tid; u < 512; u += 256) {
            int row = u >> 2, seg = u & 3;
            size_t bo = (size_t)row * 768 + c0 + seg * 8;
            cpa16(bb + row * 80 + seg * 16, Bhg + bo);
            cpa16(bb + 10240 + row * 80 + seg * 16, Blg + bo);
        }
    };

    prefetch(0);
    stage_b(0, 0);
    CP_COMMIT();
    __syncthreads();   // atts visible

    for (int ci = 0; ci < 24; ci++) {
        CP_WAIT0();
        sts_a(ci * 32, ci & 1);
        __syncthreads();
        if (ci < 23) {
            prefetch((ci + 1) * 32);
            stage_b((ci + 1) * 32, (ci + 1) & 1);
            CP_COMMIT();
        }
        uint32_t abuf = sb + ((ci & 1) ? KF_A1 : KF_A0);
        uint32_t bbuf = sb + ((ci & 1) ? KF_B1 : KF_B0);
        int quad = lane >> 3, rrl = lane & 7;
        #pragma unroll
        for (int s = 0; s < 2; s++) {
            int k0 = s * 16;
            uint32_t ah[2][4], al[2][4];
            #pragma unroll
            for (int t = 0; t < 2; t++) {
                int row = wm * 32 + t * 16 + (lane & 15);
                uint32_t ad = abuf + row * 80 + (k0 + ((lane >> 4) << 3)) * 2;
                ldm_x4(ah[t], ad);
                ldm_x4(al[t], ad + 10240);
            }
            #pragma unroll
            for (int p = 0; p < 4; p++) {
                int n = wn * 64 + p * 16 + ((quad >> 1) << 3) + rrl;
                uint32_t bd = bbuf + n * 80 + (k0 + ((quad & 1) << 3)) * 2;
                uint32_t bh4[4], bl4[4];
                ldm_x4(bh4, bd);
                ldm_x4(bl4, bd + 10240);
                #pragma unroll
                for (int half = 0; half < 2; half++) {
                    int nt = 2 * p + half, w2 = half * 2;
                    #pragma unroll
                    for (int t = 0; t < 2; t++) {
                        mma_bf16(c[t][nt], ah[t], bh4[w2], bh4[w2 + 1]);
                        mma_bf16(c[t][nt], ah[t], bl4[w2], bl4[w2 + 1]);
                        mma_bf16(c[t][nt], al[t], bh4[w2], bh4[w2 + 1]);
                    }
                }
            }
        }
    }

    int gid = lane >> 2, tig = lane & 3;
    #pragma unroll
    for (int t = 0; t < 2; t++) {
        size_t rb = (size_t)b * Ldim + l0 + wm * 32 + t * 16 + gid;
        #pragma unroll
        for (int nt = 0; nt < 8; nt++) {
            int o = o0 + wn * 64 + nt * 8 + tig * 2;
            *(float2*)(out + rb * Ddim + o)       = make_float2(c[t][nt][0], c[t][nt][1]);
            *(float2*)(out + (rb + 8) * Ddim + o) = make_float2(c[t][nt][2], c[t][nt][3]);
        }
    }
}

// ------------------- K4: final row RMSNorm (in place) -------------------
__global__ __launch_bounds__(256) void k_norm(float* __restrict__ out,
                                              const float* __restrict__ nsc) {
    __shared__ float ns[512];
    int tid = threadIdx.x;
    ns[tid] = nsc[tid];
    ns[tid + 256] = nsc[tid + 256];
    __syncthreads();

    int warp = tid >> 5, lane = tid & 31;
    size_t row = (size_t)blockIdx.x * 8 + warp;
    float* p = out + row * Ddim;

    float4 v[4];
    float ssq = 0.f;
    #pragma unroll
    for (int q = 0; q < 4; q++) {
        v[q] = *(const float4*)(p + (q * 32 + lane) * 4);
        ssq += v[q].x * v[q].x + v[q].y * v[q].y + v[q].z * v[q].z + v[q].w * v[q].w;
    }
    #pragma unroll
    for (int off = 16; off > 0; off >>= 1)
        ssq += __shfl_xor_sync(0xFFFFFFFFu, ssq, off);
    float rms = sqrtf(ssq * (1.f / 512.f));
    float inv = 1.f / (rms + EPSF);
    #pragma unroll
    for (int q = 0; q < 4; q++) {
        int base = (q * 32 + lane) * 4;
        float4 w;
        w.x = v[q].x * ns[base + 0] * inv;
        w.y = v[q].y * ns[base + 1] * inv;
        w.z = v[q].z * ns[base + 2] * inv;
        w.w = v[q].w * ns[base + 3] * inv;
        *(float4*)(p + base) = w;
    }
}

// ------------------- launch -------------------
extern "C" void kernel_launch(void* const* d_in, const int* in_sizes, int n_in,
                              void* d_out, int out_size) {
    const float* x = (const float*)d_in[0];
    const float *dw[4], *pw[4], *cnp[4];
    if (in_sizes[2] == 768) {
        for (int i = 0; i < 4; i++) {
            dw[i]  = (const float*)d_in[1 + i];
            pw[i]  = (const float*)d_in[5 + i];
            cnp[i] = (const float*)d_in[9 + i];
        }
    } else {
        for (int i = 0; i < 4; i++) {
            dw[i]  = (const float*)d_in[1 + 3 * i];
            pw[i]  = (const float*)d_in[2 + 3 * i];
            cnp[i] = (const float*)d_in[3 + 3 * i];
        }
    }
    const float* w1  = (const float*)d_in[13];
    const float* b1  = (const float*)d_in[14];
    const float* w2  = (const float*)d_in[15];
    const float* b2  = (const float*)d_in[16];
    const float* fw  = (const float*)d_in[17];
    const float* nsc = (const float*)d_in[18];
    const float* rw  = (const float*)d_in[19];
    float* out = (float*)d_out;

    cudaFuncSetAttribute(k_conv,      cudaFuncAttributeMaxDynamicSharedMemorySize, KC_SM);
    cudaFuncSetAttribute(k_attn,      cudaFuncAttributeMaxDynamicSharedMemorySize, KA_SM);
    cudaFuncSetAttribute(k_final_mma, cudaFuncAttributeMaxDynamicSharedMemorySize, KF_SM);

    k_prepW<<<589824 / 256, 256>>>(pw[0], pw[1], pw[2], pw[3], w1, fw, rw);
    k_conv<<<dim3(Ldim / 128, Bdim, 4), 256, KC_SM>>>(x, dw[0], dw[1], dw[2], dw[3],
                                                      cnp[0], cnp[1], cnp[2], cnp[3]);
    k_attn<<<dim3(Ldim / 128, Bdim), 256, KA_SM>>>(b1, w2, b2);
    k_final_mma<<<dim3(Ddim / 128, Ldim / 128, Bdim), 256, KF_SM>>>(x, out);
    k_norm<<<(Bdim * Ldim) / 8, 256>>>(out, nsc);
}

// round 14
// speedup vs baseline: 2.7029x; 1.0620x over previous
#include <cuda_runtime.h>
#include <cuda_bf16.h>
#include <math.h>
#include <stdint.h>

#define Bdim 16
#define Ldim 4096
#define Cdim 256
#define Ddim 512
#define EPSF 1e-8f

typedef unsigned long long ull;

// ------------------- scratch (device globals; no allocs allowed) -------------------
__device__ float g_attn[(size_t)Bdim * 4 * Ldim];           // [b][i][l]
__device__ __nv_bfloat16 gF_hi[(size_t)Bdim * Ldim * 512];  // feats (post-gelu) [b][l][512]
__device__ __nv_bfloat16 gF_lo[(size_t)Bdim * Ldim * 512];
__device__ __nv_bfloat16 gB_hi[512 * 768];                  // [o][768]: fw | rw
__device__ __nv_bfloat16 gB_lo[512 * 768];
__device__ __nv_bfloat16 pwB_hi[4 * 128 * 256];             // [sc][o][c]
__device__ __nv_bfloat16 pwB_lo[4 * 128 * 256];
__device__ __nv_bfloat16 w1B_hi[128 * 512];                 // [dh][d]
__device__ __nv_bfloat16 w1B_lo[128 * 512];

// ------------------- helpers -------------------
__device__ __forceinline__ void cpa16(void* dst, const void* src) {
    unsigned s = (unsigned)__cvta_generic_to_shared(dst);
    asm volatile("cp.async.cg.shared.global [%0], [%1], 16;" :: "r"(s), "l"(src));
}
#define CP_COMMIT() asm volatile("cp.async.commit_group;")
#define CP_WAIT0()  asm volatile("cp.async.wait_group 0;" ::: "memory")

__device__ __forceinline__ uint32_t smem_u32(const void* p) {
    uint32_t a;
    asm("{ .reg .u64 t; cvta.to.shared.u64 t, %1; cvt.u32.u64 %0, t; }" : "=r"(a) : "l"(p));
    return a;
}
__device__ __forceinline__ void ldm_x4(uint32_t r[4], uint32_t addr) {
    asm volatile("ldmatrix.sync.aligned.m8n8.x4.shared.b16 {%0,%1,%2,%3}, [%4];"
                 : "=r"(r[0]), "=r"(r[1]), "=r"(r[2]), "=r"(r[3]) : "r"(addr));
}
__device__ __forceinline__ void mma_bf16(float c[4], const uint32_t a[4],
                                         uint32_t b0, uint32_t b1) {
    asm volatile("mma.sync.aligned.m16n8k16.row.col.f32.bf16.bf16.f32 "
                 "{%0,%1,%2,%3}, {%4,%5,%6,%7}, {%8,%9}, {%0,%1,%2,%3};"
                 : "+f"(c[0]), "+f"(c[1]), "+f"(c[2]), "+f"(c[3])
                 : "r"(a[0]), "r"(a[1]), "r"(a[2]), "r"(a[3]), "r"(b0), "r"(b1));
}
__device__ __forceinline__ void split_bf16(float v, __nv_bfloat16& hi, __nv_bfloat16& lo) {
    hi = __float2bfloat16(v);
    lo = __float2bfloat16(v - __bfloat162float(hi));
}
__device__ __forceinline__ uint32_t pack_bf2(__nv_bfloat16 a, __nv_bfloat16 b) {
    uint16_t ua = *(uint16_t*)&a, ub = *(uint16_t*)&b;
    return (uint32_t)ua | ((uint32_t)ub << 16);
}

// ------------------- K0: split all tensor-path weights to bf16 hi/lo -------------------
__global__ void k_prepW(const float* __restrict__ pw1, const float* __restrict__ pw3,
                        const float* __restrict__ pw5, const float* __restrict__ pw7,
                        const float* __restrict__ w1,
                        const float* __restrict__ fw, const float* __restrict__ rw) {
    int idx = blockIdx.x * blockDim.x + threadIdx.x;
    if (idx >= 589824) return;
    float v;
    __nv_bfloat16 hi, lo;
    if (idx < 131072) {
        int s = idx >> 15, r = idx & 32767;
        int o = r >> 8, c = r & 255;
        const float* pw = (s == 0) ? pw1 : (s == 1) ? pw3 : (s == 2) ? pw5 : pw7;
        v = pw[o * 256 + c];
        split_bf16(v, hi, lo);
        pwB_hi[idx] = hi; pwB_lo[idx] = lo;
    } else if (idx < 196608) {
        int r = idx - 131072;
        v = w1[r];
        split_bf16(v, hi, lo);
        w1B_hi[r] = hi; w1B_lo[r] = lo;
    } else {
        int r = idx - 196608;
        int o = r / 768, d = r % 768;
        v = (d < 512) ? fw[o * 512 + d] : rw[o * 256 + (d - 512)];
        split_bf16(v, hi, lo);
        gB_hi[r] = hi; gB_lo[r] = lo;
    }
}

// ------------------- K1: conv (scalar) + pointwise (mma bf16x3) + RMSNorm + GELU -------------------
#define KC_XS  0
#define KC_AH  17152
#define KC_AL  27392
#define KC_PW0 37632
#define KC_PW1 58112
#define KC_SM  78592
__global__ __launch_bounds__(256, 2) void k_conv(
    const float* __restrict__ x,
    const float* __restrict__ dw1, const float* __restrict__ dw3,
    const float* __restrict__ dw5, const float* __restrict__ dw7,
    const float* __restrict__ cn1, const float* __restrict__ cn3,
    const float* __restrict__ cn5, const float* __restrict__ cn7) {
    extern __shared__ char smc[];
    float* xs = (float*)(smc + KC_XS);

    int tid = threadIdx.x, lane = tid & 31, warp = tid >> 5;
    int wm = warp >> 1, wn = warp & 1;
    int lt = blockIdx.x, b = blockIdx.y, sc = blockIdx.z;
    int l0 = lt * 128;
    int k = 2 * sc + 1, r = sc;
    bool edge = (lt == 0) || (lt == Ldim / 128 - 1);
    const float* dw = (sc == 0) ? dw1 : (sc == 1) ? dw3 : (sc == 2) ? dw5 : dw7;
    const float* cn = (sc == 0) ? cn1 : (sc == 1) ? cn3 : (sc == 2) ? cn5 : cn7;
    const __nv_bfloat16* pwh = pwB_hi + sc * 32768;
    const __nv_bfloat16* pwl = pwB_lo + sc * 32768;
    uint32_t sb = smem_u32(smc);

    int c2 = (tid & 15) << 1;   // channel pair
    int lgrp = tid >> 4;        // 16 groups x 8 l

    float c[2][8][4];
    #pragma unroll
    for (int t = 0; t < 2; t++)
        #pragma unroll
        for (int n = 0; n < 8; n++)
            #pragma unroll
            for (int q = 0; q < 4; q++) c[t][n][q] = 0.f;

    auto stage_x = [&](int c0) {
        if (!edge) {
            for (int u = tid; u < 1072; u += 256) {
                int i = u >> 3, seg = u & 7;
                cpa16(smc + KC_XS + i * 128 + seg * 16,
                      x + ((size_t)b * Ldim + l0 - 3 + i) * Cdim + c0 + seg * 4);
            }
        } else {
            for (int u = tid; u < 4288; u += 256) {
                int i = u >> 5, cc = u & 31;
                int gl = l0 - 3 + i;
                xs[u] = (gl >= 0 && gl < Ldim)
                      ? x[((size_t)b * Ldim + gl) * Cdim + c0 + cc] : 0.f;
            }
        }
    };
    auto stage_pw = [&](int c0, int buf) {
        char* base = smc + (buf ? KC_PW1 : KC_PW0);
        for (int u = tid; u < 512; u += 256) {
            int o = u >> 2, seg = u & 3;
            cpa16(base + o * 80 + seg * 16, pwh + (size_t)o * 256 + c0 + seg * 8);
            cpa16(base + 10240 + o * 80 + seg * 16, pwl + (size_t)o * 256 + c0 + seg * 8);
        }
    };

    stage_x(0);
    stage_pw(0, 0);
    CP_COMMIT();

    for (int ci = 0; ci < 8; ci++) {
        int c0 = ci * 32;
        CP_WAIT0();
        __syncthreads();
        // depthwise conv, 2 channels x 8 l per thread, packed uint32 stores
        float rd0[7], rd1[7];
        #pragma unroll
        for (int t = 0; t < 7; t++) {
            rd0[t] = (t < k) ? dw[(c0 + c2) * k + t] : 0.f;
            rd1[t] = (t < k) ? dw[(c0 + c2 + 1) * k + t] : 0.f;
        }
        #pragma unroll
        for (int ii = 0; ii < 8; ii++) {
            int l = lgrp * 8 + ii;
            float s0 = 0.f, s1 = 0.f;
            for (int t = 0; t < k; t++) {
                float2 xv = *(const float2*)&xs[(l + 3 - r + t) * 32 + c2];
                s0 += rd0[t] * xv.x;
                s1 += rd1[t] * xv.y;
            }
            __nv_bfloat16 h0, lo0, h1, lo1;
            split_bf16(s0, h0, lo0);
            split_bf16(s1, h1, lo1);
            *(uint32_t*)(smc + KC_AH + l * 80 + c2 * 2) = pack_bf2(h0, h1);
            *(uint32_t*)(smc + KC_AL + l * 80 + c2 * 2) = pack_bf2(lo0, lo1);
        }
        __syncthreads();
        if (ci < 7) {
            stage_x(c0 + 32);
            stage_pw(c0 + 32, (ci + 1) & 1);
            CP_COMMIT();
        }
        uint32_t pwbuf = sb + ((ci & 1) ? KC_PW1 : KC_PW0);
        int quad = lane >> 3, rr = lane & 7;
        #pragma unroll
        for (int s = 0; s < 2; s++) {
            int k0 = s * 16;
            uint32_t ah[2][4], al[2][4];
            #pragma unroll
            for (int t = 0; t < 2; t++) {
                int row = wm * 32 + t * 16 + (lane & 15);
                uint32_t ad = sb + KC_AH + row * 80 + (k0 + ((lane >> 4) << 3)) * 2;
                ldm_x4(ah[t], ad);
                ldm_x4(al[t], ad + (KC_AL - KC_AH));
            }
            uint32_t bh[4][4], bl[4][4];
            #pragma unroll
            for (int p = 0; p < 4; p++) {
                int n = wn * 64 + p * 16 + ((quad >> 1) << 3) + rr;
                uint32_t bd = pwbuf + n * 80 + (k0 + ((quad & 1) << 3)) * 2;
                ldm_x4(bh[p], bd);
                ldm_x4(bl[p], bd + 10240);
            }
            #pragma unroll
            for (int t = 0; t < 2; t++)
                #pragma unroll
                for (int nt = 0; nt < 8; nt++) {
                    int p = nt >> 1, w2 = (nt & 1) * 2;
                    mma_bf16(c[t][nt], ah[t], bh[p][w2], bh[p][w2 + 1]);
                    mma_bf16(c[t][nt], ah[t], bl[p][w2], bl[p][w2 + 1]);
                    mma_bf16(c[t][nt], al[t], bh[p][w2], bh[p][w2 + 1]);
                }
        }
    }
    __syncthreads();

    float* red = (float*)(smc + KC_XS);   // [128][2]
    int gid = lane >> 2, tig = lane & 3;
    #pragma unroll
    for (int t = 0; t < 2; t++) {
        float p0 = 0.f, p1 = 0.f;
        #pragma unroll
        for (int nt = 0; nt < 8; nt++) {
            p0 += c[t][nt][0] * c[t][nt][0] + c[t][nt][1] * c[t][nt][1];
            p1 += c[t][nt][2] * c[t][nt][2] + c[t][nt][3] * c[t][nt][3];
        }
        p0 += __shfl_xor_sync(0xFFFFFFFFu, p0, 1);
        p0 += __shfl_xor_sync(0xFFFFFFFFu, p0, 2);
        p1 += __shfl_xor_sync(0xFFFFFFFFu, p1, 1);
        p1 += __shfl_xor_sync(0xFFFFFFFFu, p1, 2);
        if (tig == 0) {
            int r0 = wm * 32 + t * 16 + gid;
            red[r0 * 2 + wn] = p0;
            red[(r0 + 8) * 2 + wn] = p1;
        }
    }
    __syncthreads();
    #pragma unroll
    for (int t = 0; t < 2; t++) {
        int r0 = wm * 32 + t * 16 + gid;
        float inv0 = 1.f / (sqrtf((red[r0 * 2] + red[r0 * 2 + 1]) * (1.f / 128.f)) + EPSF);
        float inv1 = 1.f / (sqrtf((red[(r0 + 8) * 2] + red[(r0 + 8) * 2 + 1]) * (1.f / 128.f)) + EPSF);
        #pragma unroll
        for (int nt = 0; nt < 8; nt++) {
            int o = wn * 64 + nt * 8 + tig * 2;
            float cn0 = cn[o], cn1 = cn[o + 1];
            float h00 = c[t][nt][0] * cn0 * inv0, h01 = c[t][nt][1] * cn1 * inv0;
            float h10 = c[t][nt][2] * cn0 * inv1, h11 = c[t][nt][3] * cn1 * inv1;
            h00 *= normcdff(h00); h01 *= normcdff(h01);
            h10 *= normcdff(h10); h11 *= normcdff(h11);
            size_t row0 = ((size_t)b * Ldim + l0 + r0) * 512 + sc * 128 + o;
            size_t row1 = row0 + 8 * 512;
            __nv_bfloat16 a0h, a0l, a1h, a1l;
            split_bf16(h00, a0h, a0l); split_bf16(h01, a1h, a1l);
            *(uint32_t*)(gF_hi + row0) = pack_bf2(a0h, a1h);
            *(uint32_t*)(gF_lo + row0) = pack_bf2(a0l, a1l);
            split_bf16(h10, a0h, a0l); split_bf16(h11, a1h, a1l);
            *(uint32_t*)(gF_hi + row1) = pack_bf2(a0h, a1h);
            *(uint32_t*)(gF_lo + row1) = pack_bf2(a0l, a1l);
        }
    }
}

// ------------------- K2: attention MLP (mma bf16x3) + softmax -------------------
#define KA_A0  0
#define KA_A1  20480
#define KA_B0  40960
#define KA_B1  61440
#define KA_W2  81920
#define KA_SM  83968
__global__ __launch_bounds__(256, 2) void k_attn(const float* __restrict__ b1p,
                                                 const float* __restrict__ w2p,
                                                 const float* __restrict__ b2p) {
    extern __shared__ char smc[];
    float* w2s = (float*)(smc + KA_W2);
    int tid = threadIdx.x, lane = tid & 31, warp = tid >> 5;
    int wm = warp >> 1, wn = warp & 1;
    int b = blockIdx.y;
    int l0 = blockIdx.x * 128;
    uint32_t sb = smem_u32(smc);
    size_t bL = (size_t)b * Ldim + l0;

    w2s[tid] = w2p[tid];
    w2s[tid + 256] = w2p[tid + 256];

    float c[2][8][4];
    #pragma unroll
    for (int t = 0; t < 2; t++)
        #pragma unroll
        for (int n = 0; n < 8; n++)
            #pragma unroll
            for (int q = 0; q < 4; q++) c[t][n][q] = 0.f;

    auto stage = [&](int c0, int buf) {
        char* ab = smc + (buf ? KA_A1 : KA_A0);
        char* bb = smc + (buf ? KA_B1 : KA_B0);
        for (int u = tid; u < 512; u += 256) {
            int row = u >> 2, seg = u & 3;
            size_t ao = (bL + row) * 512 + c0 + seg * 8;
            cpa16(ab + row * 80 + seg * 16, gF_hi + ao);
            cpa16(ab + 10240 + row * 80 + seg * 16, gF_lo + ao);
            size_t bo = (size_t)row * 512 + c0 + seg * 8;
            cpa16(bb + row * 80 + seg * 16, w1B_hi + bo);
            cpa16(bb + 10240 + row * 80 + seg * 16, w1B_lo + bo);
        }
    };

    stage(0, 0);
    CP_COMMIT();

    for (int ci = 0; ci < 16; ci++) {
        CP_WAIT0();
        __syncthreads();
        if (ci < 15) {
            stage((ci + 1) * 32, (ci + 1) & 1);
            CP_COMMIT();
        }
        uint32_t abuf = sb + ((ci & 1) ? KA_A1 : KA_A0);
        uint32_t bbuf = sb + ((ci & 1) ? KA_B1 : KA_B0);
        int quad = lane >> 3, rr = lane & 7;
        #pragma unroll
        for (int s = 0; s < 2; s++) {
            int k0 = s * 16;
            uint32_t ah[2][4], al[2][4];
            #pragma unroll
            for (int t = 0; t < 2; t++) {
                int row = wm * 32 + t * 16 + (lane & 15);
                uint32_t ad = abuf + row * 80 + (k0 + ((lane >> 4) << 3)) * 2;
                ldm_x4(ah[t], ad);
                ldm_x4(al[t], ad + 10240);
            }
            uint32_t bh[4][4], bl[4][4];
            #pragma unroll
            for (int p = 0; p < 4; p++) {
                int n = wn * 64 + p * 16 + ((quad >> 1) << 3) + rr;
                uint32_t bd = bbuf + n * 80 + (k0 + ((quad & 1) << 3)) * 2;
                ldm_x4(bh[p], bd);
                ldm_x4(bl[p], bd + 10240);
            }
            #pragma unroll
            for (int t = 0; t < 2; t++)
                #pragma unroll
                for (int nt = 0; nt < 8; nt++) {
                    int p = nt >> 1, w2 = (nt & 1) * 2;
                    mma_bf16(c[t][nt], ah[t], bh[p][w2], bh[p][w2 + 1]);
                    mma_bf16(c[t][nt], ah[t], bl[p][w2], bl[p][w2 + 1]);
                    mma_bf16(c[t][nt], al[t], bh[p][w2], bh[p][w2 + 1]);
                }
        }
    }
    __syncthreads();

    float* red4 = (float*)smc;
    int gid = lane >> 2, tig = lane & 3;
    float part[4][2][2];
    #pragma unroll
    for (int i4 = 0; i4 < 4; i4++)
        #pragma unroll
        for (int t = 0; t < 2; t++) { part[i4][t][0] = 0.f; part[i4][t][1] = 0.f; }
    #pragma unroll
    for (int t = 0; t < 2; t++)
        #pragma unroll
        for (int nt = 0; nt < 8; nt++) {
            int dh = wn * 64 + nt * 8 + tig * 2;
            float b10 = b1p[dh], b11 = b1p[dh + 1];
            float g00 = c[t][nt][0] + b10, g01 = c[t][nt][1] + b11;
            float g10 = c[t][nt][2] + b10, g11 = c[t][nt][3] + b11;
            g00 *= normcdff(g00); g01 *= normcdff(g01);
            g10 *= normcdff(g10); g11 *= normcdff(g11);
            #pragma unroll
            for (int i4 = 0; i4 < 4; i4++) {
                float w0 = w2s[i4 * 128 + dh], w1v = w2s[i4 * 128 + dh + 1];
                part[i4][t][0] += w0 * g00 + w1v * g01;
                part[i4][t][1] += w0 * g10 + w1v * g11;
            }
        }
    #pragma unroll
    for (int i4 = 0; i4 < 4; i4++)
        #pragma unroll
        for (int t = 0; t < 2; t++)
            #pragma unroll
            for (int rr2 = 0; rr2 < 2; rr2++) {
                float p = part[i4][t][rr2];
                p += __shfl_xor_sync(0xFFFFFFFFu, p, 1);
                p += __shfl_xor_sync(0xFFFFFFFFu, p, 2);
                part[i4][t][rr2] = p;
            }
    if (tig == 0) {
        #pragma unroll
        for (int i4 = 0; i4 < 4; i4++)
            #pragma unroll
            for (int t = 0; t < 2; t++) {
                int r0 = wm * 32 + t * 16 + gid;
                red4[(i4 * 128 + r0) * 2 + wn] = part[i4][t][0];
                red4[(i4 * 128 + r0 + 8) * 2 + wn] = part[i4][t][1];
            }
    }
    __syncthreads();
    if (wn == 0 && tig == 0) {
        #pragma unroll
        for (int t = 0; t < 2; t++)
            #pragma unroll
            for (int rr2 = 0; rr2 < 2; rr2++) {
                int l = wm * 32 + t * 16 + gid + rr2 * 8;
                float a2[4];
                #pragma unroll
                for (int i4 = 0; i4 < 4; i4++)
                    a2[i4] = red4[(i4 * 128 + l) * 2] + red4[(i4 * 128 + l) * 2 + 1] + b2p[i4];
                float m = fmaxf(fmaxf(a2[0], a2[1]), fmaxf(a2[2], a2[3]));
                float s = 0.f;
                #pragma unroll
                for (int i4 = 0; i4 < 4; i4++) { a2[i4] = expf(a2[i4] - m); s += a2[i4]; }
                float invs = 1.f / s;
                #pragma unroll
                for (int i4 = 0; i4 < 4; i4++)
                    g_attn[((size_t)b * 4 + i4) * Ldim + l0 + l] = a2[i4] * invs;
            }
    }
}

// ------------------- K3: fused final GEMM, A-conversion pipelined off critical path -------------------
#define KF_A0 0
#define KF_A1 20480
#define KF_B0 40960
#define KF_B1 61440
#define KF_AT 81920
#define KF_SM 83968
__global__ __launch_bounds__(256, 2) void k_final_mma(const float* __restrict__ x,
                                                      float* __restrict__ out) {
    extern __shared__ char smc[];
    float* atts = (float*)(smc + KF_AT);
    int tid = threadIdx.x, lane = tid & 31, warp = tid >> 5;
    int wm = warp >> 1, wn = warp & 1;
    int ot = blockIdx.x, lt = blockIdx.y, b = blockIdx.z;
    int l0 = lt * 128, o0 = ot * 128;
    uint32_t sb = smem_u32(smc);

    atts[tid]       = g_attn[((size_t)b * 4 + (tid >> 7)) * Ldim + l0 + (tid & 127)];
    atts[tid + 256] = g_attn[((size_t)b * 4 + 2 + (tid >> 7)) * Ldim + l0 + (tid & 127)];

    int arow = tid >> 1, aseg = tid & 1;
    size_t xrow = (size_t)b * Ldim + l0 + arow;
    const __nv_bfloat16* Bhg = gB_hi + (size_t)o0 * 768;
    const __nv_bfloat16* Blg = gB_lo + (size_t)o0 * 768;

    float c[2][8][4];
    #pragma unroll
    for (int t = 0; t < 2; t++)
        #pragma unroll
        for (int n = 0; n < 8; n++)
            #pragma unroll
            for (int q = 0; q < 4; q++) c[t][n][q] = 0.f;

    uint4 r0, r1, r2, r3;
    auto prefetch = [&](int c0) {
        if (c0 < 512) {
            size_t base = xrow * 512 + c0 + aseg * 16;
            r0 = *(const uint4*)(gF_hi + base);
            r1 = *(const uint4*)(gF_hi + base + 8);
            r2 = *(const uint4*)(gF_lo + base);
            r3 = *(const uint4*)(gF_lo + base + 8);
        } else {
            size_t base = xrow * 256 + (c0 - 512) + aseg * 16;
            r0 = *(const uint4*)(x + base);
            r1 = *(const uint4*)(x + base + 4);
            r2 = *(const uint4*)(x + base + 8);
            r3 = *(const uint4*)(x + base + 12);
        }
    };
    auto sts_a = [&](int c0, int buf) {
        char* ab = smc + (buf ? KF_A1 : KF_A0);
        float f[16];
        uint4 rr4[4] = {r0, r1, r2, r3};
        if (c0 < 512) {
            float av = atts[((c0 >> 7) << 7) + arow];
            const __nv_bfloat16* ph = (const __nv_bfloat16*)&rr4[0];
            const __nv_bfloat16* pl = (const __nv_bfloat16*)&rr4[2];
            #pragma unroll
            for (int e = 0; e < 16; e++)
                f[e] = (__bfloat162float(ph[e]) + __bfloat162float(pl[e])) * av;
        } else {
            const float* pf = (const float*)rr4;
            #pragma unroll
            for (int e = 0; e < 16; e++) f[e] = pf[e];
        }
        uint32_t oh[8], ol[8];
        #pragma unroll
        for (int e2 = 0; e2 < 8; e2++) {
            __nv_bfloat16 h0, lo0, h1, lo1;
            split_bf16(f[2 * e2], h0, lo0);
            split_bf16(f[2 * e2 + 1], h1, lo1);
            oh[e2] = pack_bf2(h0, h1);
            ol[e2] = pack_bf2(lo0, lo1);
        }
        char* dh = ab + arow * 80 + aseg * 32;
        *(uint4*)dh        = make_uint4(oh[0], oh[1], oh[2], oh[3]);
        *(uint4*)(dh + 16) = make_uint4(oh[4], oh[5], oh[6], oh[7]);
        char* dl = dh + 10240;
        *(uint4*)dl        = make_uint4(ol[0], ol[1], ol[2], ol[3]);
        *(uint4*)(dl + 16) = make_uint4(ol[4], ol[5], ol[6], ol[7]);
    };
    auto stage_b = [&](int c0, int buf) {
        char* bb = smc + (buf ? KF_B1 : KF_B0);
        for (int u = tid; u < 512; u += 256) {
            int row = u >> 2, seg = u & 3;
            size_t bo = (size_t)row * 768 + c0 + seg * 8;
            cpa16(bb + row * 80 + seg * 16, Bhg + bo);
            cpa16(bb + 10240 + row * 80 + seg * 16, Blg + bo);
        }
    };

    // preamble: A[0] written before first loop sync; B[0] in flight
    prefetch(0);
    stage_b(0, 0);
    CP_COMMIT();
    __syncthreads();     // atts visible (needed by sts_a)
    sts_a(0, 0);
    prefetch(32);        // chunk 1 = column offset 32 (R13 bug: was prefetch(1))
    for (int ci = 0; ci < 24; ci++) {
        CP_WAIT0();
        __syncthreads();     // publishes A[ci] + B[ci]; gates A-buffer reuse
        if (ci < 23) {
            stage_b((ci + 1) * 32, (ci + 1) & 1);
            CP_COMMIT();
        }
        uint32_t abuf = sb + ((ci & 1) ? KF_A1 : KF_A0);
        uint32_t bbuf = sb + ((ci & 1) ? KF_B1 : KF_B0);
        int quad = lane >> 3, rrl = lane & 7;
        #pragma unroll
        for (int s = 0; s < 2; s++) {
            int k0 = s * 16;
            uint32_t ah[2][4], al[2][4];
            #pragma unroll
            for (int t = 0; t < 2; t++) {
                int row = wm * 32 + t * 16 + (lane & 15);
                uint32_t ad = abuf + row * 80 + (k0 + ((lane >> 4) << 3)) * 2;
                ldm_x4(ah[t], ad);
                ldm_x4(al[t], ad + 10240);
            }
            #pragma unroll
            for (int p = 0; p < 4; p++) {
                int n = wn * 64 + p * 16 + ((quad >> 1) << 3) + rrl;
                uint32_t bd = bbuf + n * 80 + (k0 + ((quad & 1) << 3)) * 2;
                uint32_t bh4[4], bl4[4];
                ldm_x4(bh4, bd);
                ldm_x4(bl4, bd + 10240);
                #pragma unroll
                for (int half = 0; half < 2; half++) {
                    int nt = 2 * p + half, w2 = half * 2;
                    #pragma unroll
                    for (int t = 0; t < 2; t++) {
                        mma_bf16(c[t][nt], ah[t], bh4[w2], bh4[w2 + 1]);
                        mma_bf16(c[t][nt], ah[t], bl4[w2], bl4[w2 + 1]);
                        mma_bf16(c[t][nt], al[t], bh4[w2], bh4[w2 + 1]);
                    }
                }
            }
        }
        // A-conversion for next chunk, overlapped with this chunk's tensor work
        if (ci < 23) sts_a((ci + 1) * 32, (ci + 1) & 1);
        if (ci < 22) prefetch((ci + 2) * 32);
    }

    int gid = lane >> 2, tig = lane & 3;
    #pragma unroll
    for (int t = 0; t < 2; t++) {
        size_t rb = (size_t)b * Ldim + l0 + wm * 32 + t * 16 + gid;
        #pragma unroll
        for (int nt = 0; nt < 8; nt++) {
            int o = o0 + wn * 64 + nt * 8 + tig * 2;
            *(float2*)(out + rb * Ddim + o)       = make_float2(c[t][nt][0], c[t][nt][1]);
            *(float2*)(out + (rb + 8) * Ddim + o) = make_float2(c[t][nt][2], c[t][nt][3]);
        }
    }
}

// ------------------- K4: final row RMSNorm (in place) -------------------
__global__ __launch_bounds__(256) void k_norm(float* __restrict__ out,
                                              const float* __restrict__ nsc) {
    __shared__ float ns[512];
    int tid = threadIdx.x;
    ns[tid] = nsc[tid];
    ns[tid + 256] = nsc[tid + 256];
    __syncthreads();

    int warp = tid >> 5, lane = tid & 31;
    size_t row = (size_t)blockIdx.x * 8 + warp;
    float* p = out + row * Ddim;

    float4 v[4];
    float ssq = 0.f;
    #pragma unroll
    for (int q = 0; q < 4; q++) {
        v[q] = *(const float4*)(p + (q * 32 + lane) * 4);
        ssq += v[q].x * v[q].x + v[q].y * v[q].y + v[q].z * v[q].z + v[q].w * v[q].w;
    }
    #pragma unroll
    for (int off = 16; off > 0; off >>= 1)
        ssq += __shfl_xor_sync(0xFFFFFFFFu, ssq, off);
    float rms = sqrtf(ssq * (1.f / 512.f));
    float inv = 1.f / (rms + EPSF);
    #pragma unroll
    for (int q = 0; q < 4; q++) {
        int base = (q * 32 + lane) * 4;
        float4 w;
        w.x = v[q].x * ns[base + 0] * inv;
        w.y = v[q].y * ns[base + 1] * inv;
        w.z = v[q].z * ns[base + 2] * inv;
        w.w = v[q].w * ns[base + 3] * inv;
        *(float4*)(p + base) = w;
    }
}

// ------------------- launch -------------------
extern "C" void kernel_launch(void* const* d_in, const int* in_sizes, int n_in,
                              void* d_out, int out_size) {
    const float* x = (const float*)d_in[0];
    const float *dw[4], *pw[4], *cnp[4];
    if (in_sizes[2] == 768) {
        for (int i = 0; i < 4; i++) {
            dw[i]  = (const float*)d_in[1 + i];
            pw[i]  = (const float*)d_in[5 + i];
            cnp[i] = (const float*)d_in[9 + i];
        }
    } else {
        for (int i = 0; i < 4; i++) {
            dw[i]  = (const float*)d_in[1 + 3 * i];
            pw[i]  = (const float*)d_in[2 + 3 * i];
            cnp[i] = (const float*)d_in[3 + 3 * i];
        }
    }
    const float* w1  = (const float*)d_in[13];
    const float* b1  = (const float*)d_in[14];
    const float* w2  = (const float*)d_in[15];
    const float* b2  = (const float*)d_in[16];
    const float* fw  = (const float*)d_in[17];
    const float* nsc = (const float*)d_in[18];
    const float* rw  = (const float*)d_in[19];
    float* out = (float*)d_out;

    cudaFuncSetAttribute(k_conv,      cudaFuncAttributeMaxDynamicSharedMemorySize, KC_SM);
    cudaFuncSetAttribute(k_attn,      cudaFuncAttributeMaxDynamicSharedMemorySize, KA_SM);
    cudaFuncSetAttribute(k_final_mma, cudaFuncAttributeMaxDynamicSharedMemorySize, KF_SM);

    k_prepW<<<589824 / 256, 256>>>(pw[0], pw[1], pw[2], pw[3], w1, fw, rw);
    k_conv<<<dim3(Ldim / 128, Bdim, 4), 256, KC_SM>>>(x, dw[0], dw[1], dw[2], dw[3],
                                                      cnp[0], cnp[1], cnp[2], cnp[3]);
    k_attn<<<dim3(Ldim / 128, Bdim), 256, KA_SM>>>(b1, w2, b2);
    k_final_mma<<<dim3(Ddim / 128, Ldim / 128, Bdim), 256, KF_SM>>>(x, out);
    k_norm<<<(Bdim * Ldim) / 8, 256>>>(out, nsc);
}